// round 2
// baseline (speedup 1.0000x reference)
#include <cuda_runtime.h>
#include <cstdint>

#define MT 32768
#define TC 1024
#define TH 512
#define TO 1024
#define TR 32

// scratch (__device__ globals: sanctioned alloc-free workaround)
__device__ float g_wres[(size_t)TO * TC];          // w - U@V
__device__ float g_wq[(size_t)TO * TC];            // fake-quant weight values (rotated basis)
__device__ float g_x[(size_t)MT * TC];             // rotated x, then fake-quant in place
__device__ float g_p[(size_t)MT * TR];             // x @ V^T

// fake-quant: matches jnp.clip(jnp.round(v/s),-8,7)*s exactly (half-even rint,
// correctly-rounded div/mul regardless of fast-math flags)
__device__ __forceinline__ float fq(float v, float s) {
    float q = rintf(__fdiv_rn(v, s));
    q = fminf(fmaxf(q, -8.0f), 7.0f);
    return __fmul_rn(q, s);
}

// ---------------- 1) w_res = w - U @ V ----------------
__global__ void k_wres(const float* __restrict__ w, const float* __restrict__ U,
                       const float* __restrict__ V) {
    int o = blockIdx.x;
    __shared__ float u[TR];
    if (threadIdx.x < TR) u[threadIdx.x] = U[o * TR + threadIdx.x];
    __syncthreads();
    for (int c = threadIdx.x; c < TC; c += 256) {
        float acc = w[(size_t)o * TC + c];
#pragma unroll
        for (int r = 0; r < TR; r++) acc = __fmaf_rn(-u[r], V[r * TC + c], acc);
        g_wres[(size_t)o * TC + c] = acc;
    }
}

// ------- 2) weight rotate (Kahan fp32) + static quant -> g_wq -------
// grid (256, 2): 4 output rows per block, half per blockIdx.y
__global__ void __launch_bounds__(256) k_wrotq(const float* __restrict__ R0,
                                               const float* __restrict__ R1,
                                               const float* __restrict__ ws0,
                                               const float* __restrict__ ws1) {
    int half = blockIdx.y;
    const float* R = half ? R1 : R0;
    const float* ws = half ? ws1 : ws0;
    int o0 = blockIdx.x * 4;
    __shared__ float wr[4][TH];
    for (int i = threadIdx.x; i < 4 * TH; i += 256)
        wr[i >> 9][i & 511] = g_wres[(size_t)(o0 + (i >> 9)) * TC + half * TH + (i & 511)];
    __syncthreads();
    int n = threadIdx.x;               // cols n and n+256
    float s[4][2] = {}, c[4][2] = {};
    for (int k = 0; k < TH; k++) {
        float b0 = R[k * TH + n], b1 = R[k * TH + n + 256];
#pragma unroll
        for (int i = 0; i < 4; i++) {
            float a = wr[i][k];
            float p0 = __fmul_rn(a, b0);
            float y0 = __fadd_rn(p0, -c[i][0]);
            float t0 = __fadd_rn(s[i][0], y0);
            c[i][0] = __fadd_rn(__fadd_rn(t0, -s[i][0]), -y0);
            s[i][0] = t0;
            float p1 = __fmul_rn(a, b1);
            float y1 = __fadd_rn(p1, -c[i][1]);
            float t1 = __fadd_rn(s[i][1], y1);
            c[i][1] = __fadd_rn(__fadd_rn(t1, -s[i][1]), -y1);
            s[i][1] = t1;
        }
    }
#pragma unroll
    for (int i = 0; i < 4; i++) {
        float sw = ws[o0 + i];
        g_wq[(size_t)(o0 + i) * TC + half * TH + n]       = fq(s[i][0], sw);
        g_wq[(size_t)(o0 + i) * TC + half * TH + n + 256] = fq(s[i][1], sw);
    }
}

// ---------------- 3) x rotation (fp32 SGEMM 128x128, BK=8) ----------------
// grid (4, 256, 2)
__global__ void __launch_bounds__(256) k_xrot(const float* __restrict__ x,
                                              const float* __restrict__ R0,
                                              const float* __restrict__ R1) {
    int half = blockIdx.z;
    const float* R = half ? R1 : R0;
    int n0 = blockIdx.x * 128, m0 = blockIdx.y * 128;
    __shared__ __align__(16) float As[8 * 128];
    __shared__ __align__(16) float Bs[8 * 128];
    int tid = threadIdx.x, tx = tid & 15, ty = tid >> 4;
    float acc[8][8];
#pragma unroll
    for (int i = 0; i < 8; i++)
#pragma unroll
        for (int j = 0; j < 8; j++) acc[i][j] = 0.0f;

    for (int k0 = 0; k0 < TH; k0 += 8) {
        int m = tid >> 1, q = (tid & 1) * 4;
        float4 a = *(const float4*)&x[(size_t)(m0 + m) * TC + half * TH + k0 + q];
        As[(q + 0) * 128 + m] = a.x; As[(q + 1) * 128 + m] = a.y;
        As[(q + 2) * 128 + m] = a.z; As[(q + 3) * 128 + m] = a.w;
        int kk = tid >> 5, nq = (tid & 31) * 4;
        *(float4*)&Bs[kk * 128 + nq] = *(const float4*)&R[(k0 + kk) * TH + n0 + nq];
        __syncthreads();
#pragma unroll
        for (int k = 0; k < 8; k++) {
            float a8[8], b8[8];
            *(float4*)&a8[0] = *(float4*)&As[k * 128 + ty * 8];
            *(float4*)&a8[4] = *(float4*)&As[k * 128 + ty * 8 + 4];
            *(float4*)&b8[0] = *(float4*)&Bs[k * 128 + tx * 8];
            *(float4*)&b8[4] = *(float4*)&Bs[k * 128 + tx * 8 + 4];
#pragma unroll
            for (int i = 0; i < 8; i++)
#pragma unroll
                for (int j = 0; j < 8; j++)
                    acc[i][j] = __fmaf_rn(a8[i], b8[j], acc[i][j]);
        }
        __syncthreads();
    }
#pragma unroll
    for (int i = 0; i < 8; i++) {
        size_t row = m0 + ty * 8 + i;
        *(float4*)&g_x[row * TC + half * TH + n0 + tx * 8] =
            make_float4(acc[i][0], acc[i][1], acc[i][2], acc[i][3]);
        *(float4*)&g_x[row * TC + half * TH + n0 + tx * 8 + 4] =
            make_float4(acc[i][4], acc[i][5], acc[i][6], acc[i][7]);
    }
}

// ---------------- 4) p = x @ V^T  (M x 32) ----------------
// grid 512: 64 tokens/block
__global__ void __launch_bounds__(256) k_p(const float* __restrict__ x,
                                           const float* __restrict__ V) {
    int m0 = blockIdx.x * 64;
    __shared__ float xs[64][68];
    __shared__ float vs[TR][65];
    int tid = threadIdx.x;
    int tm = tid >> 5, tr = tid & 31;
    float acc[8] = {0, 0, 0, 0, 0, 0, 0, 0};
    for (int k0 = 0; k0 < TC; k0 += 64) {
        int tok = tid >> 2, kq = (tid & 3) * 16;
#pragma unroll
        for (int l = 0; l < 4; l++) {
            float4 v4 = *(const float4*)&x[(size_t)(m0 + tok) * TC + k0 + kq + l * 4];
            xs[tok][kq + l * 4 + 0] = v4.x; xs[tok][kq + l * 4 + 1] = v4.y;
            xs[tok][kq + l * 4 + 2] = v4.z; xs[tok][kq + l * 4 + 3] = v4.w;
        }
#pragma unroll
        for (int l = 0; l < 8; l++) {
            int lin = tid + l * 256;
            vs[lin >> 6][lin & 63] = V[(lin >> 6) * TC + k0 + (lin & 63)];
        }
        __syncthreads();
#pragma unroll 4
        for (int k = 0; k < 64; k++) {
            float b = vs[tr][k];
#pragma unroll
            for (int i = 0; i < 8; i++) acc[i] = __fmaf_rn(xs[tm * 8 + i][k], b, acc[i]);
        }
        __syncthreads();
    }
#pragma unroll
    for (int i = 0; i < 8; i++) g_p[(size_t)(m0 + tm * 8 + i) * TR + tr] = acc[i];
}

// -------- 5) per-token dynamic quant (in place on g_x) --------
__global__ void k_quant() {
    size_t t = blockIdx.x;
    int tid = threadIdx.x;
    float4 v = *(float4*)&g_x[t * TC + tid * 4];
    float m = fmaxf(fmaxf(fabsf(v.x), fabsf(v.y)), fmaxf(fabsf(v.z), fabsf(v.w)));
#pragma unroll
    for (int o = 16; o; o >>= 1) m = fmaxf(m, __shfl_xor_sync(0xffffffffu, m, o));
    __shared__ float wm[8];
    __shared__ float sc[2];
    if ((tid & 31) == 0) wm[tid >> 5] = m;
    __syncthreads();
    if (tid == 0) {
        sc[0] = fmaxf(__fdiv_rn(fmaxf(fmaxf(wm[0], wm[1]), fmaxf(wm[2], wm[3])), 7.0f), 1e-8f);
        sc[1] = fmaxf(__fdiv_rn(fmaxf(fmaxf(wm[4], wm[5]), fmaxf(wm[6], wm[7])), 7.0f), 1e-8f);
    }
    __syncthreads();
    float s = sc[tid >> 7];
    v.x = fq(v.x, s); v.y = fq(v.y, s); v.z = fq(v.z, s); v.w = fq(v.w, s);
    *(float4*)&g_x[t * TC + tid * 4] = v;
}

// -------- 6) main GEMM (fp32, K=1024) + fused epilogue --------
// out = gamma*(xq@wq^T + bias + p@U^T) + beta ; grid (8, 256)
__global__ void __launch_bounds__(256) k_main(const float* __restrict__ U,
                                              const float* __restrict__ bias,
                                              const float* __restrict__ gamma,
                                              const float* __restrict__ beta,
                                              float* __restrict__ out) {
    __shared__ __align__(16) float sm[8448];   // mainloop: As|Bs ; epilogue: ps|us
    float* As = sm;
    float* Bs = sm + 1024;
    int tid = threadIdx.x;
    int n0 = blockIdx.x * 128, m0 = blockIdx.y * 128;
    int tx = tid & 15, ty = tid >> 4;
    float acc[8][8];
#pragma unroll
    for (int i = 0; i < 8; i++)
#pragma unroll
        for (int j = 0; j < 8; j++) acc[i][j] = 0.0f;

    for (int k0 = 0; k0 < TC; k0 += 8) {
        int m = tid >> 1, q = (tid & 1) * 4;
        float4 a = *(const float4*)&g_x[(size_t)(m0 + m) * TC + k0 + q];
        As[(q + 0) * 128 + m] = a.x; As[(q + 1) * 128 + m] = a.y;
        As[(q + 2) * 128 + m] = a.z; As[(q + 3) * 128 + m] = a.w;
        float4 b = *(const float4*)&g_wq[(size_t)(n0 + m) * TC + k0 + q];
        Bs[(q + 0) * 128 + m] = b.x; Bs[(q + 1) * 128 + m] = b.y;
        Bs[(q + 2) * 128 + m] = b.z; Bs[(q + 3) * 128 + m] = b.w;
        __syncthreads();
#pragma unroll
        for (int k = 0; k < 8; k++) {
            float a8[8], b8[8];
            *(float4*)&a8[0] = *(float4*)&As[k * 128 + ty * 8];
            *(float4*)&a8[4] = *(float4*)&As[k * 128 + ty * 8 + 4];
            *(float4*)&b8[0] = *(float4*)&Bs[k * 128 + tx * 8];
            *(float4*)&b8[4] = *(float4*)&Bs[k * 128 + tx * 8 + 4];
#pragma unroll
            for (int i = 0; i < 8; i++)
#pragma unroll
                for (int j = 0; j < 8; j++)
                    acc[i][j] = __fmaf_rn(a8[i], b8[j], acc[i][j]);
        }
        __syncthreads();
    }

    // epilogue: stage p-tile [128][32] and U-tile [128][33] in smem
    float* ps = sm;
    float* us = sm + 4096;
#pragma unroll
    for (int l = 0; l < 4; l++) {
        int e = tid + l * 256;
        ((float4*)ps)[e] = ((const float4*)(g_p + (size_t)m0 * TR))[e];
    }
#pragma unroll
    for (int l = 0; l < 16; l++) {
        int lin = tid + l * 256;
        us[(lin >> 5) * 33 + (lin & 31)] = U[(size_t)(n0 + (lin >> 5)) * TR + (lin & 31)];
    }
    __syncthreads();
#pragma unroll
    for (int i = 0; i < 8; i++) {
        size_t row = m0 + ty * 8 + i;
#pragma unroll
        for (int j = 0; j < 8; j++) {
            int col = n0 + tx * 8 + j;
            float fp = 0.0f;
#pragma unroll
            for (int r = 0; r < TR; r++)
                fp = __fmaf_rn(ps[(ty * 8 + i) * TR + r], us[(tx * 8 + j) * 33 + r], fp);
            float v = acc[i][j] + bias[col] + fp;
            out[row * TO + col] = __fmaf_rn(v, gamma[col], beta[col]);
        }
    }
}

extern "C" void kernel_launch(void* const* d_in, const int* in_sizes, int n_in,
                              void* d_out, int out_size) {
    const float* x     = (const float*)d_in[0];
    const float* w     = (const float*)d_in[1];
    const float* bias  = (const float*)d_in[2];
    const float* U     = (const float*)d_in[3];
    const float* V     = (const float*)d_in[4];
    const float* R0    = (const float*)d_in[5];
    const float* R1    = (const float*)d_in[6];
    const float* ws0   = (const float*)d_in[7];
    const float* ws1   = (const float*)d_in[8];
    const float* gamma = (const float*)d_in[9];
    const float* beta  = (const float*)d_in[10];
    float* out = (float*)d_out;

    k_wres<<<TO, 256>>>(w, U, V);
    k_wrotq<<<dim3(256, 2), 256>>>(R0, R1, ws0, ws1);
    k_xrot<<<dim3(4, 256, 2), 256>>>(x, R0, R1);
    k_p<<<512, 256>>>(x, V);
    k_quant<<<MT, 256>>>();
    k_main<<<dim3(8, 256), 256>>>(U, bias, gamma, beta, out);
}

// round 3
// speedup vs baseline: 2.6131x; 2.6131x over previous
#include <cuda_runtime.h>
#include <cuda_bf16.h>
#include <cstdint>

#define MT 32768
#define TC 1024
#define TH 512
#define TO 1024
#define TR 32

__device__ float g_wres[(size_t)TO * TC];
__device__ __nv_bfloat16 g_qwb[(size_t)TO * TC];     // weight codes (bf16, exact ints)
__device__ float g_x[(size_t)MT * TC];               // rotated activations (fp32)
__device__ __nv_bfloat16 g_qx[(size_t)MT * TC];      // activation codes (bf16, exact ints)
__device__ float g_s0[MT];
__device__ float g_s1[MT];
__device__ float g_p[(size_t)MT * TR];               // x @ V^T

__device__ __forceinline__ float qcode(float v, float s) {
    float q = rintf(__fdiv_rn(v, s));
    return fminf(fmaxf(q, -8.0f), 7.0f);
}

// ---------------- 1) w_res = w - U @ V ----------------
__global__ void k_wres(const float* __restrict__ w, const float* __restrict__ U,
                       const float* __restrict__ V) {
    int o = blockIdx.x;
    __shared__ float u[TR];
    if (threadIdx.x < TR) u[threadIdx.x] = U[o * TR + threadIdx.x];
    __syncthreads();
    for (int c = threadIdx.x; c < TC; c += 256) {
        float acc = w[(size_t)o * TC + c];
#pragma unroll
        for (int r = 0; r < TR; r++) acc = __fmaf_rn(-u[r], V[r * TC + c], acc);
        g_wres[(size_t)o * TC + c] = acc;
    }
}

// ------- 2) weight rotate (Kahan fp32) + static quant -> bf16 codes -------
__global__ void __launch_bounds__(256) k_wrotq(const float* __restrict__ R0,
                                               const float* __restrict__ R1,
                                               const float* __restrict__ ws0,
                                               const float* __restrict__ ws1) {
    int half = blockIdx.y;
    const float* R = half ? R1 : R0;
    const float* ws = half ? ws1 : ws0;
    int o0 = blockIdx.x * 4;
    __shared__ float wr[4][TH];
    for (int i = threadIdx.x; i < 4 * TH; i += 256)
        wr[i >> 9][i & 511] = g_wres[(size_t)(o0 + (i >> 9)) * TC + half * TH + (i & 511)];
    __syncthreads();
    int n = threadIdx.x;
    float s[4][2] = {}, c[4][2] = {};
    for (int k = 0; k < TH; k++) {
        float b0 = R[k * TH + n], b1 = R[k * TH + n + 256];
#pragma unroll
        for (int i = 0; i < 4; i++) {
            float a = wr[i][k];
            float p0 = __fmul_rn(a, b0);
            float y0 = __fadd_rn(p0, -c[i][0]);
            float t0 = __fadd_rn(s[i][0], y0);
            c[i][0] = __fadd_rn(__fadd_rn(t0, -s[i][0]), -y0);
            s[i][0] = t0;
            float p1 = __fmul_rn(a, b1);
            float y1 = __fadd_rn(p1, -c[i][1]);
            float t1 = __fadd_rn(s[i][1], y1);
            c[i][1] = __fadd_rn(__fadd_rn(t1, -s[i][1]), -y1);
            s[i][1] = t1;
        }
    }
#pragma unroll
    for (int i = 0; i < 4; i++) {
        float sw = ws[o0 + i];
        g_qwb[(size_t)(o0 + i) * TC + half * TH + n]       = __float2bfloat16_rn(qcode(s[i][0], sw));
        g_qwb[(size_t)(o0 + i) * TC + half * TH + n + 256] = __float2bfloat16_rn(qcode(s[i][1], sw));
    }
}

// ---------------- 3) x rotation (fp32 SGEMM) ----------------
__global__ void __launch_bounds__(256) k_xrot(const float* __restrict__ x,
                                              const float* __restrict__ R0,
                                              const float* __restrict__ R1) {
    int half = blockIdx.z;
    const float* R = half ? R1 : R0;
    int n0 = blockIdx.x * 128, m0 = blockIdx.y * 128;
    __shared__ __align__(16) float As[8 * 128];
    __shared__ __align__(16) float Bs[8 * 128];
    int tid = threadIdx.x, tx = tid & 15, ty = tid >> 4;
    float acc[8][8];
#pragma unroll
    for (int i = 0; i < 8; i++)
#pragma unroll
        for (int j = 0; j < 8; j++) acc[i][j] = 0.0f;

    for (int k0 = 0; k0 < TH; k0 += 8) {
        int m = tid >> 1, q = (tid & 1) * 4;
        float4 a = *(const float4*)&x[(size_t)(m0 + m) * TC + half * TH + k0 + q];
        As[(q + 0) * 128 + m] = a.x; As[(q + 1) * 128 + m] = a.y;
        As[(q + 2) * 128 + m] = a.z; As[(q + 3) * 128 + m] = a.w;
        int kk = tid >> 5, nq = (tid & 31) * 4;
        *(float4*)&Bs[kk * 128 + nq] = *(const float4*)&R[(k0 + kk) * TH + n0 + nq];
        __syncthreads();
#pragma unroll
        for (int k = 0; k < 8; k++) {
            float a8[8], b8[8];
            *(float4*)&a8[0] = *(float4*)&As[k * 128 + ty * 8];
            *(float4*)&a8[4] = *(float4*)&As[k * 128 + ty * 8 + 4];
            *(float4*)&b8[0] = *(float4*)&Bs[k * 128 + tx * 8];
            *(float4*)&b8[4] = *(float4*)&Bs[k * 128 + tx * 8 + 4];
#pragma unroll
            for (int i = 0; i < 8; i++)
#pragma unroll
                for (int j = 0; j < 8; j++)
                    acc[i][j] = __fmaf_rn(a8[i], b8[j], acc[i][j]);
        }
        __syncthreads();
    }
#pragma unroll
    for (int i = 0; i < 8; i++) {
        size_t row = m0 + ty * 8 + i;
        *(float4*)&g_x[row * TC + half * TH + n0 + tx * 8] =
            make_float4(acc[i][0], acc[i][1], acc[i][2], acc[i][3]);
        *(float4*)&g_x[row * TC + half * TH + n0 + tx * 8 + 4] =
            make_float4(acc[i][4], acc[i][5], acc[i][6], acc[i][7]);
    }
}

// ---------------- 4) p = x @ V^T ----------------
__global__ void __launch_bounds__(256) k_p(const float* __restrict__ x,
                                           const float* __restrict__ V) {
    int m0 = blockIdx.x * 64;
    __shared__ float xs[64][68];
    __shared__ float vs[TR][65];
    int tid = threadIdx.x;
    int tm = tid >> 5, tr = tid & 31;
    float acc[8] = {0, 0, 0, 0, 0, 0, 0, 0};
    for (int k0 = 0; k0 < TC; k0 += 64) {
        int tok = tid >> 2, kq = (tid & 3) * 16;
#pragma unroll
        for (int l = 0; l < 4; l++) {
            float4 v4 = *(const float4*)&x[(size_t)(m0 + tok) * TC + k0 + kq + l * 4];
            xs[tok][kq + l * 4 + 0] = v4.x; xs[tok][kq + l * 4 + 1] = v4.y;
            xs[tok][kq + l * 4 + 2] = v4.z; xs[tok][kq + l * 4 + 3] = v4.w;
        }
#pragma unroll
        for (int l = 0; l < 8; l++) {
            int lin = tid + l * 256;
            vs[lin >> 6][lin & 63] = V[(lin >> 6) * TC + k0 + (lin & 63)];
        }
        __syncthreads();
#pragma unroll 4
        for (int k = 0; k < 64; k++) {
            float b = vs[tr][k];
#pragma unroll
            for (int i = 0; i < 8; i++) acc[i] = __fmaf_rn(xs[tm * 8 + i][k], b, acc[i]);
        }
        __syncthreads();
    }
#pragma unroll
    for (int i = 0; i < 8; i++) g_p[(size_t)(m0 + tm * 8 + i) * TR + tr] = acc[i];
}

// -------- 5) dynamic quant: scales + bf16 codes --------
__global__ void k_quant() {
    size_t t = blockIdx.x;
    int tid = threadIdx.x;
    float4 v = *(float4*)&g_x[t * TC + tid * 4];
    float m = fmaxf(fmaxf(fabsf(v.x), fabsf(v.y)), fmaxf(fabsf(v.z), fabsf(v.w)));
#pragma unroll
    for (int o = 16; o; o >>= 1) m = fmaxf(m, __shfl_xor_sync(0xffffffffu, m, o));
    __shared__ float wm[8];
    __shared__ float sc[2];
    if ((tid & 31) == 0) wm[tid >> 5] = m;
    __syncthreads();
    if (tid == 0) {
        sc[0] = fmaxf(__fdiv_rn(fmaxf(fmaxf(wm[0], wm[1]), fmaxf(wm[2], wm[3])), 7.0f), 1e-8f);
        sc[1] = fmaxf(__fdiv_rn(fmaxf(fmaxf(wm[4], wm[5]), fmaxf(wm[6], wm[7])), 7.0f), 1e-8f);
        g_s0[t] = sc[0];
        g_s1[t] = sc[1];
    }
    __syncthreads();
    float s = sc[tid >> 7];
    __nv_bfloat16 cd[4];
    cd[0] = __float2bfloat16_rn(qcode(v.x, s));
    cd[1] = __float2bfloat16_rn(qcode(v.y, s));
    cd[2] = __float2bfloat16_rn(qcode(v.z, s));
    cd[3] = __float2bfloat16_rn(qcode(v.w, s));
    *(uint2*)&g_qx[t * TC + tid * 4] = *(uint2*)cd;
}

// -------- 6) main GEMM: bf16 HMMA on integer codes + fused skip/affine --------
#define SMA 40   // smem row stride in bf16 (32 + 8 pad)

__device__ __forceinline__ void mma_bf16(float* c, uint32_t a0, uint32_t a1,
                                         uint32_t a2, uint32_t a3,
                                         uint32_t b0, uint32_t b1) {
    asm volatile(
        "mma.sync.aligned.m16n8k16.row.col.f32.bf16.bf16.f32 "
        "{%0,%1,%2,%3}, {%4,%5,%6,%7}, {%8,%9}, {%0,%1,%2,%3};"
        : "+f"(c[0]), "+f"(c[1]), "+f"(c[2]), "+f"(c[3])
        : "r"(a0), "r"(a1), "r"(a2), "r"(a3), "r"(b0), "r"(b1));
}

__device__ __forceinline__ void ldsm4(uint32_t* r, uint32_t addr) {
    asm volatile("ldmatrix.sync.aligned.m8n8.x4.shared.b16 {%0,%1,%2,%3}, [%4];"
                 : "=r"(r[0]), "=r"(r[1]), "=r"(r[2]), "=r"(r[3]) : "r"(addr));
}

__device__ __forceinline__ void mm_compute(uint32_t aBase, uint32_t bBase,
                                           float (&acc)[4][4][4]) {
#pragma unroll
    for (int ks = 0; ks < 2; ks++) {
        uint32_t a[4][4], b[2][4];
#pragma unroll
        for (int mi = 0; mi < 4; mi++) ldsm4(a[mi], aBase + mi * (16 * SMA * 2) + ks * 32);
#pragma unroll
        for (int p = 0; p < 2; p++) ldsm4(b[p], bBase + p * (16 * SMA * 2) + ks * 32);
#pragma unroll
        for (int mi = 0; mi < 4; mi++)
#pragma unroll
            for (int ni = 0; ni < 4; ni++) {
                int p = ni >> 1, s = (ni & 1) * 2;
                mma_bf16(acc[mi][ni], a[mi][0], a[mi][1], a[mi][2], a[mi][3],
                         b[p][s], b[p][s + 1]);
            }
    }
}

__global__ void __launch_bounds__(256) k_main(const float* __restrict__ U,
                                              const float* __restrict__ bias,
                                              const float* __restrict__ ws0,
                                              const float* __restrict__ ws1,
                                              const float* __restrict__ gamma,
                                              const float* __restrict__ beta,
                                              float* __restrict__ out) {
    __shared__ __align__(16) __nv_bfloat16 As[128 * SMA];
    __shared__ __align__(16) __nv_bfloat16 Bs[128 * SMA];
    const int tid = threadIdx.x;
    const int lane = tid & 31, wid = tid >> 5;
    const int wm = wid >> 2, wn = wid & 3;          // 2(M) x 4(N) warps
    const int n0 = blockIdx.x * 128, m0 = blockIdx.y * 128;

    float acc[4][4][4];
#pragma unroll
    for (int i = 0; i < 4; i++)
#pragma unroll
        for (int j = 0; j < 4; j++)
#pragma unroll
            for (int c = 0; c < 4; c++) acc[i][j][c] = 0.0f;

    // ldmatrix per-thread base addresses
    const int g = lane >> 3, r = lane & 7;
    uint32_t smA = (uint32_t)__cvta_generic_to_shared(As);
    uint32_t smB = (uint32_t)__cvta_generic_to_shared(Bs);
    uint32_t aBase = smA + (uint32_t)(((wm * 64 + (g & 1) * 8 + r) * SMA + (g >> 1) * 8) * 2);
    uint32_t bBase = smB + (uint32_t)(((wn * 32 + (g >> 1) * 8 + r) * SMA + (g & 1) * 8) * 2);

    // gmem tile load indices: each thread 2x uint4 per tile (A and B)
    const int lrow = tid >> 2, lq = (tid & 3) * 8;
    const __nv_bfloat16* Ag = g_qx + (size_t)m0 * TC;
    const __nv_bfloat16* Bg = g_qwb + (size_t)n0 * TC;

    uint4 av0, av1, bv0, bv1;
    av0 = *(const uint4*)(Ag + (size_t)lrow * TC + lq);
    av1 = *(const uint4*)(Ag + (size_t)(lrow + 64) * TC + lq);
    bv0 = *(const uint4*)(Bg + (size_t)lrow * TC + lq);
    bv1 = *(const uint4*)(Bg + (size_t)(lrow + 64) * TC + lq);
    *(uint4*)&As[lrow * SMA + lq] = av0;
    *(uint4*)&As[(lrow + 64) * SMA + lq] = av1;
    *(uint4*)&Bs[lrow * SMA + lq] = bv0;
    *(uint4*)&Bs[(lrow + 64) * SMA + lq] = bv1;
    __syncthreads();

    const int qrow = lane >> 2, qcol = (lane & 3) * 2;

    for (int it = 0; it < 32; it++) {
        if (it < 31) {
            int k0 = (it + 1) * 32;
            av0 = *(const uint4*)(Ag + (size_t)lrow * TC + k0 + lq);
            av1 = *(const uint4*)(Ag + (size_t)(lrow + 64) * TC + k0 + lq);
            bv0 = *(const uint4*)(Bg + (size_t)lrow * TC + k0 + lq);
            bv1 = *(const uint4*)(Bg + (size_t)(lrow + 64) * TC + k0 + lq);
        }
        mm_compute(aBase, bBase, acc);
        if (it == 15) {   // fold s0*ws0/(s1*ws1) into half-0 integer dots
            float rr[4][2], rc[4][2];
#pragma unroll
            for (int mi = 0; mi < 4; mi++) {
                int rw = m0 + wm * 64 + mi * 16 + qrow;
                rr[mi][0] = __fdiv_rn(g_s0[rw], g_s1[rw]);
                rr[mi][1] = __fdiv_rn(g_s0[rw + 8], g_s1[rw + 8]);
            }
#pragma unroll
            for (int ni = 0; ni < 4; ni++) {
                int cl = n0 + wn * 32 + ni * 8 + qcol;
                rc[ni][0] = __fdiv_rn(ws0[cl], ws1[cl]);
                rc[ni][1] = __fdiv_rn(ws0[cl + 1], ws1[cl + 1]);
            }
#pragma unroll
            for (int mi = 0; mi < 4; mi++)
#pragma unroll
                for (int ni = 0; ni < 4; ni++) {
                    acc[mi][ni][0] *= rr[mi][0] * rc[ni][0];
                    acc[mi][ni][1] *= rr[mi][0] * rc[ni][1];
                    acc[mi][ni][2] *= rr[mi][1] * rc[ni][0];
                    acc[mi][ni][3] *= rr[mi][1] * rc[ni][1];
                }
        }
        __syncthreads();
        if (it < 31) {
            *(uint4*)&As[lrow * SMA + lq] = av0;
            *(uint4*)&As[(lrow + 64) * SMA + lq] = av1;
            *(uint4*)&Bs[lrow * SMA + lq] = bv0;
            *(uint4*)&Bs[(lrow + 64) * SMA + lq] = bv1;
            __syncthreads();
        }
    }

    // scale by s1[row]*ws1[col]
    {
        float sr[4][2], sc[4][2];
#pragma unroll
        for (int mi = 0; mi < 4; mi++) {
            int rw = m0 + wm * 64 + mi * 16 + qrow;
            sr[mi][0] = g_s1[rw];
            sr[mi][1] = g_s1[rw + 8];
        }
#pragma unroll
        for (int ni = 0; ni < 4; ni++) {
            int cl = n0 + wn * 32 + ni * 8 + qcol;
            sc[ni][0] = ws1[cl];
            sc[ni][1] = ws1[cl + 1];
        }
#pragma unroll
        for (int mi = 0; mi < 4; mi++)
#pragma unroll
            for (int ni = 0; ni < 4; ni++) {
                acc[mi][ni][0] *= sr[mi][0] * sc[ni][0];
                acc[mi][ni][1] *= sr[mi][0] * sc[ni][1];
                acc[mi][ni][2] *= sr[mi][1] * sc[ni][0];
                acc[mi][ni][3] *= sr[mi][1] * sc[ni][1];
            }
    }

    // low-rank skip p@U^T via 3 split-bf16 MMA passes (ph*Uh + ph*Ul + pl*Uh)
#pragma unroll 1
    for (int pass = 0; pass < 3; pass++) {
        __syncthreads();
#pragma unroll
        for (int l = 0; l < 16; l++) {
            int idx = tid + l * 256, row = idx >> 5, c = idx & 31;
            if (pass != 1) {   // A tile: ph (pass0,1) / pl (pass2)
                float v = g_p[(size_t)(m0 + row) * TR + c];
                __nv_bfloat16 h = __float2bfloat16_rn(v);
                As[row * SMA + c] =
                    (pass == 2) ? __float2bfloat16_rn(v - __bfloat162float(h)) : h;
            }
            {   // B tile: Uh (pass0,2) / Ul (pass1)
                float v = U[(size_t)(n0 + row) * TR + c];
                __nv_bfloat16 h = __float2bfloat16_rn(v);
                Bs[row * SMA + c] =
                    (pass == 1) ? __float2bfloat16_rn(v - __bfloat162float(h)) : h;
            }
        }
        __syncthreads();
        mm_compute(aBase, bBase, acc);
    }

    // epilogue: out = (acc + bias)*gamma + beta
    float bi[4][2], ga[4][2], be[4][2];
#pragma unroll
    for (int ni = 0; ni < 4; ni++) {
        int cl = n0 + wn * 32 + ni * 8 + qcol;
        bi[ni][0] = bias[cl];  bi[ni][1] = bias[cl + 1];
        ga[ni][0] = gamma[cl]; ga[ni][1] = gamma[cl + 1];
        be[ni][0] = beta[cl];  be[ni][1] = beta[cl + 1];
    }
#pragma unroll
    for (int mi = 0; mi < 4; mi++) {
        size_t r0 = m0 + wm * 64 + mi * 16 + qrow;
#pragma unroll
        for (int ni = 0; ni < 4; ni++) {
            int cl = n0 + wn * 32 + ni * 8 + qcol;
            float2 o0, o1;
            o0.x = __fmaf_rn(acc[mi][ni][0] + bi[ni][0], ga[ni][0], be[ni][0]);
            o0.y = __fmaf_rn(acc[mi][ni][1] + bi[ni][1], ga[ni][1], be[ni][1]);
            o1.x = __fmaf_rn(acc[mi][ni][2] + bi[ni][0], ga[ni][0], be[ni][0]);
            o1.y = __fmaf_rn(acc[mi][ni][3] + bi[ni][1], ga[ni][1], be[ni][1]);
            *(float2*)&out[r0 * TO + cl] = o0;
            *(float2*)&out[(r0 + 8) * TO + cl] = o1;
        }
    }
}

extern "C" void kernel_launch(void* const* d_in, const int* in_sizes, int n_in,
                              void* d_out, int out_size) {
    const float* x     = (const float*)d_in[0];
    const float* w     = (const float*)d_in[1];
    const float* bias  = (const float*)d_in[2];
    const float* U     = (const float*)d_in[3];
    const float* V     = (const float*)d_in[4];
    const float* R0    = (const float*)d_in[5];
    const float* R1    = (const float*)d_in[6];
    const float* ws0   = (const float*)d_in[7];
    const float* ws1   = (const float*)d_in[8];
    const float* gamma = (const float*)d_in[9];
    const float* beta  = (const float*)d_in[10];
    float* out = (float*)d_out;

    k_wres<<<TO, 256>>>(w, U, V);
    k_wrotq<<<dim3(256, 2), 256>>>(R0, R1, ws0, ws1);
    k_xrot<<<dim3(4, 256, 2), 256>>>(x, R0, R1);
    k_p<<<512, 256>>>(x, V);
    k_quant<<<MT, 256>>>();
    k_main<<<dim3(8, 256), 256>>>(U, bias, ws0, ws1, gamma, beta, out);
}

// round 6
// speedup vs baseline: 2.6985x; 1.0327x over previous
#include <cuda_runtime.h>
#include <cuda_bf16.h>
#include <cstdint>

#define MT 32768
#define TC 1024
#define TH 512
#define TO 1024
#define TR 32

typedef unsigned long long u64t;

__device__ float g_wres[(size_t)TO * TC];
__device__ __nv_bfloat16 g_qwb[(size_t)TO * TC];     // weight codes (bf16, exact ints)
__device__ float g_x[(size_t)MT * TC];               // rotated activations (fp32)
__device__ __nv_bfloat16 g_qx[(size_t)MT * TC];      // activation codes (bf16, exact ints)
__device__ float g_s0[MT];
__device__ float g_s1[MT];
__device__ float g_p[(size_t)MT * TR];               // x @ V^T

__device__ __forceinline__ float qcode(float v, float s) {
    float q = rintf(__fdiv_rn(v, s));
    return fminf(fmaxf(q, -8.0f), 7.0f);
}

// ---- packed f32x2 helpers (each lane is an exact fma.rn.f32) ----
__device__ __forceinline__ u64t pack2(float lo, float hi) {
    u64t r;
    asm("mov.b64 %0, {%1, %2};" : "=l"(r) : "f"(lo), "f"(hi));
    return r;
}
__device__ __forceinline__ void fma2(u64t& c, u64t a, u64t b) {
    asm("fma.rn.f32x2 %0, %1, %2, %0;" : "+l"(c) : "l"(a), "l"(b));
}
__device__ __forceinline__ float2 unpack2(u64t v) {
    float2 f;
    asm("mov.b64 {%0, %1}, %2;" : "=f"(f.x), "=f"(f.y) : "l"(v));
    return f;
}

// ---------------- 1) w_res = w - U @ V ----------------
__global__ void k_wres(const float* __restrict__ w, const float* __restrict__ U,
                       const float* __restrict__ V) {
    int o = blockIdx.x;
    __shared__ float u[TR];
    if (threadIdx.x < TR) u[threadIdx.x] = U[o * TR + threadIdx.x];
    __syncthreads();
    for (int c = threadIdx.x; c < TC; c += 256) {
        float acc = w[(size_t)o * TC + c];
#pragma unroll
        for (int r = 0; r < TR; r++) acc = __fmaf_rn(-u[r], V[r * TC + c], acc);
        g_wres[(size_t)o * TC + c] = acc;
    }
}

// ------- 2) weight rotate (Kahan fp32) + static quant -> bf16 codes -------
__global__ void __launch_bounds__(256) k_wrotq(const float* __restrict__ R0,
                                               const float* __restrict__ R1,
                                               const float* __restrict__ ws0,
                                               const float* __restrict__ ws1) {
    int half = blockIdx.y;
    const float* R = half ? R1 : R0;
    const float* ws = half ? ws1 : ws0;
    int o0 = blockIdx.x * 4;
    __shared__ float wr[4][TH];
    for (int i = threadIdx.x; i < 4 * TH; i += 256)
        wr[i >> 9][i & 511] = g_wres[(size_t)(o0 + (i >> 9)) * TC + half * TH + (i & 511)];
    __syncthreads();
    int n = threadIdx.x;
    float s[4][2] = {}, c[4][2] = {};
    for (int k = 0; k < TH; k++) {
        float b0 = R[k * TH + n], b1 = R[k * TH + n + 256];
#pragma unroll
        for (int i = 0; i < 4; i++) {
            float a = wr[i][k];
            float p0 = __fmul_rn(a, b0);
            float y0 = __fadd_rn(p0, -c[i][0]);
            float t0 = __fadd_rn(s[i][0], y0);
            c[i][0] = __fadd_rn(__fadd_rn(t0, -s[i][0]), -y0);
            s[i][0] = t0;
            float p1 = __fmul_rn(a, b1);
            float y1 = __fadd_rn(p1, -c[i][1]);
            float t1 = __fadd_rn(s[i][1], y1);
            c[i][1] = __fadd_rn(__fadd_rn(t1, -s[i][1]), -y1);
            s[i][1] = t1;
        }
    }
#pragma unroll
    for (int i = 0; i < 4; i++) {
        float sw = ws[o0 + i];
        g_qwb[(size_t)(o0 + i) * TC + half * TH + n]       = __float2bfloat16_rn(qcode(s[i][0], sw));
        g_qwb[(size_t)(o0 + i) * TC + half * TH + n + 256] = __float2bfloat16_rn(qcode(s[i][1], sw));
    }
}

// ------- 3) x rotation: fp32 SGEMM, packed f32x2 FMA -------
// Per-output accumulation chain is serial k-ascending fma.rn.f32 —
// bit-identical to the round-1/2 scalar kernel (reference-correlated rounding).
__global__ void __launch_bounds__(256) k_xrot(const float* __restrict__ x,
                                              const float* __restrict__ R0,
                                              const float* __restrict__ R1) {
    int half = blockIdx.z;
    const float* R = half ? R1 : R0;
    int n0 = blockIdx.x * 128, m0 = blockIdx.y * 128;
    __shared__ __align__(16) float As[8 * 128];
    __shared__ __align__(16) float Bs[8 * 128];
    int tid = threadIdx.x, tx = tid & 15, ty = tid >> 4;

    u64t acc2[8][4];
#pragma unroll
    for (int i = 0; i < 8; i++)
#pragma unroll
        for (int j = 0; j < 4; j++) acc2[i][j] = 0ULL;   // (+0.f, +0.f)

    for (int k0 = 0; k0 < TH; k0 += 8) {
        int m = tid >> 1, q = (tid & 1) * 4;
        float4 a = *(const float4*)&x[(size_t)(m0 + m) * TC + half * TH + k0 + q];
        As[(q + 0) * 128 + m] = a.x; As[(q + 1) * 128 + m] = a.y;
        As[(q + 2) * 128 + m] = a.z; As[(q + 3) * 128 + m] = a.w;
        int kk = tid >> 5, nq = (tid & 31) * 4;
        *(float4*)&Bs[kk * 128 + nq] = *(const float4*)&R[(k0 + kk) * TH + n0 + nq];
        __syncthreads();
#pragma unroll
        for (int k = 0; k < 8; k++) {
            float a8[8];
            *(float4*)&a8[0] = *(float4*)&As[k * 128 + ty * 8];
            *(float4*)&a8[4] = *(float4*)&As[k * 128 + ty * 8 + 4];
            // adjacent column pairs straight from aligned smem loads
            ulonglong2 bp0 = *(ulonglong2*)&Bs[k * 128 + tx * 8];
            ulonglong2 bp1 = *(ulonglong2*)&Bs[k * 128 + tx * 8 + 4];
            u64t b2[4] = {bp0.x, bp0.y, bp1.x, bp1.y};
#pragma unroll
            for (int i = 0; i < 8; i++) {
                u64t aa = pack2(a8[i], a8[i]);
#pragma unroll
                for (int j = 0; j < 4; j++) fma2(acc2[i][j], aa, b2[j]);
            }
        }
        __syncthreads();
    }
#pragma unroll
    for (int i = 0; i < 8; i++) {
        size_t row = m0 + ty * 8 + i;
        float2 f0 = unpack2(acc2[i][0]), f1 = unpack2(acc2[i][1]);
        float2 f2 = unpack2(acc2[i][2]), f3 = unpack2(acc2[i][3]);
        *(float4*)&g_x[row * TC + half * TH + n0 + tx * 8] =
            make_float4(f0.x, f0.y, f1.x, f1.y);
        *(float4*)&g_x[row * TC + half * TH + n0 + tx * 8 + 4] =
            make_float4(f2.x, f2.y, f3.x, f3.y);
    }
}

// ---------------- 4) p = x @ V^T ----------------
__global__ void __launch_bounds__(256) k_p(const float* __restrict__ x,
                                           const float* __restrict__ V) {
    int m0 = blockIdx.x * 128;
    __shared__ __align__(16) float xs[32][132];
    __shared__ __align__(16) float vs[32][36];
    int tid = threadIdx.x;
    int tt = (tid >> 3) * 4;
    int rr = (tid & 7) * 4;
    int lrow = tid & 127, lq = (tid >> 7) * 16;
    int vr = tid & 31, vk = (tid >> 5) * 4;
    float acc[4][4];
#pragma unroll
    for (int i = 0; i < 4; i++)
#pragma unroll
        for (int j = 0; j < 4; j++) acc[i][j] = 0.0f;

    for (int k0 = 0; k0 < TC; k0 += 32) {
#pragma unroll
        for (int j = 0; j < 4; j++) {
            float4 a = *(const float4*)&x[(size_t)(m0 + lrow) * TC + k0 + lq + j * 4];
            xs[lq + j * 4 + 0][lrow] = a.x;
            xs[lq + j * 4 + 1][lrow] = a.y;
            xs[lq + j * 4 + 2][lrow] = a.z;
            xs[lq + j * 4 + 3][lrow] = a.w;
        }
        {
            float4 b = *(const float4*)&V[(size_t)vr * TC + k0 + vk];
            vs[vk + 0][vr] = b.x; vs[vk + 1][vr] = b.y;
            vs[vk + 2][vr] = b.z; vs[vk + 3][vr] = b.w;
        }
        __syncthreads();
#pragma unroll
        for (int k = 0; k < 32; k++) {
            float4 xa = *(float4*)&xs[k][tt];
            float4 vb = *(float4*)&vs[k][rr];
            float xv[4] = {xa.x, xa.y, xa.z, xa.w};
            float vv[4] = {vb.x, vb.y, vb.z, vb.w};
#pragma unroll
            for (int i = 0; i < 4; i++)
#pragma unroll
                for (int j = 0; j < 4; j++)
                    acc[i][j] = __fmaf_rn(xv[i], vv[j], acc[i][j]);
        }
        __syncthreads();
    }
#pragma unroll
    for (int i = 0; i < 4; i++)
        *(float4*)&g_p[(size_t)(m0 + tt + i) * TR + rr] =
            make_float4(acc[i][0], acc[i][1], acc[i][2], acc[i][3]);
}

// -------- 5) dynamic quant: scales + bf16 codes --------
__global__ void k_quant() {
    size_t t = blockIdx.x;
    int tid = threadIdx.x;
    float4 v = *(float4*)&g_x[t * TC + tid * 4];
    float m = fmaxf(fmaxf(fabsf(v.x), fabsf(v.y)), fmaxf(fabsf(v.z), fabsf(v.w)));
#pragma unroll
    for (int o = 16; o; o >>= 1) m = fmaxf(m, __shfl_xor_sync(0xffffffffu, m, o));
    __shared__ float wm[8];
    __shared__ float sc[2];
    if ((tid & 31) == 0) wm[tid >> 5] = m;
    __syncthreads();
    if (tid == 0) {
        sc[0] = fmaxf(__fdiv_rn(fmaxf(fmaxf(wm[0], wm[1]), fmaxf(wm[2], wm[3])), 7.0f), 1e-8f);
        sc[1] = fmaxf(__fdiv_rn(fmaxf(fmaxf(wm[4], wm[5]), fmaxf(wm[6], wm[7])), 7.0f), 1e-8f);
        g_s0[t] = sc[0];
        g_s1[t] = sc[1];
    }
    __syncthreads();
    float s = sc[tid >> 7];
    __nv_bfloat16 cd[4];
    cd[0] = __float2bfloat16_rn(qcode(v.x, s));
    cd[1] = __float2bfloat16_rn(qcode(v.y, s));
    cd[2] = __float2bfloat16_rn(qcode(v.z, s));
    cd[3] = __float2bfloat16_rn(qcode(v.w, s));
    *(uint2*)&g_qx[t * TC + tid * 4] = *(uint2*)cd;
}

// -------- 6) main GEMM: bf16 HMMA on integer codes + fused skip/affine --------
#define SMA 40

__device__ __forceinline__ void mma_bf16(float* c, uint32_t a0, uint32_t a1,
                                         uint32_t a2, uint32_t a3,
                                         uint32_t b0, uint32_t b1) {
    asm volatile(
        "mma.sync.aligned.m16n8k16.row.col.f32.bf16.bf16.f32 "
        "{%0,%1,%2,%3}, {%4,%5,%6,%7}, {%8,%9}, {%0,%1,%2,%3};"
        : "+f"(c[0]), "+f"(c[1]), "+f"(c[2]), "+f"(c[3])
        : "r"(a0), "r"(a1), "r"(a2), "r"(a3), "r"(b0), "r"(b1));
}

__device__ __forceinline__ void ldsm4(uint32_t* r, uint32_t addr) {
    asm volatile("ldmatrix.sync.aligned.m8n8.x4.shared.b16 {%0,%1,%2,%3}, [%4];"
                 : "=r"(r[0]), "=r"(r[1]), "=r"(r[2]), "=r"(r[3]) : "r"(addr));
}

__device__ __forceinline__ void mm_compute(uint32_t aBase, uint32_t bBase,
                                           float (&acc)[4][4][4]) {
#pragma unroll
    for (int ks = 0; ks < 2; ks++) {
        uint32_t a[4][4], b[2][4];
#pragma unroll
        for (int mi = 0; mi < 4; mi++) ldsm4(a[mi], aBase + mi * (16 * SMA * 2) + ks * 32);
#pragma unroll
        for (int p = 0; p < 2; p++) ldsm4(b[p], bBase + p * (16 * SMA * 2) + ks * 32);
#pragma unroll
        for (int mi = 0; mi < 4; mi++)
#pragma unroll
            for (int ni = 0; ni < 4; ni++) {
                int p = ni >> 1, s = (ni & 1) * 2;
                mma_bf16(acc[mi][ni], a[mi][0], a[mi][1], a[mi][2], a[mi][3],
                         b[p][s], b[p][s + 1]);
            }
    }
}

__global__ void __launch_bounds__(256) k_main(const float* __restrict__ U,
                                              const float* __restrict__ bias,
                                              const float* __restrict__ ws0,
                                              const float* __restrict__ ws1,
                                              const float* __restrict__ gamma,
                                              const float* __restrict__ beta,
                                              float* __restrict__ out) {
    __shared__ __align__(16) __nv_bfloat16 As[128 * SMA];
    __shared__ __align__(16) __nv_bfloat16 Bs[128 * SMA];
    const int tid = threadIdx.x;
    const int lane = tid & 31, wid = tid >> 5;
    const int wm = wid >> 2, wn = wid & 3;
    const int n0 = blockIdx.x * 128, m0 = blockIdx.y * 128;

    float acc[4][4][4];
#pragma unroll
    for (int i = 0; i < 4; i++)
#pragma unroll
        for (int j = 0; j < 4; j++)
#pragma unroll
            for (int c = 0; c < 4; c++) acc[i][j][c] = 0.0f;

    const int g = lane >> 3, r = lane & 7;
    uint32_t smA = (uint32_t)__cvta_generic_to_shared(As);
    uint32_t smB = (uint32_t)__cvta_generic_to_shared(Bs);
    uint32_t aBase = smA + (uint32_t)(((wm * 64 + (g & 1) * 8 + r) * SMA + (g >> 1) * 8) * 2);
    uint32_t bBase = smB + (uint32_t)(((wn * 32 + (g >> 1) * 8 + r) * SMA + (g & 1) * 8) * 2);

    const int lrow = tid >> 2, lq = (tid & 3) * 8;
    const __nv_bfloat16* Ag = g_qx + (size_t)m0 * TC;
    const __nv_bfloat16* Bg = g_qwb + (size_t)n0 * TC;

    uint4 av0, av1, bv0, bv1;
    av0 = *(const uint4*)(Ag + (size_t)lrow * TC + lq);
    av1 = *(const uint4*)(Ag + (size_t)(lrow + 64) * TC + lq);
    bv0 = *(const uint4*)(Bg + (size_t)lrow * TC + lq);
    bv1 = *(const uint4*)(Bg + (size_t)(lrow + 64) * TC + lq);
    *(uint4*)&As[lrow * SMA + lq] = av0;
    *(uint4*)&As[(lrow + 64) * SMA + lq] = av1;
    *(uint4*)&Bs[lrow * SMA + lq] = bv0;
    *(uint4*)&Bs[(lrow + 64) * SMA + lq] = bv1;
    __syncthreads();

    const int qrow = lane >> 2, qcol = (lane & 3) * 2;

    for (int it = 0; it < 32; it++) {
        if (it < 31) {
            int k0 = (it + 1) * 32;
            av0 = *(const uint4*)(Ag + (size_t)lrow * TC + k0 + lq);
            av1 = *(const uint4*)(Ag + (size_t)(lrow + 64) * TC + k0 + lq);
            bv0 = *(const uint4*)(Bg + (size_t)lrow * TC + k0 + lq);
            bv1 = *(const uint4*)(Bg + (size_t)(lrow + 64) * TC + k0 + lq);
        }
        mm_compute(aBase, bBase, acc);
        if (it == 15) {
            float rr[4][2], rc[4][2];
#pragma unroll
            for (int mi = 0; mi < 4; mi++) {
                int rw = m0 + wm * 64 + mi * 16 + qrow;
                rr[mi][0] = __fdiv_rn(g_s0[rw], g_s1[rw]);
                rr[mi][1] = __fdiv_rn(g_s0[rw + 8], g_s1[rw + 8]);
            }
#pragma unroll
            for (int ni = 0; ni < 4; ni++) {
                int cl = n0 + wn * 32 + ni * 8 + qcol;
                rc[ni][0] = __fdiv_rn(ws0[cl], ws1[cl]);
                rc[ni][1] = __fdiv_rn(ws0[cl + 1], ws1[cl + 1]);
            }
#pragma unroll
            for (int mi = 0; mi < 4; mi++)
#pragma unroll
                for (int ni = 0; ni < 4; ni++) {
                    acc[mi][ni][0] *= rr[mi][0] * rc[ni][0];
                    acc[mi][ni][1] *= rr[mi][0] * rc[ni][1];
                    acc[mi][ni][2] *= rr[mi][1] * rc[ni][0];
                    acc[mi][ni][3] *= rr[mi][1] * rc[ni][1];
                }
        }
        __syncthreads();
        if (it < 31) {
            *(uint4*)&As[lrow * SMA + lq] = av0;
            *(uint4*)&As[(lrow + 64) * SMA + lq] = av1;
            *(uint4*)&Bs[lrow * SMA + lq] = bv0;
            *(uint4*)&Bs[(lrow + 64) * SMA + lq] = bv1;
            __syncthreads();
        }
    }

    {
        float sr[4][2], sc[4][2];
#pragma unroll
        for (int mi = 0; mi < 4; mi++) {
            int rw = m0 + wm * 64 + mi * 16 + qrow;
            sr[mi][0] = g_s1[rw];
            sr[mi][1] = g_s1[rw + 8];
        }
#pragma unroll
        for (int ni = 0; ni < 4; ni++) {
            int cl = n0 + wn * 32 + ni * 8 + qcol;
            sc[ni][0] = ws1[cl];
            sc[ni][1] = ws1[cl + 1];
        }
#pragma unroll
        for (int mi = 0; mi < 4; mi++)
#pragma unroll
            for (int ni = 0; ni < 4; ni++) {
                acc[mi][ni][0] *= sr[mi][0] * sc[ni][0];
                acc[mi][ni][1] *= sr[mi][0] * sc[ni][1];
                acc[mi][ni][2] *= sr[mi][1] * sc[ni][0];
                acc[mi][ni][3] *= sr[mi][1] * sc[ni][1];
            }
    }

#pragma unroll 1
    for (int pass = 0; pass < 3; pass++) {
        __syncthreads();
#pragma unroll
        for (int l = 0; l < 16; l++) {
            int idx = tid + l * 256, row = idx >> 5, c = idx & 31;
            if (pass != 1) {
                float v = g_p[(size_t)(m0 + row) * TR + c];
                __nv_bfloat16 h = __float2bfloat16_rn(v);
                As[row * SMA + c] =
                    (pass == 2) ? __float2bfloat16_rn(v - __bfloat162float(h)) : h;
            }
            {
                float v = U[(size_t)(n0 + row) * TR + c];
                __nv_bfloat16 h = __float2bfloat16_rn(v);
                Bs[row * SMA + c] =
                    (pass == 1) ? __float2bfloat16_rn(v - __bfloat162float(h)) : h;
            }
        }
        __syncthreads();
        mm_compute(aBase, bBase, acc);
    }

    float bi[4][2], ga[4][2], be[4][2];
#pragma unroll
    for (int ni = 0; ni < 4; ni++) {
        int cl = n0 + wn * 32 + ni * 8 + qcol;
        bi[ni][0] = bias[cl];  bi[ni][1] = bias[cl + 1];
        ga[ni][0] = gamma[cl]; ga[ni][1] = gamma[cl + 1];
        be[ni][0] = beta[cl];  be[ni][1] = beta[cl + 1];
    }
#pragma unroll
    for (int mi = 0; mi < 4; mi++) {
        size_t r0 = m0 + wm * 64 + mi * 16 + qrow;
#pragma unroll
        for (int ni = 0; ni < 4; ni++) {
            int cl = n0 + wn * 32 + ni * 8 + qcol;
            float2 o0, o1;
            o0.x = __fmaf_rn(acc[mi][ni][0] + bi[ni][0], ga[ni][0], be[ni][0]);
            o0.y = __fmaf_rn(acc[mi][ni][1] + bi[ni][1], ga[ni][1], be[ni][1]);
            o1.x = __fmaf_rn(acc[mi][ni][2] + bi[ni][0], ga[ni][0], be[ni][0]);
            o1.y = __fmaf_rn(acc[mi][ni][3] + bi[ni][1], ga[ni][1], be[ni][1]);
            *(float2*)&out[r0 * TO + cl] = o0;
            *(float2*)&out[(r0 + 8) * TO + cl] = o1;
        }
    }
}

extern "C" void kernel_launch(void* const* d_in, const int* in_sizes, int n_in,
                              void* d_out, int out_size) {
    const float* x     = (const float*)d_in[0];
    const float* w     = (const float*)d_in[1];
    const float* bias  = (const float*)d_in[2];
    const float* U     = (const float*)d_in[3];
    const float* V     = (const float*)d_in[4];
    const float* R0    = (const float*)d_in[5];
    const float* R1    = (const float*)d_in[6];
    const float* ws0   = (const float*)d_in[7];
    const float* ws1   = (const float*)d_in[8];
    const float* gamma = (const float*)d_in[9];
    const float* beta  = (const float*)d_in[10];
    float* out = (float*)d_out;

    k_wres<<<TO, 256>>>(w, U, V);
    k_wrotq<<<dim3(256, 2), 256>>>(R0, R1, ws0, ws1);
    k_xrot<<<dim3(4, 256, 2), 256>>>(x, R0, R1);
    k_p<<<256, 256>>>(x, V);
    k_quant<<<MT, 256>>>();
    k_main<<<dim3(8, 256), 256>>>(U, bias, ws0, ws1, gamma, beta, out);
}

// round 7
// speedup vs baseline: 2.7146x; 1.0059x over previous
#include <cuda_runtime.h>
#include <cuda_bf16.h>
#include <cstdint>

#define MT 32768
#define TC 1024
#define TH 512
#define TO 1024
#define TR 32
#define FCAP (1 << 22)
#define TAU 2e-4f

__device__ float g_wres[(size_t)TO * TC];
__device__ __nv_bfloat16 g_qwb[(size_t)TO * TC];     // weight codes (bf16, exact ints)
__device__ float g_x[(size_t)MT * TC];               // rotated activations (fp32, via TF32 MMA)
__device__ __nv_bfloat16 g_qx[(size_t)MT * TC];      // activation codes (bf16, exact ints)
__device__ float g_s0[MT];
__device__ float g_s1[MT];
__device__ float g_p[(size_t)MT * TR];               // x @ V^T
__device__ int g_flagcnt;
__device__ int g_flags[FCAP];                        // (t << 10) | col
__device__ int g_aidx[MT * 2];                       // per-(row,half) argmax col (0..511)

__device__ __forceinline__ float qcode(float v, float s) {
    float q = rintf(__fdiv_rn(v, s));
    return fminf(fmaxf(q, -8.0f), 7.0f);
}

// ---------------- 1) w_res = w - U @ V ----------------
__global__ void k_wres(const float* __restrict__ w, const float* __restrict__ U,
                       const float* __restrict__ V) {
    int o = blockIdx.x;
    __shared__ float u[TR];
    if (threadIdx.x < TR) u[threadIdx.x] = U[o * TR + threadIdx.x];
    __syncthreads();
    for (int c = threadIdx.x; c < TC; c += 256) {
        float acc = w[(size_t)o * TC + c];
#pragma unroll
        for (int r = 0; r < TR; r++) acc = __fmaf_rn(-u[r], V[r * TC + c], acc);
        g_wres[(size_t)o * TC + c] = acc;
    }
}

// ------- 2) weight rotate (Kahan fp32) + static quant -> bf16 codes -------
__global__ void __launch_bounds__(256) k_wrotq(const float* __restrict__ R0,
                                               const float* __restrict__ R1,
                                               const float* __restrict__ ws0,
                                               const float* __restrict__ ws1) {
    int half = blockIdx.y;
    const float* R = half ? R1 : R0;
    const float* ws = half ? ws1 : ws0;
    int o0 = blockIdx.x * 4;
    __shared__ float wr[4][TH];
    for (int i = threadIdx.x; i < 4 * TH; i += 256)
        wr[i >> 9][i & 511] = g_wres[(size_t)(o0 + (i >> 9)) * TC + half * TH + (i & 511)];
    __syncthreads();
    int n = threadIdx.x;
    float s[4][2] = {}, c[4][2] = {};
    for (int k = 0; k < TH; k++) {
        float b0 = R[k * TH + n], b1 = R[k * TH + n + 256];
#pragma unroll
        for (int i = 0; i < 4; i++) {
            float a = wr[i][k];
            float p0 = __fmul_rn(a, b0);
            float y0 = __fadd_rn(p0, -c[i][0]);
            float t0 = __fadd_rn(s[i][0], y0);
            c[i][0] = __fadd_rn(__fadd_rn(t0, -s[i][0]), -y0);
            s[i][0] = t0;
            float p1 = __fmul_rn(a, b1);
            float y1 = __fadd_rn(p1, -c[i][1]);
            float t1 = __fadd_rn(s[i][1], y1);
            c[i][1] = __fadd_rn(__fadd_rn(t1, -s[i][1]), -y1);
            s[i][1] = t1;
        }
    }
#pragma unroll
    for (int i = 0; i < 4; i++) {
        float sw = ws[o0 + i];
        g_qwb[(size_t)(o0 + i) * TC + half * TH + n]       = __float2bfloat16_rn(qcode(s[i][0], sw));
        g_qwb[(size_t)(o0 + i) * TC + half * TH + n + 256] = __float2bfloat16_rn(qcode(s[i][1], sw));
    }
}

// ------- 3) x rotation: TF32 MMA, 2-way split, 3 passes (~1e-6 accurate) -------
__device__ __forceinline__ uint32_t f2t(float f) {
    uint32_t u;
    asm("cvt.rna.tf32.f32 %0, %1;" : "=r"(u) : "f"(f));
    return u;
}
__device__ __forceinline__ void mma_tf32(float* c, const uint32_t* a,
                                         uint32_t b0, uint32_t b1) {
    asm volatile(
        "mma.sync.aligned.m16n8k8.row.col.f32.tf32.tf32.f32 "
        "{%0,%1,%2,%3}, {%4,%5,%6,%7}, {%8,%9}, {%0,%1,%2,%3};"
        : "+f"(c[0]), "+f"(c[1]), "+f"(c[2]), "+f"(c[3])
        : "r"(a[0]), "r"(a[1]), "r"(a[2]), "r"(a[3]), "r"(b0), "r"(b1));
}

#define XAS 20
#define XBS 136

__global__ void __launch_bounds__(256) k_xrot(const float* __restrict__ x,
                                              const float* __restrict__ R0,
                                              const float* __restrict__ R1) {
    int half = blockIdx.z;
    const float* R = half ? R1 : R0;
    int n0 = blockIdx.x * 128, m0 = blockIdx.y * 128;

    __shared__ __align__(16) float Ah[128 * XAS], Al[128 * XAS];
    __shared__ __align__(16) float Bh[16 * XBS],  Bl[16 * XBS];

    int tid = threadIdx.x, lane = tid & 31, wid = tid >> 5;
    int wm = wid >> 2, wn = wid & 3;

    float acc[4][4][4];
#pragma unroll
    for (int i = 0; i < 4; i++)
#pragma unroll
        for (int j = 0; j < 4; j++)
#pragma unroll
            for (int c = 0; c < 4; c++) acc[i][j][c] = 0.0f;

    int arow = tid >> 1, aq = (tid & 1) * 8;
    int brow = tid >> 4, bq = (tid & 15) * 8;
    const float* Ag = x + (size_t)(m0 + arow) * TC + half * TH + aq;
    const float* Bg = R + (size_t)brow * TH + n0 + bq;

    float4 ar0 = *(const float4*)Ag;
    float4 ar1 = *(const float4*)(Ag + 4);
    float4 br0 = *(const float4*)Bg;
    float4 br1 = *(const float4*)(Bg + 4);

    int fr = lane >> 2, fk = lane & 3;

    for (int it = 0; it < 32; it++) {
        {
            float4 h0, l0, h1, l1;
            h0.x = __uint_as_float(f2t(ar0.x)); l0.x = __uint_as_float(f2t(ar0.x - h0.x));
            h0.y = __uint_as_float(f2t(ar0.y)); l0.y = __uint_as_float(f2t(ar0.y - h0.y));
            h0.z = __uint_as_float(f2t(ar0.z)); l0.z = __uint_as_float(f2t(ar0.z - h0.z));
            h0.w = __uint_as_float(f2t(ar0.w)); l0.w = __uint_as_float(f2t(ar0.w - h0.w));
            h1.x = __uint_as_float(f2t(ar1.x)); l1.x = __uint_as_float(f2t(ar1.x - h1.x));
            h1.y = __uint_as_float(f2t(ar1.y)); l1.y = __uint_as_float(f2t(ar1.y - h1.y));
            h1.z = __uint_as_float(f2t(ar1.z)); l1.z = __uint_as_float(f2t(ar1.z - h1.z));
            h1.w = __uint_as_float(f2t(ar1.w)); l1.w = __uint_as_float(f2t(ar1.w - h1.w));
            *(float4*)&Ah[arow * XAS + aq]     = h0;
            *(float4*)&Al[arow * XAS + aq]     = l0;
            *(float4*)&Ah[arow * XAS + aq + 4] = h1;
            *(float4*)&Al[arow * XAS + aq + 4] = l1;

            h0.x = __uint_as_float(f2t(br0.x)); l0.x = __uint_as_float(f2t(br0.x - h0.x));
            h0.y = __uint_as_float(f2t(br0.y)); l0.y = __uint_as_float(f2t(br0.y - h0.y));
            h0.z = __uint_as_float(f2t(br0.z)); l0.z = __uint_as_float(f2t(br0.z - h0.z));
            h0.w = __uint_as_float(f2t(br0.w)); l0.w = __uint_as_float(f2t(br0.w - h0.w));
            h1.x = __uint_as_float(f2t(br1.x)); l1.x = __uint_as_float(f2t(br1.x - h1.x));
            h1.y = __uint_as_float(f2t(br1.y)); l1.y = __uint_as_float(f2t(br1.y - h1.y));
            h1.z = __uint_as_float(f2t(br1.z)); l1.z = __uint_as_float(f2t(br1.z - h1.z));
            h1.w = __uint_as_float(f2t(br1.w)); l1.w = __uint_as_float(f2t(br1.w - h1.w));
            *(float4*)&Bh[brow * XBS + bq]     = h0;
            *(float4*)&Bl[brow * XBS + bq]     = l0;
            *(float4*)&Bh[brow * XBS + bq + 4] = h1;
            *(float4*)&Bl[brow * XBS + bq + 4] = l1;
        }
        __syncthreads();
        if (it < 31) {
            int k0 = (it + 1) * 16;
            ar0 = *(const float4*)(Ag + k0);
            ar1 = *(const float4*)(Ag + k0 + 4);
            br0 = *(const float4*)(Bg + (size_t)k0 * TH);
            br1 = *(const float4*)(Bg + (size_t)k0 * TH + 4);
        }
#pragma unroll
        for (int ks = 0; ks < 2; ks++) {
            int kk = ks * 8 + fk;
            uint32_t bh[4][2], bl_[4][2];
#pragma unroll
            for (int ni = 0; ni < 4; ni++) {
                int n = wn * 32 + ni * 8 + fr;
                bh[ni][0]  = *(uint32_t*)&Bh[kk * XBS + n];
                bh[ni][1]  = *(uint32_t*)&Bh[(kk + 4) * XBS + n];
                bl_[ni][0] = *(uint32_t*)&Bl[kk * XBS + n];
                bl_[ni][1] = *(uint32_t*)&Bl[(kk + 4) * XBS + n];
            }
#pragma unroll
            for (int mi = 0; mi < 4; mi++) {
                int rbase = (wm * 64 + mi * 16 + fr) * XAS;
                uint32_t ah[4], al[4];
                ah[0] = *(uint32_t*)&Ah[rbase + kk];
                ah[1] = *(uint32_t*)&Ah[rbase + 8 * XAS + kk];
                ah[2] = *(uint32_t*)&Ah[rbase + kk + 4];
                ah[3] = *(uint32_t*)&Ah[rbase + 8 * XAS + kk + 4];
                al[0] = *(uint32_t*)&Al[rbase + kk];
                al[1] = *(uint32_t*)&Al[rbase + 8 * XAS + kk];
                al[2] = *(uint32_t*)&Al[rbase + kk + 4];
                al[3] = *(uint32_t*)&Al[rbase + 8 * XAS + kk + 4];
#pragma unroll
                for (int ni = 0; ni < 4; ni++) {
                    mma_tf32(acc[mi][ni], al, bh[ni][0], bh[ni][1]);   // 2^-11
                    mma_tf32(acc[mi][ni], ah, bl_[ni][0], bl_[ni][1]); // 2^-11
                    mma_tf32(acc[mi][ni], ah, bh[ni][0], bh[ni][1]);   // 1
                }
            }
        }
        __syncthreads();
    }
    int qrow = lane >> 2, qcol = (lane & 3) * 2;
#pragma unroll
    for (int mi = 0; mi < 4; mi++) {
        size_t row = m0 + wm * 64 + mi * 16 + qrow;
#pragma unroll
        for (int ni = 0; ni < 4; ni++) {
            int col = half * TH + n0 + wn * 32 + ni * 8 + qcol;
            *(float2*)&g_x[row * TC + col] = make_float2(acc[mi][ni][0], acc[mi][ni][1]);
            *(float2*)&g_x[(row + 8) * TC + col] = make_float2(acc[mi][ni][2], acc[mi][ni][3]);
        }
    }
}

// ---------------- 4) p = x @ V^T ----------------
__global__ void __launch_bounds__(256) k_p(const float* __restrict__ x,
                                           const float* __restrict__ V) {
    int m0 = blockIdx.x * 128;
    __shared__ __align__(16) float xs[32][132];
    __shared__ __align__(16) float vs[32][36];
    int tid = threadIdx.x;
    int tt = (tid >> 3) * 4;
    int rr = (tid & 7) * 4;
    int lrow = tid & 127, lq = (tid >> 7) * 16;
    int vr = tid & 31, vk = (tid >> 5) * 4;
    float acc[4][4];
#pragma unroll
    for (int i = 0; i < 4; i++)
#pragma unroll
        for (int j = 0; j < 4; j++) acc[i][j] = 0.0f;

    for (int k0 = 0; k0 < TC; k0 += 32) {
#pragma unroll
        for (int j = 0; j < 4; j++) {
            float4 a = *(const float4*)&x[(size_t)(m0 + lrow) * TC + k0 + lq + j * 4];
            xs[lq + j * 4 + 0][lrow] = a.x;
            xs[lq + j * 4 + 1][lrow] = a.y;
            xs[lq + j * 4 + 2][lrow] = a.z;
            xs[lq + j * 4 + 3][lrow] = a.w;
        }
        {
            float4 b = *(const float4*)&V[(size_t)vr * TC + k0 + vk];
            vs[vk + 0][vr] = b.x; vs[vk + 1][vr] = b.y;
            vs[vk + 2][vr] = b.z; vs[vk + 3][vr] = b.w;
        }
        __syncthreads();
#pragma unroll
        for (int k = 0; k < 32; k++) {
            float4 xa = *(float4*)&xs[k][tt];
            float4 vb = *(float4*)&vs[k][rr];
            float xv[4] = {xa.x, xa.y, xa.z, xa.w};
            float vv[4] = {vb.x, vb.y, vb.z, vb.w};
#pragma unroll
            for (int i = 0; i < 4; i++)
#pragma unroll
                for (int j = 0; j < 4; j++)
                    acc[i][j] = __fmaf_rn(xv[i], vv[j], acc[i][j]);
        }
        __syncthreads();
    }
#pragma unroll
    for (int i = 0; i < 4; i++)
        *(float4*)&g_p[(size_t)(m0 + tt + i) * TR + rr] =
            make_float4(acc[i][0], acc[i][1], acc[i][2], acc[i][3]);
}

// -------- 5a) zero the flag counter --------
__global__ void k_zero() { g_flagcnt = 0; }

// -------- 5b) dynamic quant: scales + argmax + bf16 codes + boundary flags --------
__global__ void k_quant() {
    size_t t = blockIdx.x;
    int tid = threadIdx.x;
    float4 v = *(float4*)&g_x[t * TC + tid * 4];
    float a0 = fabsf(v.x), a1 = fabsf(v.y), a2 = fabsf(v.z), a3 = fabsf(v.w);
    float m = a0; int mi = tid * 4;
    if (a1 > m) { m = a1; mi = tid * 4 + 1; }
    if (a2 > m) { m = a2; mi = tid * 4 + 2; }
    if (a3 > m) { m = a3; mi = tid * 4 + 3; }
#pragma unroll
    for (int o = 16; o; o >>= 1) {
        float om = __shfl_xor_sync(0xffffffffu, m, o);
        int   oi = __shfl_xor_sync(0xffffffffu, mi, o);
        if (om > m || (om == m && oi < mi)) { m = om; mi = oi; }
    }
    __shared__ float wm[8];
    __shared__ int   wi[8];
    __shared__ float sc[2];
    if ((tid & 31) == 0) { wm[tid >> 5] = m; wi[tid >> 5] = mi; }
    __syncthreads();
    if (tid == 0) {
        float m0 = wm[0]; int i0 = wi[0];
#pragma unroll
        for (int w = 1; w < 4; w++)
            if (wm[w] > m0 || (wm[w] == m0 && wi[w] < i0)) { m0 = wm[w]; i0 = wi[w]; }
        float m1 = wm[4]; int i1 = wi[4];
#pragma unroll
        for (int w = 5; w < 8; w++)
            if (wm[w] > m1 || (wm[w] == m1 && wi[w] < i1)) { m1 = wm[w]; i1 = wi[w]; }
        sc[0] = fmaxf(__fdiv_rn(m0, 7.0f), 1e-8f);
        sc[1] = fmaxf(__fdiv_rn(m1, 7.0f), 1e-8f);
        g_s0[t] = sc[0];
        g_s1[t] = sc[1];
        g_aidx[t * 2]     = i0;
        g_aidx[t * 2 + 1] = i1 - 512;
    }
    __syncthreads();
    float s = sc[tid >> 7];
    float vv[4] = {v.x, v.y, v.z, v.w};
    __nv_bfloat16 cd[4];
#pragma unroll
    for (int j = 0; j < 4; j++) {
        float u = __fdiv_rn(vv[j], s);
        float r = rintf(u);
        cd[j] = __float2bfloat16_rn(fminf(fmaxf(r, -8.0f), 7.0f));
        if (0.5f - fabsf(u - r) < TAU) {   // near a rounding boundary: flag for exact redo
            int idx = atomicAdd(&g_flagcnt, 1);
            if (idx < FCAP) g_flags[idx] = ((int)t << 10) | (tid * 4 + j);
        }
    }
    *(uint2*)&g_qx[t * TC + tid * 4] = *(uint2*)cd;
}

// -------- 5c) fix-up: exact serial fp32 chain for flagged codes (+ exact scale) --------
__global__ void k_fix(const float* __restrict__ x, const float* __restrict__ R0,
                      const float* __restrict__ R1) {
    int cnt = g_flagcnt;
    if (cnt > FCAP) cnt = FCAP;
    for (int i = blockIdx.x * blockDim.x + threadIdx.x; i < cnt;
         i += gridDim.x * blockDim.x) {
        int e = g_flags[i];
        int t = e >> 10, c = e & 1023;
        int h = c >> 9, cc = c & 511;
        const float* xr = x + (size_t)t * TC + h * TH;
        const float* R = h ? R1 : R0;
        int ac = g_aidx[t * 2 + h];
        float v = 0.0f, va = 0.0f;
        for (int k = 0; k < TH; k++) {       // k-ascending serial fma chain (ref-matching)
            float xv = xr[k];
            v  = __fmaf_rn(xv, R[k * TH + cc], v);
            va = __fmaf_rn(xv, R[k * TH + ac], va);
        }
        float s = fmaxf(__fdiv_rn(fabsf(va), 7.0f), 1e-8f);
        g_qx[(size_t)t * TC + c] = __float2bfloat16_rn(qcode(v, s));
    }
}

// -------- 6) main GEMM: bf16 HMMA on integer codes + fused skip/affine --------
#define SMA 40

__device__ __forceinline__ void mma_bf16(float* c, uint32_t a0, uint32_t a1,
                                         uint32_t a2, uint32_t a3,
                                         uint32_t b0, uint32_t b1) {
    asm volatile(
        "mma.sync.aligned.m16n8k16.row.col.f32.bf16.bf16.f32 "
        "{%0,%1,%2,%3}, {%4,%5,%6,%7}, {%8,%9}, {%0,%1,%2,%3};"
        : "+f"(c[0]), "+f"(c[1]), "+f"(c[2]), "+f"(c[3])
        : "r"(a0), "r"(a1), "r"(a2), "r"(a3), "r"(b0), "r"(b1));
}

__device__ __forceinline__ void ldsm4(uint32_t* r, uint32_t addr) {
    asm volatile("ldmatrix.sync.aligned.m8n8.x4.shared.b16 {%0,%1,%2,%3}, [%4];"
                 : "=r"(r[0]), "=r"(r[1]), "=r"(r[2]), "=r"(r[3]) : "r"(addr));
}

__device__ __forceinline__ void mm_compute(uint32_t aBase, uint32_t bBase,
                                           float (&acc)[4][4][4]) {
#pragma unroll
    for (int ks = 0; ks < 2; ks++) {
        uint32_t a[4][4], b[2][4];
#pragma unroll
        for (int mi = 0; mi < 4; mi++) ldsm4(a[mi], aBase + mi * (16 * SMA * 2) + ks * 32);
#pragma unroll
        for (int p = 0; p < 2; p++) ldsm4(b[p], bBase + p * (16 * SMA * 2) + ks * 32);
#pragma unroll
        for (int mi = 0; mi < 4; mi++)
#pragma unroll
            for (int ni = 0; ni < 4; ni++) {
                int p = ni >> 1, s = (ni & 1) * 2;
                mma_bf16(acc[mi][ni], a[mi][0], a[mi][1], a[mi][2], a[mi][3],
                         b[p][s], b[p][s + 1]);
            }
    }
}

__global__ void __launch_bounds__(256) k_main(const float* __restrict__ U,
                                              const float* __restrict__ bias,
                                              const float* __restrict__ ws0,
                                              const float* __restrict__ ws1,
                                              const float* __restrict__ gamma,
                                              const float* __restrict__ beta,
                                              float* __restrict__ out) {
    __shared__ __align__(16) __nv_bfloat16 As[128 * SMA];
    __shared__ __align__(16) __nv_bfloat16 Bs[128 * SMA];
    const int tid = threadIdx.x;
    const int lane = tid & 31, wid = tid >> 5;
    const int wm = wid >> 2, wn = wid & 3;
    const int n0 = blockIdx.x * 128, m0 = blockIdx.y * 128;

    float acc[4][4][4];
#pragma unroll
    for (int i = 0; i < 4; i++)
#pragma unroll
        for (int j = 0; j < 4; j++)
#pragma unroll
            for (int c = 0; c < 4; c++) acc[i][j][c] = 0.0f;

    const int g = lane >> 3, r = lane & 7;
    uint32_t smA = (uint32_t)__cvta_generic_to_shared(As);
    uint32_t smB = (uint32_t)__cvta_generic_to_shared(Bs);
    uint32_t aBase = smA + (uint32_t)(((wm * 64 + (g & 1) * 8 + r) * SMA + (g >> 1) * 8) * 2);
    uint32_t bBase = smB + (uint32_t)(((wn * 32 + (g >> 1) * 8 + r) * SMA + (g & 1) * 8) * 2);

    const int lrow = tid >> 2, lq = (tid & 3) * 8;
    const __nv_bfloat16* Ag = g_qx + (size_t)m0 * TC;
    const __nv_bfloat16* Bg = g_qwb + (size_t)n0 * TC;

    uint4 av0, av1, bv0, bv1;
    av0 = *(const uint4*)(Ag + (size_t)lrow * TC + lq);
    av1 = *(const uint4*)(Ag + (size_t)(lrow + 64) * TC + lq);
    bv0 = *(const uint4*)(Bg + (size_t)lrow * TC + lq);
    bv1 = *(const uint4*)(Bg + (size_t)(lrow + 64) * TC + lq);
    *(uint4*)&As[lrow * SMA + lq] = av0;
    *(uint4*)&As[(lrow + 64) * SMA + lq] = av1;
    *(uint4*)&Bs[lrow * SMA + lq] = bv0;
    *(uint4*)&Bs[(lrow + 64) * SMA + lq] = bv1;
    __syncthreads();

    const int qrow = lane >> 2, qcol = (lane & 3) * 2;

    for (int it = 0; it < 32; it++) {
        if (it < 31) {
            int k0 = (it + 1) * 32;
            av0 = *(const uint4*)(Ag + (size_t)lrow * TC + k0 + lq);
            av1 = *(const uint4*)(Ag + (size_t)(lrow + 64) * TC + k0 + lq);
            bv0 = *(const uint4*)(Bg + (size_t)lrow * TC + k0 + lq);
            bv1 = *(const uint4*)(Bg + (size_t)(lrow + 64) * TC + k0 + lq);
        }
        mm_compute(aBase, bBase, acc);
        if (it == 15) {
            float rr[4][2], rc[4][2];
#pragma unroll
            for (int mi = 0; mi < 4; mi++) {
                int rw = m0 + wm * 64 + mi * 16 + qrow;
                rr[mi][0] = __fdiv_rn(g_s0[rw], g_s1[rw]);
                rr[mi][1] = __fdiv_rn(g_s0[rw + 8], g_s1[rw + 8]);
            }
#pragma unroll
            for (int ni = 0; ni < 4; ni++) {
                int cl = n0 + wn * 32 + ni * 8 + qcol;
                rc[ni][0] = __fdiv_rn(ws0[cl], ws1[cl]);
                rc[ni][1] = __fdiv_rn(ws0[cl + 1], ws1[cl + 1]);
            }
#pragma unroll
            for (int mi = 0; mi < 4; mi++)
#pragma unroll
                for (int ni = 0; ni < 4; ni++) {
                    acc[mi][ni][0] *= rr[mi][0] * rc[ni][0];
                    acc[mi][ni][1] *= rr[mi][0] * rc[ni][1];
                    acc[mi][ni][2] *= rr[mi][1] * rc[ni][0];
                    acc[mi][ni][3] *= rr[mi][1] * rc[ni][1];
                }
        }
        __syncthreads();
        if (it < 31) {
            *(uint4*)&As[lrow * SMA + lq] = av0;
            *(uint4*)&As[(lrow + 64) * SMA + lq] = av1;
            *(uint4*)&Bs[lrow * SMA + lq] = bv0;
            *(uint4*)&Bs[(lrow + 64) * SMA + lq] = bv1;
            __syncthreads();
        }
    }

    {
        float sr[4][2], sc[4][2];
#pragma unroll
        for (int mi = 0; mi < 4; mi++) {
            int rw = m0 + wm * 64 + mi * 16 + qrow;
            sr[mi][0] = g_s1[rw];
            sr[mi][1] = g_s1[rw + 8];
        }
#pragma unroll
        for (int ni = 0; ni < 4; ni++) {
            int cl = n0 + wn * 32 + ni * 8 + qcol;
            sc[ni][0] = ws1[cl];
            sc[ni][1] = ws1[cl + 1];
        }
#pragma unroll
        for (int mi = 0; mi < 4; mi++)
#pragma unroll
            for (int ni = 0; ni < 4; ni++) {
                acc[mi][ni][0] *= sr[mi][0] * sc[ni][0];
                acc[mi][ni][1] *= sr[mi][0] * sc[ni][1];
                acc[mi][ni][2] *= sr[mi][1] * sc[ni][0];
                acc[mi][ni][3] *= sr[mi][1] * sc[ni][1];
            }
    }

#pragma unroll 1
    for (int pass = 0; pass < 3; pass++) {
        __syncthreads();
#pragma unroll
        for (int l = 0; l < 16; l++) {
            int idx = tid + l * 256, row = idx >> 5, c = idx & 31;
            if (pass != 1) {
                float v = g_p[(size_t)(m0 + row) * TR + c];
                __nv_bfloat16 h = __float2bfloat16_rn(v);
                As[row * SMA + c] =
                    (pass == 2) ? __float2bfloat16_rn(v - __bfloat162float(h)) : h;
            }
            {
                float v = U[(size_t)(n0 + row) * TR + c];
                __nv_bfloat16 h = __float2bfloat16_rn(v);
                Bs[row * SMA + c] =
                    (pass == 1) ? __float2bfloat16_rn(v - __bfloat162float(h)) : h;
            }
        }
        __syncthreads();
        mm_compute(aBase, bBase, acc);
    }

    float bi[4][2], ga[4][2], be[4][2];
#pragma unroll
    for (int ni = 0; ni < 4; ni++) {
        int cl = n0 + wn * 32 + ni * 8 + qcol;
        bi[ni][0] = bias[cl];  bi[ni][1] = bias[cl + 1];
        ga[ni][0] = gamma[cl]; ga[ni][1] = gamma[cl + 1];
        be[ni][0] = beta[cl];  be[ni][1] = beta[cl + 1];
    }
#pragma unroll
    for (int mi = 0; mi < 4; mi++) {
        size_t r0 = m0 + wm * 64 + mi * 16 + qrow;
#pragma unroll
        for (int ni = 0; ni < 4; ni++) {
            int cl = n0 + wn * 32 + ni * 8 + qcol;
            float2 o0, o1;
            o0.x = __fmaf_rn(acc[mi][ni][0] + bi[ni][0], ga[ni][0], be[ni][0]);
            o0.y = __fmaf_rn(acc[mi][ni][1] + bi[ni][1], ga[ni][1], be[ni][1]);
            o1.x = __fmaf_rn(acc[mi][ni][2] + bi[ni][0], ga[ni][0], be[ni][0]);
            o1.y = __fmaf_rn(acc[mi][ni][3] + bi[ni][1], ga[ni][1], be[ni][1]);
            *(float2*)&out[r0 * TO + cl] = o0;
            *(float2*)&out[(r0 + 8) * TO + cl] = o1;
        }
    }
}

extern "C" void kernel_launch(void* const* d_in, const int* in_sizes, int n_in,
                              void* d_out, int out_size) {
    const float* x     = (const float*)d_in[0];
    const float* w     = (const float*)d_in[1];
    const float* bias  = (const float*)d_in[2];
    const float* U     = (const float*)d_in[3];
    const float* V     = (const float*)d_in[4];
    const float* R0    = (const float*)d_in[5];
    const float* R1    = (const float*)d_in[6];
    const float* ws0   = (const float*)d_in[7];
    const float* ws1   = (const float*)d_in[8];
    const float* gamma = (const float*)d_in[9];
    const float* beta  = (const float*)d_in[10];
    float* out = (float*)d_out;

    k_wres<<<TO, 256>>>(w, U, V);
    k_wrotq<<<dim3(256, 2), 256>>>(R0, R1, ws0, ws1);
    k_xrot<<<dim3(4, 256, 2), 256>>>(x, R0, R1);
    k_p<<<256, 256>>>(x, V);
    k_zero<<<1, 1>>>();
    k_quant<<<MT, 256>>>();
    k_fix<<<1024, 128>>>(x, R0, R1);
    k_main<<<dim3(8, 256), 256>>>(U, bias, ws0, ws1, gamma, beta, out);
}

// round 9
// speedup vs baseline: 2.9439x; 1.0845x over previous
#include <cuda_runtime.h>
#include <cuda_bf16.h>
#include <cstdint>

#define MT 32768
#define TC 1024
#define TH 512
#define TO 1024
#define TR 32
#define FCAP (1 << 22)
#define TAU 6e-4f

__device__ float g_wres[(size_t)TO * TC];
__device__ __nv_bfloat16 g_qwb[(size_t)TO * TC];
__device__ float g_x[(size_t)MT * TC];
__device__ __nv_bfloat16 g_qx[(size_t)MT * TC];
__device__ float g_s0[MT];
__device__ float g_s1[MT];
__device__ float g_p[(size_t)MT * TR];
__device__ int g_flagcnt;
__device__ int g_flags[FCAP];
__device__ int g_aidx[MT * 2];

__device__ __forceinline__ float qcode(float v, float s) {
    float q = rintf(__fdiv_rn(v, s));
    return fminf(fmaxf(q, -8.0f), 7.0f);
}

// ---- shared MMA helpers (bf16 m16n8k16, ldmatrix, [row][k] smem, stride SMA) ----
#define SMA 40

__device__ __forceinline__ void mma_bf16(float* c, uint32_t a0, uint32_t a1,
                                         uint32_t a2, uint32_t a3,
                                         uint32_t b0, uint32_t b1) {
    asm volatile(
        "mma.sync.aligned.m16n8k16.row.col.f32.bf16.bf16.f32 "
        "{%0,%1,%2,%3}, {%4,%5,%6,%7}, {%8,%9}, {%0,%1,%2,%3};"
        : "+f"(c[0]), "+f"(c[1]), "+f"(c[2]), "+f"(c[3])
        : "r"(a0), "r"(a1), "r"(a2), "r"(a3), "r"(b0), "r"(b1));
}

__device__ __forceinline__ void ldsm4(uint32_t* r, uint32_t addr) {
    asm volatile("ldmatrix.sync.aligned.m8n8.x4.shared.b16 {%0,%1,%2,%3}, [%4];"
                 : "=r"(r[0]), "=r"(r[1]), "=r"(r[2]), "=r"(r[3]) : "r"(addr));
}

// one 128x128x32 block-tile step: 2 k-steps x (2M x 4N warps) x 4x4 MMAs
__device__ __forceinline__ void mm_compute(uint32_t aBase, uint32_t bBase,
                                           float (&acc)[4][4][4]) {
#pragma unroll
    for (int ks = 0; ks < 2; ks++) {
        uint32_t a[4][4], b[2][4];
#pragma unroll
        for (int mi = 0; mi < 4; mi++) ldsm4(a[mi], aBase + mi * (16 * SMA * 2) + ks * 32);
#pragma unroll
        for (int p = 0; p < 2; p++) ldsm4(b[p], bBase + p * (16 * SMA * 2) + ks * 32);
#pragma unroll
        for (int mi = 0; mi < 4; mi++)
#pragma unroll
            for (int ni = 0; ni < 4; ni++) {
                int p = ni >> 1, s = (ni & 1) * 2;
                mma_bf16(acc[mi][ni], a[mi][0], a[mi][1], a[mi][2], a[mi][3],
                         b[p][s], b[p][s + 1]);
            }
    }
}

// ---------------- 1) w_res = w - U @ V ----------------
__global__ void k_wres(const float* __restrict__ w, const float* __restrict__ U,
                       const float* __restrict__ V) {
    int o = blockIdx.x;
    __shared__ float u[TR];
    if (threadIdx.x < TR) u[threadIdx.x] = U[o * TR + threadIdx.x];
    __syncthreads();
    for (int c = threadIdx.x; c < TC; c += 256) {
        float acc = w[(size_t)o * TC + c];
#pragma unroll
        for (int r = 0; r < TR; r++) acc = __fmaf_rn(-u[r], V[r * TC + c], acc);
        g_wres[(size_t)o * TC + c] = acc;
    }
}

// ------- 2) weight rotate (Kahan fp32) + static quant -> bf16 codes -------
__global__ void __launch_bounds__(256) k_wrotq(const float* __restrict__ R0,
                                               const float* __restrict__ R1,
                                               const float* __restrict__ ws0,
                                               const float* __restrict__ ws1) {
    int half = blockIdx.y;
    const float* R = half ? R1 : R0;
    const float* ws = half ? ws1 : ws0;
    int o0 = blockIdx.x * 4;
    __shared__ float wr[4][TH];
    for (int i = threadIdx.x; i < 4 * TH; i += 256)
        wr[i >> 9][i & 511] = g_wres[(size_t)(o0 + (i >> 9)) * TC + half * TH + (i & 511)];
    __syncthreads();
    int n = threadIdx.x;
    float s[4][2] = {}, c[4][2] = {};
    for (int k = 0; k < TH; k++) {
        float b0 = R[k * TH + n], b1 = R[k * TH + n + 256];
#pragma unroll
        for (int i = 0; i < 4; i++) {
            float a = wr[i][k];
            float p0 = __fmul_rn(a, b0);
            float y0 = __fadd_rn(p0, -c[i][0]);
            float t0 = __fadd_rn(s[i][0], y0);
            c[i][0] = __fadd_rn(__fadd_rn(t0, -s[i][0]), -y0);
            s[i][0] = t0;
            float p1 = __fmul_rn(a, b1);
            float y1 = __fadd_rn(p1, -c[i][1]);
            float t1 = __fadd_rn(s[i][1], y1);
            c[i][1] = __fadd_rn(__fadd_rn(t1, -s[i][1]), -y1);
            s[i][1] = t1;
        }
    }
#pragma unroll
    for (int i = 0; i < 4; i++) {
        float sw = ws[o0 + i];
        g_qwb[(size_t)(o0 + i) * TC + half * TH + n]       = __float2bfloat16_rn(qcode(s[i][0], sw));
        g_qwb[(size_t)(o0 + i) * TC + half * TH + n + 256] = __float2bfloat16_rn(qcode(s[i][1], sw));
    }
}

// ------- 3) x rotation: bf16 HMMA, 2-way split, 3 passes (hh + hm + mh) -------
__global__ void __launch_bounds__(256) k_xrot(const float* __restrict__ x,
                                              const float* __restrict__ R0,
                                              const float* __restrict__ R1) {
    __shared__ __align__(16) __nv_bfloat16 Ah[128 * SMA], Am[128 * SMA];
    __shared__ __align__(16) __nv_bfloat16 Bh[128 * SMA], Bm[128 * SMA];
    const int half = blockIdx.z;
    const float* R = half ? R1 : R0;
    const int n0 = blockIdx.x * 128, m0 = blockIdx.y * 128;
    const int tid = threadIdx.x, lane = tid & 31, wid = tid >> 5;
    const int wm = wid >> 2, wn = wid & 3;

    float acc[4][4][4];
#pragma unroll
    for (int i = 0; i < 4; i++)
#pragma unroll
        for (int j = 0; j < 4; j++)
#pragma unroll
            for (int c = 0; c < 4; c++) acc[i][j][c] = 0.0f;

    const int g = lane >> 3, r = lane & 7;
    uint32_t smAh = (uint32_t)__cvta_generic_to_shared(Ah);
    uint32_t smAm = (uint32_t)__cvta_generic_to_shared(Am);
    uint32_t smBh = (uint32_t)__cvta_generic_to_shared(Bh);
    uint32_t smBm = (uint32_t)__cvta_generic_to_shared(Bm);
    uint32_t aoff = (uint32_t)(((wm * 64 + (g & 1) * 8 + r) * SMA + (g >> 1) * 8) * 2);
    uint32_t boff = (uint32_t)(((wn * 32 + (g >> 1) * 8 + r) * SMA + (g & 1) * 8) * 2);

    // staging indices
    const int arow = tid >> 1, alq = (tid & 1) * 16;         // A: 128 rows x 32 k
    const int bn = tid & 127, bkb = (tid >> 7) * 16;         // B: 128 n x 32 k (transpose)
    const float* Agr = x + (size_t)(m0 + arow) * TC + half * TH + alq;

    for (int it = 0; it < 16; it++) {
        int k0 = it * 32;
        {   // ---- stage A [128 x 32]: 16 floats/thread -> h/m bf16 ----
            __nv_bfloat16 h16[16], m16[16];
#pragma unroll
            for (int j = 0; j < 4; j++) {
                float4 v = *(const float4*)(Agr + k0 + j * 4);
                float vv[4] = {v.x, v.y, v.z, v.w};
#pragma unroll
                for (int q = 0; q < 4; q++) {
                    __nv_bfloat16 h = __float2bfloat16_rn(vv[q]);
                    h16[j * 4 + q] = h;
                    m16[j * 4 + q] = __float2bfloat16_rn(vv[q] - __bfloat162float(h));
                }
            }
            *(uint4*)&Ah[arow * SMA + alq]     = *(uint4*)&h16[0];
            *(uint4*)&Ah[arow * SMA + alq + 8] = *(uint4*)&h16[8];
            *(uint4*)&Am[arow * SMA + alq]     = *(uint4*)&m16[0];
            *(uint4*)&Am[arow * SMA + alq + 8] = *(uint4*)&m16[8];
        }
        {   // ---- stage B [128 n x 32 k] = R[k][n] transposed ----
            __nv_bfloat16 h16[16], m16[16];
#pragma unroll
            for (int k = 0; k < 16; k++) {
                float v = R[(size_t)(k0 + bkb + k) * TH + n0 + bn];
                __nv_bfloat16 h = __float2bfloat16_rn(v);
                h16[k] = h;
                m16[k] = __float2bfloat16_rn(v - __bfloat162float(h));
            }
            *(uint4*)&Bh[bn * SMA + bkb]     = *(uint4*)&h16[0];
            *(uint4*)&Bh[bn * SMA + bkb + 8] = *(uint4*)&h16[8];
            *(uint4*)&Bm[bn * SMA + bkb]     = *(uint4*)&m16[0];
            *(uint4*)&Bm[bn * SMA + bkb + 8] = *(uint4*)&m16[8];
        }
        __syncthreads();
        mm_compute(smAh + aoff, smBm + boff, acc);   // h*m  (2^-9)
        mm_compute(smAm + aoff, smBh + boff, acc);   // m*h  (2^-9)
        mm_compute(smAh + aoff, smBh + boff, acc);   // h*h  (1)
        __syncthreads();
    }

    const int qrow = lane >> 2, qcol = (lane & 3) * 2;
#pragma unroll
    for (int mi = 0; mi < 4; mi++) {
        size_t row = m0 + wm * 64 + mi * 16 + qrow;
#pragma unroll
        for (int ni = 0; ni < 4; ni++) {
            int col = half * TH + n0 + wn * 32 + ni * 8 + qcol;
            *(float2*)&g_x[row * TC + col] = make_float2(acc[mi][ni][0], acc[mi][ni][1]);
            *(float2*)&g_x[(row + 8) * TC + col] = make_float2(acc[mi][ni][2], acc[mi][ni][3]);
        }
    }
}

// ---------------- 4) p = x @ V^T ----------------
__global__ void __launch_bounds__(256) k_p(const float* __restrict__ x,
                                           const float* __restrict__ V) {
    int m0 = blockIdx.x * 128;
    __shared__ __align__(16) float xs[32][132];
    __shared__ __align__(16) float vs[32][36];
    int tid = threadIdx.x;
    int tt = (tid >> 3) * 4;
    int rr = (tid & 7) * 4;
    int lrow = tid & 127, lq = (tid >> 7) * 16;
    int vr = tid & 31, vk = (tid >> 5) * 4;
    float acc[4][4];
#pragma unroll
    for (int i = 0; i < 4; i++)
#pragma unroll
        for (int j = 0; j < 4; j++) acc[i][j] = 0.0f;

    for (int k0 = 0; k0 < TC; k0 += 32) {
#pragma unroll
        for (int j = 0; j < 4; j++) {
            float4 a = *(const float4*)&x[(size_t)(m0 + lrow) * TC + k0 + lq + j * 4];
            xs[lq + j * 4 + 0][lrow] = a.x;
            xs[lq + j * 4 + 1][lrow] = a.y;
            xs[lq + j * 4 + 2][lrow] = a.z;
            xs[lq + j * 4 + 3][lrow] = a.w;
        }
        {
            float4 b = *(const float4*)&V[(size_t)vr * TC + k0 + vk];
            vs[vk + 0][vr] = b.x; vs[vk + 1][vr] = b.y;
            vs[vk + 2][vr] = b.z; vs[vk + 3][vr] = b.w;
        }
        __syncthreads();
#pragma unroll
        for (int k = 0; k < 32; k++) {
            float4 xa = *(float4*)&xs[k][tt];
            float4 vb = *(float4*)&vs[k][rr];
            float xv[4] = {xa.x, xa.y, xa.z, xa.w};
            float vv[4] = {vb.x, vb.y, vb.z, vb.w};
#pragma unroll
            for (int i = 0; i < 4; i++)
#pragma unroll
                for (int j = 0; j < 4; j++)
                    acc[i][j] = __fmaf_rn(xv[i], vv[j], acc[i][j]);
        }
        __syncthreads();
    }
#pragma unroll
    for (int i = 0; i < 4; i++)
        *(float4*)&g_p[(size_t)(m0 + tt + i) * TR + rr] =
            make_float4(acc[i][0], acc[i][1], acc[i][2], acc[i][3]);
}

// -------- 5a) zero flag counter --------
__global__ void k_zero() { g_flagcnt = 0; }

// -------- 5b) dynamic quant: scales + argmax + codes + boundary flags --------
__global__ void k_quant() {
    size_t t = blockIdx.x;
    int tid = threadIdx.x;
    float4 v = *(float4*)&g_x[t * TC + tid * 4];
    float a0 = fabsf(v.x), a1 = fabsf(v.y), a2 = fabsf(v.z), a3 = fabsf(v.w);
    float m = a0; int mi = tid * 4;
    if (a1 > m) { m = a1; mi = tid * 4 + 1; }
    if (a2 > m) { m = a2; mi = tid * 4 + 2; }
    if (a3 > m) { m = a3; mi = tid * 4 + 3; }
#pragma unroll
    for (int o = 16; o; o >>= 1) {
        float om = __shfl_xor_sync(0xffffffffu, m, o);
        int   oi = __shfl_xor_sync(0xffffffffu, mi, o);
        if (om > m || (om == m && oi < mi)) { m = om; mi = oi; }
    }
    __shared__ float wm[8];
    __shared__ int   wi[8];
    __shared__ float sc[2];
    if ((tid & 31) == 0) { wm[tid >> 5] = m; wi[tid >> 5] = mi; }
    __syncthreads();
    if (tid == 0) {
        float m0 = wm[0]; int i0 = wi[0];
#pragma unroll
        for (int w = 1; w < 4; w++)
            if (wm[w] > m0 || (wm[w] == m0 && wi[w] < i0)) { m0 = wm[w]; i0 = wi[w]; }
        float m1 = wm[4]; int i1 = wi[4];
#pragma unroll
        for (int w = 5; w < 8; w++)
            if (wm[w] > m1 || (wm[w] == m1 && wi[w] < i1)) { m1 = wm[w]; i1 = wi[w]; }
        sc[0] = fmaxf(__fdiv_rn(m0, 7.0f), 1e-8f);
        sc[1] = fmaxf(__fdiv_rn(m1, 7.0f), 1e-8f);
        g_s0[t] = sc[0];
        g_s1[t] = sc[1];
        g_aidx[t * 2]     = i0;
        g_aidx[t * 2 + 1] = i1 - 512;
    }
    __syncthreads();
    float s = sc[tid >> 7];
    float vv[4] = {v.x, v.y, v.z, v.w};
    __nv_bfloat16 cd[4];
#pragma unroll
    for (int j = 0; j < 4; j++) {
        float u = __fdiv_rn(vv[j], s);
        float r = rintf(u);
        cd[j] = __float2bfloat16_rn(fminf(fmaxf(r, -8.0f), 7.0f));
        if (0.5f - fabsf(u - r) < TAU) {
            int idx = atomicAdd(&g_flagcnt, 1);
            if (idx < FCAP) g_flags[idx] = ((int)t << 10) | (tid * 4 + j);
        }
    }
    *(uint2*)&g_qx[t * TC + tid * 4] = *(uint2*)cd;
}

// -------- 5c) fix-up: exact serial fp32 chain for flagged codes --------
__global__ void k_fix(const float* __restrict__ x, const float* __restrict__ R0,
                      const float* __restrict__ R1) {
    int cnt = g_flagcnt;
    if (cnt > FCAP) cnt = FCAP;
    for (int i = blockIdx.x * blockDim.x + threadIdx.x; i < cnt;
         i += gridDim.x * blockDim.x) {
        int e = g_flags[i];
        int t = e >> 10, c = e & 1023;
        int h = c >> 9, cc = c & 511;
        const float* xr = x + (size_t)t * TC + h * TH;
        const float* R = h ? R1 : R0;
        int ac = g_aidx[t * 2 + h];
        float v = 0.0f, va = 0.0f;
        for (int k = 0; k < TH; k++) {
            float xv = xr[k];
            v  = __fmaf_rn(xv, R[k * TH + cc], v);
            va = __fmaf_rn(xv, R[k * TH + ac], va);
        }
        float s = fmaxf(__fdiv_rn(fabsf(va), 7.0f), 1e-8f);
        g_qx[(size_t)t * TC + c] = __float2bfloat16_rn(qcode(v, s));
    }
}

// -------- 6) main GEMM: bf16 HMMA on integer codes + fused skip/affine --------
__global__ void __launch_bounds__(256) k_main(const float* __restrict__ U,
                                              const float* __restrict__ bias,
                                              const float* __restrict__ ws0,
                                              const float* __restrict__ ws1,
                                              const float* __restrict__ gamma,
                                              const float* __restrict__ beta,
                                              float* __restrict__ out) {
    __shared__ __align__(16) __nv_bfloat16 As[128 * SMA];
    __shared__ __align__(16) __nv_bfloat16 Bs[128 * SMA];
    const int tid = threadIdx.x;
    const int lane = tid & 31, wid = tid >> 5;
    const int wm = wid >> 2, wn = wid & 3;
    const int n0 = blockIdx.x * 128, m0 = blockIdx.y * 128;

    float acc[4][4][4];
#pragma unroll
    for (int i = 0; i < 4; i++)
#pragma unroll
        for (int j = 0; j < 4; j++)
#pragma unroll
            for (int c = 0; c < 4; c++) acc[i][j][c] = 0.0f;

    const int g = lane >> 3, r = lane & 7;
    uint32_t smA = (uint32_t)__cvta_generic_to_shared(As);
    uint32_t smB = (uint32_t)__cvta_generic_to_shared(Bs);
    uint32_t aBase = smA + (uint32_t)(((wm * 64 + (g & 1) * 8 + r) * SMA + (g >> 1) * 8) * 2);
    uint32_t bBase = smB + (uint32_t)(((wn * 32 + (g >> 1) * 8 + r) * SMA + (g & 1) * 8) * 2);

    const int lrow = tid >> 2, lq = (tid & 3) * 8;
    const __nv_bfloat16* Ag = g_qx + (size_t)m0 * TC;
    const __nv_bfloat16* Bg = g_qwb + (size_t)n0 * TC;

    uint4 av0, av1, bv0, bv1;
    av0 = *(const uint4*)(Ag + (size_t)lrow * TC + lq);
    av1 = *(const uint4*)(Ag + (size_t)(lrow + 64) * TC + lq);
    bv0 = *(const uint4*)(Bg + (size_t)lrow * TC + lq);
    bv1 = *(const uint4*)(Bg + (size_t)(lrow + 64) * TC + lq);
    *(uint4*)&As[lrow * SMA + lq] = av0;
    *(uint4*)&As[(lrow + 64) * SMA + lq] = av1;
    *(uint4*)&Bs[lrow * SMA + lq] = bv0;
    *(uint4*)&Bs[(lrow + 64) * SMA + lq] = bv1;
    __syncthreads();

    const int qrow = lane >> 2, qcol = (lane & 3) * 2;

    for (int it = 0; it < 32; it++) {
        if (it < 31) {
            int k0 = (it + 1) * 32;
            av0 = *(const uint4*)(Ag + (size_t)lrow * TC + k0 + lq);
            av1 = *(const uint4*)(Ag + (size_t)(lrow + 64) * TC + k0 + lq);
            bv0 = *(const uint4*)(Bg + (size_t)lrow * TC + k0 + lq);
            bv1 = *(const uint4*)(Bg + (size_t)(lrow + 64) * TC + k0 + lq);
        }
        mm_compute(aBase, bBase, acc);
        if (it == 15) {
            float rr[4][2], rc[4][2];
#pragma unroll
            for (int mi = 0; mi < 4; mi++) {
                int rw = m0 + wm * 64 + mi * 16 + qrow;
                rr[mi][0] = __fdiv_rn(g_s0[rw], g_s1[rw]);
                rr[mi][1] = __fdiv_rn(g_s0[rw + 8], g_s1[rw + 8]);
            }
#pragma unroll
            for (int ni = 0; ni < 4; ni++) {
                int cl = n0 + wn * 32 + ni * 8 + qcol;
                rc[ni][0] = __fdiv_rn(ws0[cl], ws1[cl]);
                rc[ni][1] = __fdiv_rn(ws0[cl + 1], ws1[cl + 1]);
            }
#pragma unroll
            for (int mi = 0; mi < 4; mi++)
#pragma unroll
                for (int ni = 0; ni < 4; ni++) {
                    acc[mi][ni][0] *= rr[mi][0] * rc[ni][0];
                    acc[mi][ni][1] *= rr[mi][0] * rc[ni][1];
                    acc[mi][ni][2] *= rr[mi][1] * rc[ni][0];
                    acc[mi][ni][3] *= rr[mi][1] * rc[ni][1];
                }
        }
        __syncthreads();
        if (it < 31) {
            *(uint4*)&As[lrow * SMA + lq] = av0;
            *(uint4*)&As[(lrow + 64) * SMA + lq] = av1;
            *(uint4*)&Bs[lrow * SMA + lq] = bv0;
            *(uint4*)&Bs[(lrow + 64) * SMA + lq] = bv1;
            __syncthreads();
        }
    }

    {
        float sr[4][2], sc[4][2];
#pragma unroll
        for (int mi = 0; mi < 4; mi++) {
            int rw = m0 + wm * 64 + mi * 16 + qrow;
            sr[mi][0] = g_s1[rw];
            sr[mi][1] = g_s1[rw + 8];
        }
#pragma unroll
        for (int ni = 0; ni < 4; ni++) {
            int cl = n0 + wn * 32 + ni * 8 + qcol;
            sc[ni][0] = ws1[cl];
            sc[ni][1] = ws1[cl + 1];
        }
#pragma unroll
        for (int mi = 0; mi < 4; mi++)
#pragma unroll
            for (int ni = 0; ni < 4; ni++) {
                acc[mi][ni][0] *= sr[mi][0] * sc[ni][0];
                acc[mi][ni][1] *= sr[mi][0] * sc[ni][1];
                acc[mi][ni][2] *= sr[mi][1] * sc[ni][0];
                acc[mi][ni][3] *= sr[mi][1] * sc[ni][1];
            }
    }

#pragma unroll 1
    for (int pass = 0; pass < 3; pass++) {
        __syncthreads();
#pragma unroll
        for (int l = 0; l < 16; l++) {
            int idx = tid + l * 256, row = idx >> 5, c = idx & 31;
            if (pass != 1) {
                float v = g_p[(size_t)(m0 + row) * TR + c];
                __nv_bfloat16 h = __float2bfloat16_rn(v);
                As[row * SMA + c] =
                    (pass == 2) ? __float2bfloat16_rn(v - __bfloat162float(h)) : h;
            }
            {
                float v = U[(size_t)(n0 + row) * TR + c];
                __nv_bfloat16 h = __float2bfloat16_rn(v);
                Bs[row * SMA + c] =
                    (pass == 1) ? __float2bfloat16_rn(v - __bfloat162float(h)) : h;
            }
        }
        __syncthreads();
        mm_compute(aBase, bBase, acc);
    }

    float bi[4][2], ga[4][2], be[4][2];
#pragma unroll
    for (int ni = 0; ni < 4; ni++) {
        int cl = n0 + wn * 32 + ni * 8 + qcol;
        bi[ni][0] = bias[cl];  bi[ni][1] = bias[cl + 1];
        ga[ni][0] = gamma[cl]; ga[ni][1] = gamma[cl + 1];
        be[ni][0] = beta[cl];  be[ni][1] = beta[cl + 1];
    }
#pragma unroll
    for (int mi = 0; mi < 4; mi++) {
        size_t r0 = m0 + wm * 64 + mi * 16 + qrow;
#pragma unroll
        for (int ni = 0; ni < 4; ni++) {
            int cl = n0 + wn * 32 + ni * 8 + qcol;
            float2 o0, o1;
            o0.x = __fmaf_rn(acc[mi][ni][0] + bi[ni][0], ga[ni][0], be[ni][0]);
            o0.y = __fmaf_rn(acc[mi][ni][1] + bi[ni][1], ga[ni][1], be[ni][1]);
            o1.x = __fmaf_rn(acc[mi][ni][2] + bi[ni][0], ga[ni][0], be[ni][0]);
            o1.y = __fmaf_rn(acc[mi][ni][3] + bi[ni][1], ga[ni][1], be[ni][1]);
            *(float2*)&out[r0 * TO + cl] = o0;
            *(float2*)&out[(r0 + 8) * TO + cl] = o1;
        }
    }
}

extern "C" void kernel_launch(void* const* d_in, const int* in_sizes, int n_in,
                              void* d_out, int out_size) {
    const float* x     = (const float*)d_in[0];
    const float* w     = (const float*)d_in[1];
    const float* bias  = (const float*)d_in[2];
    const float* U     = (const float*)d_in[3];
    const float* V     = (const float*)d_in[4];
    const float* R0    = (const float*)d_in[5];
    const float* R1    = (const float*)d_in[6];
    const float* ws0   = (const float*)d_in[7];
    const float* ws1   = (const float*)d_in[8];
    const float* gamma = (const float*)d_in[9];
    const float* beta  = (const float*)d_in[10];
    float* out = (float*)d_out;

    k_wres<<<TO, 256>>>(w, U, V);
    k_wrotq<<<dim3(256, 2), 256>>>(R0, R1, ws0, ws1);
    k_xrot<<<dim3(4, 256, 2), 256>>>(x, R0, R1);
    k_p<<<256, 256>>>(x, V);
    k_zero<<<1, 1>>>();
    k_quant<<<MT, 256>>>();
    k_fix<<<1024, 128>>>(x, R0, R1);
    k_main<<<dim3(8, 256), 256>>>(U, bias, ws0, ws1, gamma, beta, out);
}

// round 10
// speedup vs baseline: 3.1973x; 1.0861x over previous
#include <cuda_runtime.h>
#include <cuda_bf16.h>
#include <cstdint>

#define MT 32768
#define TC 1024
#define TH 512
#define TO 1024
#define TR 32
#define FCAP (1 << 22)
#define TAU 6e-4f

__device__ float g_wres[(size_t)TO * TC];
__device__ __nv_bfloat16 g_qwb[(size_t)TO * TC];
__device__ float g_x[(size_t)MT * TC];               // rotated activations
__device__ __nv_bfloat16 g_qx[(size_t)MT * TC];      // activation codes
__device__ __nv_bfloat16 g_xh[(size_t)MT * TC];      // x split hi (bf16)
__device__ __nv_bfloat16 g_xm[(size_t)MT * TC];      // x split residual (bf16)
__device__ __nv_bfloat16 g_rh[2 * TH * TH];          // R^T split hi   [half][n][k]
__device__ __nv_bfloat16 g_rm[2 * TH * TH];          // R^T split res
__device__ float g_s0[MT];
__device__ float g_s1[MT];
__device__ float g_p[(size_t)MT * TR];
__device__ int g_flagcnt;
__device__ int g_flags[FCAP];
__device__ int g_aidx[MT * 2];

__device__ __forceinline__ float qcode(float v, float s) {
    float q = rintf(__fdiv_rn(v, s));
    return fminf(fmaxf(q, -8.0f), 7.0f);
}

// ---- shared MMA helpers (bf16 m16n8k16, ldmatrix, [row][k] smem, stride SMA) ----
#define SMA 40

__device__ __forceinline__ void mma_bf16(float* c, uint32_t a0, uint32_t a1,
                                         uint32_t a2, uint32_t a3,
                                         uint32_t b0, uint32_t b1) {
    asm volatile(
        "mma.sync.aligned.m16n8k16.row.col.f32.bf16.bf16.f32 "
        "{%0,%1,%2,%3}, {%4,%5,%6,%7}, {%8,%9}, {%0,%1,%2,%3};"
        : "+f"(c[0]), "+f"(c[1]), "+f"(c[2]), "+f"(c[3])
        : "r"(a0), "r"(a1), "r"(a2), "r"(a3), "r"(b0), "r"(b1));
}

__device__ __forceinline__ void ldsm4(uint32_t* r, uint32_t addr) {
    asm volatile("ldmatrix.sync.aligned.m8n8.x4.shared.b16 {%0,%1,%2,%3}, [%4];"
                 : "=r"(r[0]), "=r"(r[1]), "=r"(r[2]), "=r"(r[3]) : "r"(addr));
}

__device__ __forceinline__ void mm_compute(uint32_t aBase, uint32_t bBase,
                                           float (&acc)[4][4][4]) {
#pragma unroll
    for (int ks = 0; ks < 2; ks++) {
        uint32_t a[4][4], b[2][4];
#pragma unroll
        for (int mi = 0; mi < 4; mi++) ldsm4(a[mi], aBase + mi * (16 * SMA * 2) + ks * 32);
#pragma unroll
        for (int p = 0; p < 2; p++) ldsm4(b[p], bBase + p * (16 * SMA * 2) + ks * 32);
#pragma unroll
        for (int mi = 0; mi < 4; mi++)
#pragma unroll
            for (int ni = 0; ni < 4; ni++) {
                int p = ni >> 1, s = (ni & 1) * 2;
                mma_bf16(acc[mi][ni], a[mi][0], a[mi][1], a[mi][2], a[mi][3],
                         b[p][s], b[p][s + 1]);
            }
    }
}

// ---------------- 1) w_res = w - U @ V ----------------
__global__ void k_wres(const float* __restrict__ w, const float* __restrict__ U,
                       const float* __restrict__ V) {
    int o = blockIdx.x;
    __shared__ float u[TR];
    if (threadIdx.x < TR) u[threadIdx.x] = U[o * TR + threadIdx.x];
    __syncthreads();
    for (int c = threadIdx.x; c < TC; c += 256) {
        float acc = w[(size_t)o * TC + c];
#pragma unroll
        for (int r = 0; r < TR; r++) acc = __fmaf_rn(-u[r], V[r * TC + c], acc);
        g_wres[(size_t)o * TC + c] = acc;
    }
}

// ------- 2) weight rotate (Kahan fp32) + static quant -> bf16 codes -------
__global__ void __launch_bounds__(256) k_wrotq(const float* __restrict__ R0,
                                               const float* __restrict__ R1,
                                               const float* __restrict__ ws0,
                                               const float* __restrict__ ws1) {
    int half = blockIdx.y;
    const float* R = half ? R1 : R0;
    const float* ws = half ? ws1 : ws0;
    int o0 = blockIdx.x * 4;
    __shared__ float wr[4][TH];
    for (int i = threadIdx.x; i < 4 * TH; i += 256)
        wr[i >> 9][i & 511] = g_wres[(size_t)(o0 + (i >> 9)) * TC + half * TH + (i & 511)];
    __syncthreads();
    int n = threadIdx.x;
    float s[4][2] = {}, c[4][2] = {};
    for (int k = 0; k < TH; k++) {
        float b0 = R[k * TH + n], b1 = R[k * TH + n + 256];
#pragma unroll
        for (int i = 0; i < 4; i++) {
            float a = wr[i][k];
            float p0 = __fmul_rn(a, b0);
            float y0 = __fadd_rn(p0, -c[i][0]);
            float t0 = __fadd_rn(s[i][0], y0);
            c[i][0] = __fadd_rn(__fadd_rn(t0, -s[i][0]), -y0);
            s[i][0] = t0;
            float p1 = __fmul_rn(a, b1);
            float y1 = __fadd_rn(p1, -c[i][1]);
            float t1 = __fadd_rn(s[i][1], y1);
            c[i][1] = __fadd_rn(__fadd_rn(t1, -s[i][1]), -y1);
            s[i][1] = t1;
        }
    }
#pragma unroll
    for (int i = 0; i < 4; i++) {
        float sw = ws[o0 + i];
        g_qwb[(size_t)(o0 + i) * TC + half * TH + n]       = __float2bfloat16_rn(qcode(s[i][0], sw));
        g_qwb[(size_t)(o0 + i) * TC + half * TH + n + 256] = __float2bfloat16_rn(qcode(s[i][1], sw));
    }
}

// -------- 2b) pre-split R into transposed bf16 h/m: g_rh/g_rm [half][n][k] --------
__global__ void k_rsplit(const float* __restrict__ R0, const float* __restrict__ R1) {
    int half = blockIdx.y, n = blockIdx.x;
    const float* R = half ? R1 : R0;
    size_t ob = (size_t)half * TH * TH + (size_t)n * TH;
    for (int k = threadIdx.x; k < TH; k += 256) {
        float v = R[(size_t)k * TH + n];
        __nv_bfloat16 h = __float2bfloat16_rn(v);
        g_rh[ob + k] = h;
        g_rm[ob + k] = __float2bfloat16_rn(v - __bfloat162float(h));
    }
}

// -------- 2c) pre-split x into bf16 h/m --------
__global__ void __launch_bounds__(256) k_xsplit(const float* __restrict__ x) {
    size_t base = ((size_t)blockIdx.x * 256 + threadIdx.x) * 16;
    __nv_bfloat16 h16[16], m16[16];
#pragma unroll
    for (int j = 0; j < 4; j++) {
        float4 v = *(const float4*)(x + base + j * 4);
        float vv[4] = {v.x, v.y, v.z, v.w};
#pragma unroll
        for (int q = 0; q < 4; q++) {
            __nv_bfloat16 h = __float2bfloat16_rn(vv[q]);
            h16[j * 4 + q] = h;
            m16[j * 4 + q] = __float2bfloat16_rn(vv[q] - __bfloat162float(h));
        }
    }
    *(uint4*)&g_xh[base]     = *(uint4*)&h16[0];
    *(uint4*)&g_xh[base + 8] = *(uint4*)&h16[8];
    *(uint4*)&g_xm[base]     = *(uint4*)&m16[0];
    *(uint4*)&g_xm[base + 8] = *(uint4*)&m16[8];
}

// ------- 3) x rotation: bf16 HMMA, 3 passes, pre-split operands + reg prefetch -------
__global__ void __launch_bounds__(256) k_xrot() {
    __shared__ __align__(16) __nv_bfloat16 Ah[128 * SMA], Am[128 * SMA];
    __shared__ __align__(16) __nv_bfloat16 Bh[128 * SMA], Bm[128 * SMA];
    const int half = blockIdx.z;
    const int n0 = blockIdx.x * 128, m0 = blockIdx.y * 128;
    const int tid = threadIdx.x, lane = tid & 31, wid = tid >> 5;
    const int wm = wid >> 2, wn = wid & 3;

    float acc[4][4][4];
#pragma unroll
    for (int i = 0; i < 4; i++)
#pragma unroll
        for (int j = 0; j < 4; j++)
#pragma unroll
            for (int c = 0; c < 4; c++) acc[i][j][c] = 0.0f;

    const int g = lane >> 3, r = lane & 7;
    uint32_t smAh = (uint32_t)__cvta_generic_to_shared(Ah);
    uint32_t smAm = (uint32_t)__cvta_generic_to_shared(Am);
    uint32_t smBh = (uint32_t)__cvta_generic_to_shared(Bh);
    uint32_t smBm = (uint32_t)__cvta_generic_to_shared(Bm);
    uint32_t aoff = (uint32_t)(((wm * 64 + (g & 1) * 8 + r) * SMA + (g >> 1) * 8) * 2);
    uint32_t boff = (uint32_t)(((wn * 32 + (g >> 1) * 8 + r) * SMA + (g & 1) * 8) * 2);

    const int srow = tid >> 1, skq = (tid & 1) * 16;   // 128 rows x 32 k staging
    const __nv_bfloat16* Axh = g_xh + (size_t)(m0 + srow) * TC + half * TH + skq;
    const __nv_bfloat16* Axm = g_xm + (size_t)(m0 + srow) * TC + half * TH + skq;
    const __nv_bfloat16* Brh = g_rh + (size_t)half * TH * TH + (size_t)(n0 + srow) * TH + skq;
    const __nv_bfloat16* Brm = g_rm + (size_t)half * TH * TH + (size_t)(n0 + srow) * TH + skq;

    uint4 a0 = *(const uint4*)Axh,       a1 = *(const uint4*)(Axh + 8);
    uint4 a2 = *(const uint4*)Axm,       a3 = *(const uint4*)(Axm + 8);
    uint4 b0 = *(const uint4*)Brh,       b1 = *(const uint4*)(Brh + 8);
    uint4 b2 = *(const uint4*)Brm,       b3 = *(const uint4*)(Brm + 8);

    for (int it = 0; it < 16; it++) {
        *(uint4*)&Ah[srow * SMA + skq]     = a0;
        *(uint4*)&Ah[srow * SMA + skq + 8] = a1;
        *(uint4*)&Am[srow * SMA + skq]     = a2;
        *(uint4*)&Am[srow * SMA + skq + 8] = a3;
        *(uint4*)&Bh[srow * SMA + skq]     = b0;
        *(uint4*)&Bh[srow * SMA + skq + 8] = b1;
        *(uint4*)&Bm[srow * SMA + skq]     = b2;
        *(uint4*)&Bm[srow * SMA + skq + 8] = b3;
        __syncthreads();
        if (it < 15) {
            int k0 = (it + 1) * 32;
            a0 = *(const uint4*)(Axh + k0);  a1 = *(const uint4*)(Axh + k0 + 8);
            a2 = *(const uint4*)(Axm + k0);  a3 = *(const uint4*)(Axm + k0 + 8);
            b0 = *(const uint4*)(Brh + k0);  b1 = *(const uint4*)(Brh + k0 + 8);
            b2 = *(const uint4*)(Brm + k0);  b3 = *(const uint4*)(Brm + k0 + 8);
        }
        mm_compute(smAh + aoff, smBm + boff, acc);   // h*m
        mm_compute(smAm + aoff, smBh + boff, acc);   // m*h
        mm_compute(smAh + aoff, smBh + boff, acc);   // h*h
        __syncthreads();
    }

    const int qrow = lane >> 2, qcol = (lane & 3) * 2;
#pragma unroll
    for (int mi = 0; mi < 4; mi++) {
        size_t row = m0 + wm * 64 + mi * 16 + qrow;
#pragma unroll
        for (int ni = 0; ni < 4; ni++) {
            int col = half * TH + n0 + wn * 32 + ni * 8 + qcol;
            *(float2*)&g_x[row * TC + col] = make_float2(acc[mi][ni][0], acc[mi][ni][1]);
            *(float2*)&g_x[(row + 8) * TC + col] = make_float2(acc[mi][ni][2], acc[mi][ni][3]);
        }
    }
}

// ------- 4) p = x @ V^T via bf16 3-pass MMA (smooth path) -------
__global__ void __launch_bounds__(256) k_p(const float* __restrict__ V) {
    __shared__ __align__(16) __nv_bfloat16 Ah[128 * SMA], Am[128 * SMA];
    __shared__ __align__(16) __nv_bfloat16 Bh[32 * SMA], Bm[32 * SMA];
    const int m0 = blockIdx.x * 128;
    const int tid = threadIdx.x, lane = tid & 31, wid = tid >> 5;   // 8 M-warps x 16 rows

    float acc[4][4];
#pragma unroll
    for (int i = 0; i < 4; i++)
#pragma unroll
        for (int c = 0; c < 4; c++) acc[i][c] = 0.0f;

    const int g = lane >> 3, r = lane & 7;
    uint32_t smAh = (uint32_t)__cvta_generic_to_shared(Ah);
    uint32_t smAm = (uint32_t)__cvta_generic_to_shared(Am);
    uint32_t smBh = (uint32_t)__cvta_generic_to_shared(Bh);
    uint32_t smBm = (uint32_t)__cvta_generic_to_shared(Bm);
    uint32_t aoff = (uint32_t)(((wid * 16 + (g & 1) * 8 + r) * SMA + (g >> 1) * 8) * 2);
    uint32_t boff = (uint32_t)((((g >> 1) * 8 + r) * SMA + (g & 1) * 8) * 2);

    const int srow = tid >> 1, skq = (tid & 1) * 16;
    const __nv_bfloat16* Axh = g_xh + (size_t)(m0 + srow) * TC + skq;
    const __nv_bfloat16* Axm = g_xm + (size_t)(m0 + srow) * TC + skq;
    const int vr = tid >> 3, vkq = (tid & 7) * 4;
    const float* Vg = V + (size_t)vr * TC + vkq;

    uint4 a0 = *(const uint4*)Axh, a1 = *(const uint4*)(Axh + 8);
    uint4 a2 = *(const uint4*)Axm, a3 = *(const uint4*)(Axm + 8);
    float4 bv = *(const float4*)Vg;

    for (int it = 0; it < 32; it++) {
        *(uint4*)&Ah[srow * SMA + skq]     = a0;
        *(uint4*)&Ah[srow * SMA + skq + 8] = a1;
        *(uint4*)&Am[srow * SMA + skq]     = a2;
        *(uint4*)&Am[srow * SMA + skq + 8] = a3;
        {
            float vv[4] = {bv.x, bv.y, bv.z, bv.w};
            __nv_bfloat16 h4[4], m4[4];
#pragma unroll
            for (int q = 0; q < 4; q++) {
                __nv_bfloat16 h = __float2bfloat16_rn(vv[q]);
                h4[q] = h;
                m4[q] = __float2bfloat16_rn(vv[q] - __bfloat162float(h));
            }
            *(uint2*)&Bh[vr * SMA + vkq] = *(uint2*)h4;
            *(uint2*)&Bm[vr * SMA + vkq] = *(uint2*)m4;
        }
        __syncthreads();
        if (it < 31) {
            int k0 = (it + 1) * 32;
            a0 = *(const uint4*)(Axh + k0);  a1 = *(const uint4*)(Axh + k0 + 8);
            a2 = *(const uint4*)(Axm + k0);  a3 = *(const uint4*)(Axm + k0 + 8);
            bv = *(const float4*)(Vg + k0);
        }
#pragma unroll 1
        for (int pass = 0; pass < 3; pass++) {
            uint32_t aB = (pass == 1) ? smAm + aoff : smAh + aoff;
            uint32_t bB = (pass == 0) ? smBm + boff : smBh + boff;
#pragma unroll
            for (int ks = 0; ks < 2; ks++) {
                uint32_t a[4], b[2][4];
                ldsm4(a, aB + ks * 32);
                ldsm4(b[0], bB + ks * 32);
                ldsm4(b[1], bB + 16 * SMA * 2 + ks * 32);
#pragma unroll
                for (int ni = 0; ni < 4; ni++) {
                    int p = ni >> 1, s = (ni & 1) * 2;
                    mma_bf16(acc[ni], a[0], a[1], a[2], a[3], b[p][s], b[p][s + 1]);
                }
            }
        }
        __syncthreads();
    }

    const int qrow = lane >> 2, qcol = (lane & 3) * 2;
#pragma unroll
    for (int ni = 0; ni < 4; ni++) {
        size_t row = m0 + wid * 16 + qrow;
        int col = ni * 8 + qcol;
        *(float2*)&g_p[row * TR + col]       = make_float2(acc[ni][0], acc[ni][1]);
        *(float2*)&g_p[(row + 8) * TR + col] = make_float2(acc[ni][2], acc[ni][3]);
    }
}

// -------- 5a) zero flag counter --------
__global__ void k_zero() { g_flagcnt = 0; }

// -------- 5b) dynamic quant: scales + argmax + codes + boundary flags --------
__global__ void k_quant() {
    size_t t = blockIdx.x;
    int tid = threadIdx.x;
    float4 v = *(float4*)&g_x[t * TC + tid * 4];
    float a0 = fabsf(v.x), a1 = fabsf(v.y), a2 = fabsf(v.z), a3 = fabsf(v.w);
    float m = a0; int mi = tid * 4;
    if (a1 > m) { m = a1; mi = tid * 4 + 1; }
    if (a2 > m) { m = a2; mi = tid * 4 + 2; }
    if (a3 > m) { m = a3; mi = tid * 4 + 3; }
#pragma unroll
    for (int o = 16; o; o >>= 1) {
        float om = __shfl_xor_sync(0xffffffffu, m, o);
        int   oi = __shfl_xor_sync(0xffffffffu, mi, o);
        if (om > m || (om == m && oi < mi)) { m = om; mi = oi; }
    }
    __shared__ float wm[8];
    __shared__ int   wi[8];
    __shared__ float sc[2];
    if ((tid & 31) == 0) { wm[tid >> 5] = m; wi[tid >> 5] = mi; }
    __syncthreads();
    if (tid == 0) {
        float m0 = wm[0]; int i0 = wi[0];
#pragma unroll
        for (int w = 1; w < 4; w++)
            if (wm[w] > m0 || (wm[w] == m0 && wi[w] < i0)) { m0 = wm[w]; i0 = wi[w]; }
        float m1 = wm[4]; int i1 = wi[4];
#pragma unroll
        for (int w = 5; w < 8; w++)
            if (wm[w] > m1 || (wm[w] == m1 && wi[w] < i1)) { m1 = wm[w]; i1 = wi[w]; }
        sc[0] = fmaxf(__fdiv_rn(m0, 7.0f), 1e-8f);
        sc[1] = fmaxf(__fdiv_rn(m1, 7.0f), 1e-8f);
        g_s0[t] = sc[0];
        g_s1[t] = sc[1];
        g_aidx[t * 2]     = i0;
        g_aidx[t * 2 + 1] = i1 - 512;
    }
    __syncthreads();
    float s = sc[tid >> 7];
    float vv[4] = {v.x, v.y, v.z, v.w};
    __nv_bfloat16 cd[4];
#pragma unroll
    for (int j = 0; j < 4; j++) {
        float u = __fdiv_rn(vv[j], s);
        float r = rintf(u);
        cd[j] = __float2bfloat16_rn(fminf(fmaxf(r, -8.0f), 7.0f));
        if (0.5f - fabsf(u - r) < TAU) {
            int idx = atomicAdd(&g_flagcnt, 1);
            if (idx < FCAP) g_flags[idx] = ((int)t << 10) | (tid * 4 + j);
        }
    }
    *(uint2*)&g_qx[t * TC + tid * 4] = *(uint2*)cd;
}

// -------- 5c) fix-up: exact serial fp32 chain for flagged codes --------
__global__ void k_fix(const float* __restrict__ x, const float* __restrict__ R0,
                      const float* __restrict__ R1) {
    int cnt = g_flagcnt;
    if (cnt > FCAP) cnt = FCAP;
    for (int i = blockIdx.x * blockDim.x + threadIdx.x; i < cnt;
         i += gridDim.x * blockDim.x) {
        int e = g_flags[i];
        int t = e >> 10, c = e & 1023;
        int h = c >> 9, cc = c & 511;
        const float* xr = x + (size_t)t * TC + h * TH;
        const float* R = h ? R1 : R0;
        int ac = g_aidx[t * 2 + h];
        float v = 0.0f, va = 0.0f;
        for (int k = 0; k < TH; k++) {
            float xv = xr[k];
            v  = __fmaf_rn(xv, R[k * TH + cc], v);
            va = __fmaf_rn(xv, R[k * TH + ac], va);
        }
        float s = fmaxf(__fdiv_rn(fabsf(va), 7.0f), 1e-8f);
        g_qx[(size_t)t * TC + c] = __float2bfloat16_rn(qcode(v, s));
    }
}

// -------- 6) main GEMM: bf16 HMMA on integer codes + fused skip/affine --------
__global__ void __launch_bounds__(256) k_main(const float* __restrict__ U,
                                              const float* __restrict__ bias,
                                              const float* __restrict__ ws0,
                                              const float* __restrict__ ws1,
                                              const float* __restrict__ gamma,
                                              const float* __restrict__ beta,
                                              float* __restrict__ out) {
    __shared__ __align__(16) __nv_bfloat16 As[128 * SMA];
    __shared__ __align__(16) __nv_bfloat16 Bs[128 * SMA];
    const int tid = threadIdx.x;
    const int lane = tid & 31, wid = tid >> 5;
    const int wm = wid >> 2, wn = wid & 3;
    const int n0 = blockIdx.x * 128, m0 = blockIdx.y * 128;

    float acc[4][4][4];
#pragma unroll
    for (int i = 0; i < 4; i++)
#pragma unroll
        for (int j = 0; j < 4; j++)
#pragma unroll
            for (int c = 0; c < 4; c++) acc[i][j][c] = 0.0f;

    const int g = lane >> 3, r = lane & 7;
    uint32_t smA = (uint32_t)__cvta_generic_to_shared(As);
    uint32_t smB = (uint32_t)__cvta_generic_to_shared(Bs);
    uint32_t aBase = smA + (uint32_t)(((wm * 64 + (g & 1) * 8 + r) * SMA + (g >> 1) * 8) * 2);
    uint32_t bBase = smB + (uint32_t)(((wn * 32 + (g >> 1) * 8 + r) * SMA + (g & 1) * 8) * 2);

    const int lrow = tid >> 2, lq = (tid & 3) * 8;
    const __nv_bfloat16* Ag = g_qx + (size_t)m0 * TC;
    const __nv_bfloat16* Bg = g_qwb + (size_t)n0 * TC;

    uint4 av0, av1, bv0, bv1;
    av0 = *(const uint4*)(Ag + (size_t)lrow * TC + lq);
    av1 = *(const uint4*)(Ag + (size_t)(lrow + 64) * TC + lq);
    bv0 = *(const uint4*)(Bg + (size_t)lrow * TC + lq);
    bv1 = *(const uint4*)(Bg + (size_t)(lrow + 64) * TC + lq);
    *(uint4*)&As[lrow * SMA + lq] = av0;
    *(uint4*)&As[(lrow + 64) * SMA + lq] = av1;
    *(uint4*)&Bs[lrow * SMA + lq] = bv0;
    *(uint4*)&Bs[(lrow + 64) * SMA + lq] = bv1;
    __syncthreads();

    const int qrow = lane >> 2, qcol = (lane & 3) * 2;

    for (int it = 0; it < 32; it++) {
        if (it < 31) {
            int k0 = (it + 1) * 32;
            av0 = *(const uint4*)(Ag + (size_t)lrow * TC + k0 + lq);
            av1 = *(const uint4*)(Ag + (size_t)(lrow + 64) * TC + k0 + lq);
            bv0 = *(const uint4*)(Bg + (size_t)lrow * TC + k0 + lq);
            bv1 = *(const uint4*)(Bg + (size_t)(lrow + 64) * TC + k0 + lq);
        }
        mm_compute(aBase, bBase, acc);
        if (it == 15) {
            float rr[4][2], rc[4][2];
#pragma unroll
            for (int mi = 0; mi < 4; mi++) {
                int rw = m0 + wm * 64 + mi * 16 + qrow;
                rr[mi][0] = __fdiv_rn(g_s0[rw], g_s1[rw]);
                rr[mi][1] = __fdiv_rn(g_s0[rw + 8], g_s1[rw + 8]);
            }
#pragma unroll
            for (int ni = 0; ni < 4; ni++) {
                int cl = n0 + wn * 32 + ni * 8 + qcol;
                rc[ni][0] = __fdiv_rn(ws0[cl], ws1[cl]);
                rc[ni][1] = __fdiv_rn(ws0[cl + 1], ws1[cl + 1]);
            }
#pragma unroll
            for (int mi = 0; mi < 4; mi++)
#pragma unroll
                for (int ni = 0; ni < 4; ni++) {
                    acc[mi][ni][0] *= rr[mi][0] * rc[ni][0];
                    acc[mi][ni][1] *= rr[mi][0] * rc[ni][1];
                    acc[mi][ni][2] *= rr[mi][1] * rc[ni][0];
                    acc[mi][ni][3] *= rr[mi][1] * rc[ni][1];
                }
        }
        __syncthreads();
        if (it < 31) {
            *(uint4*)&As[lrow * SMA + lq] = av0;
            *(uint4*)&As[(lrow + 64) * SMA + lq] = av1;
            *(uint4*)&Bs[lrow * SMA + lq] = bv0;
            *(uint4*)&Bs[(lrow + 64) * SMA + lq] = bv1;
            __syncthreads();
        }
    }

    {
        float sr[4][2], sc[4][2];
#pragma unroll
        for (int mi = 0; mi < 4; mi++) {
            int rw = m0 + wm * 64 + mi * 16 + qrow;
            sr[mi][0] = g_s1[rw];
            sr[mi][1] = g_s1[rw + 8];
        }
#pragma unroll
        for (int ni = 0; ni < 4; ni++) {
            int cl = n0 + wn * 32 + ni * 8 + qcol;
            sc[ni][0] = ws1[cl];
            sc[ni][1] = ws1[cl + 1];
        }
#pragma unroll
        for (int mi = 0; mi < 4; mi++)
#pragma unroll
            for (int ni = 0; ni < 4; ni++) {
                acc[mi][ni][0] *= sr[mi][0] * sc[ni][0];
                acc[mi][ni][1] *= sr[mi][0] * sc[ni][1];
                acc[mi][ni][2] *= sr[mi][1] * sc[ni][0];
                acc[mi][ni][3] *= sr[mi][1] * sc[ni][1];
            }
    }

#pragma unroll 1
    for (int pass = 0; pass < 3; pass++) {
        __syncthreads();
#pragma unroll
        for (int l = 0; l < 16; l++) {
            int idx = tid + l * 256, row = idx >> 5, c = idx & 31;
            if (pass != 1) {
                float v = g_p[(size_t)(m0 + row) * TR + c];
                __nv_bfloat16 h = __float2bfloat16_rn(v);
                As[row * SMA + c] =
                    (pass == 2) ? __float2bfloat16_rn(v - __bfloat162float(h)) : h;
            }
            {
                float v = U[(size_t)(n0 + row) * TR + c];
                __nv_bfloat16 h = __float2bfloat16_rn(v);
                Bs[row * SMA + c] =
                    (pass == 1) ? __float2bfloat16_rn(v - __bfloat162float(h)) : h;
            }
        }
        __syncthreads();
        mm_compute(aBase, bBase, acc);
    }

    float bi[4][2], ga[4][2], be[4][2];
#pragma unroll
    for (int ni = 0; ni < 4; ni++) {
        int cl = n0 + wn * 32 + ni * 8 + qcol;
        bi[ni][0] = bias[cl];  bi[ni][1] = bias[cl + 1];
        ga[ni][0] = gamma[cl]; ga[ni][1] = gamma[cl + 1];
        be[ni][0] = beta[cl];  be[ni][1] = beta[cl + 1];
    }
#pragma unroll
    for (int mi = 0; mi < 4; mi++) {
        size_t r0 = m0 + wm * 64 + mi * 16 + qrow;
#pragma unroll
        for (int ni = 0; ni < 4; ni++) {
            int cl = n0 + wn * 32 + ni * 8 + qcol;
            float2 o0, o1;
            o0.x = __fmaf_rn(acc[mi][ni][0] + bi[ni][0], ga[ni][0], be[ni][0]);
            o0.y = __fmaf_rn(acc[mi][ni][1] + bi[ni][1], ga[ni][1], be[ni][1]);
            o1.x = __fmaf_rn(acc[mi][ni][2] + bi[ni][0], ga[ni][0], be[ni][0]);
            o1.y = __fmaf_rn(acc[mi][ni][3] + bi[ni][1], ga[ni][1], be[ni][1]);
            *(float2*)&out[r0 * TO + cl] = o0;
            *(float2*)&out[(r0 + 8) * TO + cl] = o1;
        }
    }
}

extern "C" void kernel_launch(void* const* d_in, const int* in_sizes, int n_in,
                              void* d_out, int out_size) {
    const float* x     = (const float*)d_in[0];
    const float* w     = (const float*)d_in[1];
    const float* bias  = (const float*)d_in[2];
    const float* U     = (const float*)d_in[3];
    const float* V     = (const float*)d_in[4];
    const float* R0    = (const float*)d_in[5];
    const float* R1    = (const float*)d_in[6];
    const float* ws0   = (const float*)d_in[7];
    const float* ws1   = (const float*)d_in[8];
    const float* gamma = (const float*)d_in[9];
    const float* beta  = (const float*)d_in[10];
    float* out = (float*)d_out;

    k_wres<<<TO, 256>>>(w, U, V);
    k_wrotq<<<dim3(256, 2), 256>>>(R0, R1, ws0, ws1);
    k_rsplit<<<dim3(TH, 2), 256>>>(R0, R1);
    k_xsplit<<<(int)(((size_t)MT * TC) / (256 * 16)), 256>>>(x);
    k_xrot<<<dim3(4, 256, 2), 256>>>();
    k_p<<<256, 256>>>(V);
    k_zero<<<1, 1>>>();
    k_quant<<<MT, 256>>>();
    k_fix<<<1024, 128>>>(x, R0, R1);
    k_main<<<dim3(8, 256), 256>>>(U, bias, ws0, ws1, gamma, beta, out);
}

// round 11
// speedup vs baseline: 3.2360x; 1.0121x over previous
#include <cuda_runtime.h>
#include <cuda_bf16.h>
#include <cstdint>

#define MT 32768
#define TC 1024
#define TH 512
#define TO 1024
#define TR 32
#define FCAP (1 << 22)
#define TAU 6e-4f

__device__ float g_wres[(size_t)TO * TC];
__device__ __nv_bfloat16 g_qwb[(size_t)TO * TC];
__device__ float g_x[(size_t)MT * TC];               // rotated activations
__device__ __nv_bfloat16 g_qx[(size_t)MT * TC];      // activation codes
__device__ __nv_bfloat16 g_xh[(size_t)MT * TC];      // x split hi (bf16)
__device__ __nv_bfloat16 g_xm[(size_t)MT * TC];      // x split residual (bf16)
__device__ __nv_bfloat16 g_rh[2 * TH * TH];          // R^T split hi   [half][n][k]
__device__ __nv_bfloat16 g_rm[2 * TH * TH];          // R^T split res
__device__ float g_s0[MT];
__device__ float g_s1[MT];
__device__ float g_p[(size_t)MT * TR];
__device__ int g_flagcnt;
__device__ int g_flags[FCAP];
__device__ int g_aidx[MT * 2];

__device__ __forceinline__ float qcode(float v, float s) {
    float q = rintf(__fdiv_rn(v, s));
    return fminf(fmaxf(q, -8.0f), 7.0f);
}

// ---- shared MMA helpers (bf16 m16n8k16, ldmatrix, [row][k] smem, stride SMA) ----
#define SMA 40

__device__ __forceinline__ void mma_bf16(float* c, uint32_t a0, uint32_t a1,
                                         uint32_t a2, uint32_t a3,
                                         uint32_t b0, uint32_t b1) {
    asm volatile(
        "mma.sync.aligned.m16n8k16.row.col.f32.bf16.bf16.f32 "
        "{%0,%1,%2,%3}, {%4,%5,%6,%7}, {%8,%9}, {%0,%1,%2,%3};"
        : "+f"(c[0]), "+f"(c[1]), "+f"(c[2]), "+f"(c[3])
        : "r"(a0), "r"(a1), "r"(a2), "r"(a3), "r"(b0), "r"(b1));
}

__device__ __forceinline__ void ldsm4(uint32_t* r, uint32_t addr) {
    asm volatile("ldmatrix.sync.aligned.m8n8.x4.shared.b16 {%0,%1,%2,%3}, [%4];"
                 : "=r"(r[0]), "=r"(r[1]), "=r"(r[2]), "=r"(r[3]) : "r"(addr));
}

__device__ __forceinline__ void mm_compute(uint32_t aBase, uint32_t bBase,
                                           float (&acc)[4][4][4]) {
#pragma unroll
    for (int ks = 0; ks < 2; ks++) {
        uint32_t a[4][4], b[2][4];
#pragma unroll
        for (int mi = 0; mi < 4; mi++) ldsm4(a[mi], aBase + mi * (16 * SMA * 2) + ks * 32);
#pragma unroll
        for (int p = 0; p < 2; p++) ldsm4(b[p], bBase + p * (16 * SMA * 2) + ks * 32);
#pragma unroll
        for (int mi = 0; mi < 4; mi++)
#pragma unroll
            for (int ni = 0; ni < 4; ni++) {
                int p = ni >> 1, s = (ni & 1) * 2;
                mma_bf16(acc[mi][ni], a[mi][0], a[mi][1], a[mi][2], a[mi][3],
                         b[p][s], b[p][s + 1]);
            }
    }
}

#define CPA16(dst, src) \
    asm volatile("cp.async.cg.shared.global [%0], [%1], 16;" :: "r"(dst), "l"(src))
#define CPA_COMMIT() asm volatile("cp.async.commit_group;" ::: "memory")
#define CPA_WAIT0()  asm volatile("cp.async.wait_group 0;" ::: "memory")

// ---------------- 1) w_res = w - U @ V ----------------
__global__ void k_wres(const float* __restrict__ w, const float* __restrict__ U,
                       const float* __restrict__ V) {
    int o = blockIdx.x;
    __shared__ float u[TR];
    if (threadIdx.x < TR) u[threadIdx.x] = U[o * TR + threadIdx.x];
    __syncthreads();
    for (int c = threadIdx.x; c < TC; c += 256) {
        float acc = w[(size_t)o * TC + c];
#pragma unroll
        for (int r = 0; r < TR; r++) acc = __fmaf_rn(-u[r], V[r * TC + c], acc);
        g_wres[(size_t)o * TC + c] = acc;
    }
}

// ------- 2) weight rotate (Kahan fp32) + static quant -> bf16 codes -------
__global__ void __launch_bounds__(256) k_wrotq(const float* __restrict__ R0,
                                               const float* __restrict__ R1,
                                               const float* __restrict__ ws0,
                                               const float* __restrict__ ws1) {
    int half = blockIdx.y;
    const float* R = half ? R1 : R0;
    const float* ws = half ? ws1 : ws0;
    int o0 = blockIdx.x * 4;
    __shared__ float wr[4][TH];
    for (int i = threadIdx.x; i < 4 * TH; i += 256)
        wr[i >> 9][i & 511] = g_wres[(size_t)(o0 + (i >> 9)) * TC + half * TH + (i & 511)];
    __syncthreads();
    int n = threadIdx.x;
    float s[4][2] = {}, c[4][2] = {};
    for (int k = 0; k < TH; k++) {
        float b0 = R[k * TH + n], b1 = R[k * TH + n + 256];
#pragma unroll
        for (int i = 0; i < 4; i++) {
            float a = wr[i][k];
            float p0 = __fmul_rn(a, b0);
            float y0 = __fadd_rn(p0, -c[i][0]);
            float t0 = __fadd_rn(s[i][0], y0);
            c[i][0] = __fadd_rn(__fadd_rn(t0, -s[i][0]), -y0);
            s[i][0] = t0;
            float p1 = __fmul_rn(a, b1);
            float y1 = __fadd_rn(p1, -c[i][1]);
            float t1 = __fadd_rn(s[i][1], y1);
            c[i][1] = __fadd_rn(__fadd_rn(t1, -s[i][1]), -y1);
            s[i][1] = t1;
        }
    }
#pragma unroll
    for (int i = 0; i < 4; i++) {
        float sw = ws[o0 + i];
        g_qwb[(size_t)(o0 + i) * TC + half * TH + n]       = __float2bfloat16_rn(qcode(s[i][0], sw));
        g_qwb[(size_t)(o0 + i) * TC + half * TH + n + 256] = __float2bfloat16_rn(qcode(s[i][1], sw));
    }
}

// -------- 2b) pre-split R (transposed) --------
__global__ void k_rsplit(const float* __restrict__ R0, const float* __restrict__ R1) {
    int half = blockIdx.y, n = blockIdx.x;
    const float* R = half ? R1 : R0;
    size_t ob = (size_t)half * TH * TH + (size_t)n * TH;
    for (int k = threadIdx.x; k < TH; k += 256) {
        float v = R[(size_t)k * TH + n];
        __nv_bfloat16 h = __float2bfloat16_rn(v);
        g_rh[ob + k] = h;
        g_rm[ob + k] = __float2bfloat16_rn(v - __bfloat162float(h));
    }
}

// -------- 2c) pre-split x --------
__global__ void __launch_bounds__(256) k_xsplit(const float* __restrict__ x) {
    size_t base = ((size_t)blockIdx.x * 256 + threadIdx.x) * 16;
    __nv_bfloat16 h16[16], m16[16];
#pragma unroll
    for (int j = 0; j < 4; j++) {
        float4 v = *(const float4*)(x + base + j * 4);
        float vv[4] = {v.x, v.y, v.z, v.w};
#pragma unroll
        for (int q = 0; q < 4; q++) {
            __nv_bfloat16 h = __float2bfloat16_rn(vv[q]);
            h16[j * 4 + q] = h;
            m16[j * 4 + q] = __float2bfloat16_rn(vv[q] - __bfloat162float(h));
        }
    }
    *(uint4*)&g_xh[base]     = *(uint4*)&h16[0];
    *(uint4*)&g_xh[base + 8] = *(uint4*)&h16[8];
    *(uint4*)&g_xm[base]     = *(uint4*)&m16[0];
    *(uint4*)&g_xm[base + 8] = *(uint4*)&m16[8];
}

// ------- 3) x rotation: bf16 HMMA, 3 passes, double-buffered cp.async -------
#define XBUFB (128 * SMA * 2)   // bytes per operand array (10240)

__global__ void __launch_bounds__(256) k_xrot() {
    extern __shared__ __align__(16) char xsm[];
    const int half = blockIdx.z;
    const int n0 = blockIdx.x * 128, m0 = blockIdx.y * 128;
    const int tid = threadIdx.x, lane = tid & 31, wid = tid >> 5;
    const int wm = wid >> 2, wn = wid & 3;
    uint32_t sbase = (uint32_t)__cvta_generic_to_shared(xsm);

    float acc[4][4][4];
#pragma unroll
    for (int i = 0; i < 4; i++)
#pragma unroll
        for (int j = 0; j < 4; j++)
#pragma unroll
            for (int c = 0; c < 4; c++) acc[i][j][c] = 0.0f;

    const int g = lane >> 3, r = lane & 7;
    uint32_t aoff = (uint32_t)(((wm * 64 + (g & 1) * 8 + r) * SMA + (g >> 1) * 8) * 2);
    uint32_t boff = (uint32_t)(((wn * 32 + (g >> 1) * 8 + r) * SMA + (g & 1) * 8) * 2);

    const int srow = tid >> 1, skq = (tid & 1) * 16;
    const uint32_t stoff = (uint32_t)((srow * SMA + skq) * 2);   // multiple of 16
    const __nv_bfloat16* Axh = g_xh + (size_t)(m0 + srow) * TC + half * TH + skq;
    const __nv_bfloat16* Axm = g_xm + (size_t)(m0 + srow) * TC + half * TH + skq;
    const __nv_bfloat16* Brh = g_rh + (size_t)half * TH * TH + (size_t)(n0 + srow) * TH + skq;
    const __nv_bfloat16* Brm = g_rm + (size_t)half * TH * TH + (size_t)(n0 + srow) * TH + skq;

    // issue staging for chunk k0 into buffer buf
    auto issue = [&](int buf, int k0) {
        uint32_t b = sbase + (uint32_t)buf * (4 * XBUFB) + stoff;
        CPA16(b,                 Axh + k0);
        CPA16(b + 16,            Axh + k0 + 8);
        CPA16(b + XBUFB,         Axm + k0);
        CPA16(b + XBUFB + 16,    Axm + k0 + 8);
        CPA16(b + 2 * XBUFB,     Brh + k0);
        CPA16(b + 2 * XBUFB + 16, Brh + k0 + 8);
        CPA16(b + 3 * XBUFB,     Brm + k0);
        CPA16(b + 3 * XBUFB + 16, Brm + k0 + 8);
        CPA_COMMIT();
    };

    issue(0, 0);
    for (int it = 0; it < 16; it++) {
        CPA_WAIT0();
        __syncthreads();
        if (it < 15) issue((it + 1) & 1, (it + 1) * 32);
        uint32_t bb = sbase + (uint32_t)(it & 1) * (4 * XBUFB);
        mm_compute(bb + aoff, bb + 3 * XBUFB + boff, acc);              // h*m
        mm_compute(bb + XBUFB + aoff, bb + 2 * XBUFB + boff, acc);      // m*h
        mm_compute(bb + aoff, bb + 2 * XBUFB + boff, acc);              // h*h
    }

    const int qrow = lane >> 2, qcol = (lane & 3) * 2;
#pragma unroll
    for (int mi = 0; mi < 4; mi++) {
        size_t row = m0 + wm * 64 + mi * 16 + qrow;
#pragma unroll
        for (int ni = 0; ni < 4; ni++) {
            int col = half * TH + n0 + wn * 32 + ni * 8 + qcol;
            *(float2*)&g_x[row * TC + col] = make_float2(acc[mi][ni][0], acc[mi][ni][1]);
            *(float2*)&g_x[(row + 8) * TC + col] = make_float2(acc[mi][ni][2], acc[mi][ni][3]);
        }
    }
}

// ------- 4) p = x @ V^T via bf16 3-pass MMA (smooth path) -------
__global__ void __launch_bounds__(256) k_p(const float* __restrict__ V) {
    __shared__ __align__(16) __nv_bfloat16 Ah[128 * SMA], Am[128 * SMA];
    __shared__ __align__(16) __nv_bfloat16 Bh[32 * SMA], Bm[32 * SMA];
    const int m0 = blockIdx.x * 128;
    const int tid = threadIdx.x, lane = tid & 31, wid = tid >> 5;

    float acc[4][4];
#pragma unroll
    for (int i = 0; i < 4; i++)
#pragma unroll
        for (int c = 0; c < 4; c++) acc[i][c] = 0.0f;

    const int g = lane >> 3, r = lane & 7;
    uint32_t smAh = (uint32_t)__cvta_generic_to_shared(Ah);
    uint32_t smAm = (uint32_t)__cvta_generic_to_shared(Am);
    uint32_t smBh = (uint32_t)__cvta_generic_to_shared(Bh);
    uint32_t smBm = (uint32_t)__cvta_generic_to_shared(Bm);
    uint32_t aoff = (uint32_t)(((wid * 16 + (g & 1) * 8 + r) * SMA + (g >> 1) * 8) * 2);
    uint32_t boff = (uint32_t)((((g >> 1) * 8 + r) * SMA + (g & 1) * 8) * 2);

    const int srow = tid >> 1, skq = (tid & 1) * 16;
    const __nv_bfloat16* Axh = g_xh + (size_t)(m0 + srow) * TC + skq;
    const __nv_bfloat16* Axm = g_xm + (size_t)(m0 + srow) * TC + skq;
    const int vr = tid >> 3, vkq = (tid & 7) * 4;
    const float* Vg = V + (size_t)vr * TC + vkq;

    uint4 a0 = *(const uint4*)Axh, a1 = *(const uint4*)(Axh + 8);
    uint4 a2 = *(const uint4*)Axm, a3 = *(const uint4*)(Axm + 8);
    float4 bv = *(const float4*)Vg;

    for (int it = 0; it < 32; it++) {
        *(uint4*)&Ah[srow * SMA + skq]     = a0;
        *(uint4*)&Ah[srow * SMA + skq + 8] = a1;
        *(uint4*)&Am[srow * SMA + skq]     = a2;
        *(uint4*)&Am[srow * SMA + skq + 8] = a3;
        {
            float vv[4] = {bv.x, bv.y, bv.z, bv.w};
            __nv_bfloat16 h4[4], m4[4];
#pragma unroll
            for (int q = 0; q < 4; q++) {
                __nv_bfloat16 h = __float2bfloat16_rn(vv[q]);
                h4[q] = h;
                m4[q] = __float2bfloat16_rn(vv[q] - __bfloat162float(h));
            }
            *(uint2*)&Bh[vr * SMA + vkq] = *(uint2*)h4;
            *(uint2*)&Bm[vr * SMA + vkq] = *(uint2*)m4;
        }
        __syncthreads();
        if (it < 31) {
            int k0 = (it + 1) * 32;
            a0 = *(const uint4*)(Axh + k0);  a1 = *(const uint4*)(Axh + k0 + 8);
            a2 = *(const uint4*)(Axm + k0);  a3 = *(const uint4*)(Axm + k0 + 8);
            bv = *(const float4*)(Vg + k0);
        }
#pragma unroll 1
        for (int pass = 0; pass < 3; pass++) {
            uint32_t aB = (pass == 1) ? smAm + aoff : smAh + aoff;
            uint32_t bB = (pass == 0) ? smBm + boff : smBh + boff;
#pragma unroll
            for (int ks = 0; ks < 2; ks++) {
                uint32_t a[4], b[2][4];
                ldsm4(a, aB + ks * 32);
                ldsm4(b[0], bB + ks * 32);
                ldsm4(b[1], bB + 16 * SMA * 2 + ks * 32);
#pragma unroll
                for (int ni = 0; ni < 4; ni++) {
                    int p = ni >> 1, s = (ni & 1) * 2;
                    mma_bf16(acc[ni], a[0], a[1], a[2], a[3], b[p][s], b[p][s + 1]);
                }
            }
        }
        __syncthreads();
    }

    const int qrow = lane >> 2, qcol = (lane & 3) * 2;
#pragma unroll
    for (int ni = 0; ni < 4; ni++) {
        size_t row = m0 + wid * 16 + qrow;
        int col = ni * 8 + qcol;
        *(float2*)&g_p[row * TR + col]       = make_float2(acc[ni][0], acc[ni][1]);
        *(float2*)&g_p[(row + 8) * TR + col] = make_float2(acc[ni][2], acc[ni][3]);
    }
}

// -------- 5a) zero flag counter --------
__global__ void k_zero() { g_flagcnt = 0; }

// -------- 5b) dynamic quant: warp-per-half-token, shfl-only reduction --------
__global__ void __launch_bounds__(256) k_quant() {
    int wid = threadIdx.x >> 5, lane = threadIdx.x & 31;
    size_t t = (size_t)blockIdx.x * 4 + (wid >> 1);
    int half = wid & 1;
    const float* xr = g_x + t * TC + half * TH;

    float4 v[4];
    float m = 0.0f;
    int mi = 0;
#pragma unroll
    for (int j = 0; j < 4; j++) {
        int base = lane * 4 + j * 128;
        v[j] = *(const float4*)(xr + base);
        float a[4] = {fabsf(v[j].x), fabsf(v[j].y), fabsf(v[j].z), fabsf(v[j].w)};
#pragma unroll
        for (int q = 0; q < 4; q++)
            if (a[q] > m || (a[q] == m && base + q < mi)) { m = a[q]; mi = base + q; }
    }
#pragma unroll
    for (int o = 16; o; o >>= 1) {
        float om = __shfl_xor_sync(0xffffffffu, m, o);
        int   oi = __shfl_xor_sync(0xffffffffu, mi, o);
        if (om > m || (om == m && oi < mi)) { m = om; mi = oi; }
    }
    float s = fmaxf(__fdiv_rn(m, 7.0f), 1e-8f);
    if (lane == 0) {
        if (half) g_s1[t] = s; else g_s0[t] = s;
        g_aidx[t * 2 + half] = mi;
    }

    __nv_bfloat16* qr = g_qx + t * TC + half * TH;
#pragma unroll
    for (int j = 0; j < 4; j++) {
        int base = lane * 4 + j * 128;
        float vv[4] = {v[j].x, v[j].y, v[j].z, v[j].w};
        __nv_bfloat16 cd[4];
#pragma unroll
        for (int q = 0; q < 4; q++) {
            float u = __fdiv_rn(vv[q], s);
            float rr = rintf(u);
            cd[q] = __float2bfloat16_rn(fminf(fmaxf(rr, -8.0f), 7.0f));
            if (0.5f - fabsf(u - rr) < TAU) {
                int idx = atomicAdd(&g_flagcnt, 1);
                if (idx < FCAP) g_flags[idx] = ((int)t << 10) | (half * TH + base + q);
            }
        }
        *(uint2*)(qr + base) = *(uint2*)cd;
    }
}

// -------- 5c) fix-up: exact serial fp32 chain for flagged codes --------
__global__ void k_fix(const float* __restrict__ x, const float* __restrict__ R0,
                      const float* __restrict__ R1) {
    int cnt = g_flagcnt;
    if (cnt > FCAP) cnt = FCAP;
    for (int i = blockIdx.x * blockDim.x + threadIdx.x; i < cnt;
         i += gridDim.x * blockDim.x) {
        int e = g_flags[i];
        int t = e >> 10, c = e & 1023;
        int h = c >> 9, cc = c & 511;
        const float* xr = x + (size_t)t * TC + h * TH;
        const float* R = h ? R1 : R0;
        int ac = g_aidx[t * 2 + h];
        float v = 0.0f, va = 0.0f;
        for (int k = 0; k < TH; k++) {
            float xv = xr[k];
            v  = __fmaf_rn(xv, R[k * TH + cc], v);
            va = __fmaf_rn(xv, R[k * TH + ac], va);
        }
        float s = fmaxf(__fdiv_rn(fabsf(va), 7.0f), 1e-8f);
        g_qx[(size_t)t * TC + c] = __float2bfloat16_rn(qcode(v, s));
    }
}

// -------- 6) main GEMM: bf16 HMMA on integer codes + fused skip/affine --------
__global__ void __launch_bounds__(256) k_main(const float* __restrict__ U,
                                              const float* __restrict__ bias,
                                              const float* __restrict__ ws0,
                                              const float* __restrict__ ws1,
                                              const float* __restrict__ gamma,
                                              const float* __restrict__ beta,
                                              float* __restrict__ out) {
    __shared__ __align__(16) __nv_bfloat16 As[128 * SMA];
    __shared__ __align__(16) __nv_bfloat16 Bs[128 * SMA];
    const int tid = threadIdx.x;
    const int lane = tid & 31, wid = tid >> 5;
    const int wm = wid >> 2, wn = wid & 3;
    const int n0 = blockIdx.x * 128, m0 = blockIdx.y * 128;

    float acc[4][4][4];
#pragma unroll
    for (int i = 0; i < 4; i++)
#pragma unroll
        for (int j = 0; j < 4; j++)
#pragma unroll
            for (int c = 0; c < 4; c++) acc[i][j][c] = 0.0f;

    const int g = lane >> 3, r = lane & 7;
    uint32_t smA = (uint32_t)__cvta_generic_to_shared(As);
    uint32_t smB = (uint32_t)__cvta_generic_to_shared(Bs);
    uint32_t aBase = smA + (uint32_t)(((wm * 64 + (g & 1) * 8 + r) * SMA + (g >> 1) * 8) * 2);
    uint32_t bBase = smB + (uint32_t)(((wn * 32 + (g >> 1) * 8 + r) * SMA + (g & 1) * 8) * 2);

    const int lrow = tid >> 2, lq = (tid & 3) * 8;
    const __nv_bfloat16* Ag = g_qx + (size_t)m0 * TC;
    const __nv_bfloat16* Bg = g_qwb + (size_t)n0 * TC;

    uint4 av0, av1, bv0, bv1;
    av0 = *(const uint4*)(Ag + (size_t)lrow * TC + lq);
    av1 = *(const uint4*)(Ag + (size_t)(lrow + 64) * TC + lq);
    bv0 = *(const uint4*)(Bg + (size_t)lrow * TC + lq);
    bv1 = *(const uint4*)(Bg + (size_t)(lrow + 64) * TC + lq);
    *(uint4*)&As[lrow * SMA + lq] = av0;
    *(uint4*)&As[(lrow + 64) * SMA + lq] = av1;
    *(uint4*)&Bs[lrow * SMA + lq] = bv0;
    *(uint4*)&Bs[(lrow + 64) * SMA + lq] = bv1;
    __syncthreads();

    const int qrow = lane >> 2, qcol = (lane & 3) * 2;

    for (int it = 0; it < 32; it++) {
        if (it < 31) {
            int k0 = (it + 1) * 32;
            av0 = *(const uint4*)(Ag + (size_t)lrow * TC + k0 + lq);
            av1 = *(const uint4*)(Ag + (size_t)(lrow + 64) * TC + k0 + lq);
            bv0 = *(const uint4*)(Bg + (size_t)lrow * TC + k0 + lq);
            bv1 = *(const uint4*)(Bg + (size_t)(lrow + 64) * TC + k0 + lq);
        }
        mm_compute(aBase, bBase, acc);
        if (it == 15) {
            float rr[4][2], rc[4][2];
#pragma unroll
            for (int mi = 0; mi < 4; mi++) {
                int rw = m0 + wm * 64 + mi * 16 + qrow;
                rr[mi][0] = __fdiv_rn(g_s0[rw], g_s1[rw]);
                rr[mi][1] = __fdiv_rn(g_s0[rw + 8], g_s1[rw + 8]);
            }
#pragma unroll
            for (int ni = 0; ni < 4; ni++) {
                int cl = n0 + wn * 32 + ni * 8 + qcol;
                rc[ni][0] = __fdiv_rn(ws0[cl], ws1[cl]);
                rc[ni][1] = __fdiv_rn(ws0[cl + 1], ws1[cl + 1]);
            }
#pragma unroll
            for (int mi = 0; mi < 4; mi++)
#pragma unroll
                for (int ni = 0; ni < 4; ni++) {
                    acc[mi][ni][0] *= rr[mi][0] * rc[ni][0];
                    acc[mi][ni][1] *= rr[mi][0] * rc[ni][1];
                    acc[mi][ni][2] *= rr[mi][1] * rc[ni][0];
                    acc[mi][ni][3] *= rr[mi][1] * rc[ni][1];
                }
        }
        __syncthreads();
        if (it < 31) {
            *(uint4*)&As[lrow * SMA + lq] = av0;
            *(uint4*)&As[(lrow + 64) * SMA + lq] = av1;
            *(uint4*)&Bs[lrow * SMA + lq] = bv0;
            *(uint4*)&Bs[(lrow + 64) * SMA + lq] = bv1;
            __syncthreads();
        }
    }

    {
        float sr[4][2], sc[4][2];
#pragma unroll
        for (int mi = 0; mi < 4; mi++) {
            int rw = m0 + wm * 64 + mi * 16 + qrow;
            sr[mi][0] = g_s1[rw];
            sr[mi][1] = g_s1[rw + 8];
        }
#pragma unroll
        for (int ni = 0; ni < 4; ni++) {
            int cl = n0 + wn * 32 + ni * 8 + qcol;
            sc[ni][0] = ws1[cl];
            sc[ni][1] = ws1[cl + 1];
        }
#pragma unroll
        for (int mi = 0; mi < 4; mi++)
#pragma unroll
            for (int ni = 0; ni < 4; ni++) {
                acc[mi][ni][0] *= sr[mi][0] * sc[ni][0];
                acc[mi][ni][1] *= sr[mi][0] * sc[ni][1];
                acc[mi][ni][2] *= sr[mi][1] * sc[ni][0];
                acc[mi][ni][3] *= sr[mi][1] * sc[ni][1];
            }
    }

#pragma unroll 1
    for (int pass = 0; pass < 3; pass++) {
        __syncthreads();
#pragma unroll
        for (int l = 0; l < 16; l++) {
            int idx = tid + l * 256, row = idx >> 5, c = idx & 31;
            if (pass != 1) {
                float v = g_p[(size_t)(m0 + row) * TR + c];
                __nv_bfloat16 h = __float2bfloat16_rn(v);
                As[row * SMA + c] =
                    (pass == 2) ? __float2bfloat16_rn(v - __bfloat162float(h)) : h;
            }
            {
                float v = U[(size_t)(n0 + row) * TR + c];
                __nv_bfloat16 h = __float2bfloat16_rn(v);
                Bs[row * SMA + c] =
                    (pass == 1) ? __float2bfloat16_rn(v - __bfloat162float(h)) : h;
            }
        }
        __syncthreads();
        mm_compute(aBase, bBase, acc);
    }

    float bi[4][2], ga[4][2], be[4][2];
#pragma unroll
    for (int ni = 0; ni < 4; ni++) {
        int cl = n0 + wn * 32 + ni * 8 + qcol;
        bi[ni][0] = bias[cl];  bi[ni][1] = bias[cl + 1];
        ga[ni][0] = gamma[cl]; ga[ni][1] = gamma[cl + 1];
        be[ni][0] = beta[cl];  be[ni][1] = beta[cl + 1];
    }
#pragma unroll
    for (int mi = 0; mi < 4; mi++) {
        size_t r0 = m0 + wm * 64 + mi * 16 + qrow;
#pragma unroll
        for (int ni = 0; ni < 4; ni++) {
            int cl = n0 + wn * 32 + ni * 8 + qcol;
            float2 o0, o1;
            o0.x = __fmaf_rn(acc[mi][ni][0] + bi[ni][0], ga[ni][0], be[ni][0]);
            o0.y = __fmaf_rn(acc[mi][ni][1] + bi[ni][1], ga[ni][1], be[ni][1]);
            o1.x = __fmaf_rn(acc[mi][ni][2] + bi[ni][0], ga[ni][0], be[ni][0]);
            o1.y = __fmaf_rn(acc[mi][ni][3] + bi[ni][1], ga[ni][1], be[ni][1]);
            *(float2*)&out[r0 * TO + cl] = o0;
            *(float2*)&out[(r0 + 8) * TO + cl] = o1;
        }
    }
}

extern "C" void kernel_launch(void* const* d_in, const int* in_sizes, int n_in,
                              void* d_out, int out_size) {
    const float* x     = (const float*)d_in[0];
    const float* w     = (const float*)d_in[1];
    const float* bias  = (const float*)d_in[2];
    const float* U     = (const float*)d_in[3];
    const float* V     = (const float*)d_in[4];
    const float* R0    = (const float*)d_in[5];
    const float* R1    = (const float*)d_in[6];
    const float* ws0   = (const float*)d_in[7];
    const float* ws1   = (const float*)d_in[8];
    const float* gamma = (const float*)d_in[9];
    const float* beta  = (const float*)d_in[10];
    float* out = (float*)d_out;

    cudaFuncSetAttribute(k_xrot, cudaFuncAttributeMaxDynamicSharedMemorySize,
                         8 * XBUFB);

    k_wres<<<TO, 256>>>(w, U, V);
    k_wrotq<<<dim3(256, 2), 256>>>(R0, R1, ws0, ws1);
    k_rsplit<<<dim3(TH, 2), 256>>>(R0, R1);
    k_xsplit<<<(int)(((size_t)MT * TC) / (256 * 16)), 256>>>(x);
    k_xrot<<<dim3(4, 256, 2), 256, 8 * XBUFB>>>();
    k_p<<<256, 256>>>(V);
    k_zero<<<1, 1>>>();
    k_quant<<<MT / 4, 256>>>();
    k_fix<<<1024, 128>>>(x, R0, R1);
    k_main<<<dim3(8, 256), 256>>>(U, bias, ws0, ws1, gamma, beta, out);
}

// round 12
// speedup vs baseline: 3.7875x; 1.1704x over previous
#include <cuda_runtime.h>
#include <cuda_bf16.h>
#include <cstdint>

#define MT 32768
#define TC 1024
#define TH 512
#define TO 1024
#define TR 32
#define FCAP (1 << 22)
#define TAU 6e-4f

__device__ float g_wres[(size_t)TO * TC];
__device__ __nv_bfloat16 g_qwb[(size_t)TO * TC];
__device__ float g_x[(size_t)MT * TC];               // rotated activations
__device__ __nv_bfloat16 g_qx[(size_t)MT * TC];      // activation codes
__device__ __nv_bfloat16 g_xh[(size_t)MT * TC];      // x split hi (bf16)
__device__ __nv_bfloat16 g_xm[(size_t)MT * TC];      // x split residual (bf16)
__device__ __nv_bfloat16 g_rh[2 * TH * TH];          // R^T split hi   [half][n][k]
__device__ __nv_bfloat16 g_rm[2 * TH * TH];          // R^T split res
__device__ float g_s0[MT];
__device__ float g_s1[MT];
__device__ float g_p[(size_t)MT * TR];
__device__ int g_flagcnt;
__device__ int g_flags[FCAP];
__device__ int g_aidx[MT * 2];

__device__ __forceinline__ float qcode(float v, float s) {
    float q = rintf(__fdiv_rn(v, s));
    return fminf(fmaxf(q, -8.0f), 7.0f);
}

// ---- shared MMA helpers (bf16 m16n8k16, ldmatrix, [row][k] smem, stride SMA) ----
#define SMA 40

__device__ __forceinline__ void mma_bf16(float* c, uint32_t a0, uint32_t a1,
                                         uint32_t a2, uint32_t a3,
                                         uint32_t b0, uint32_t b1) {
    asm volatile(
        "mma.sync.aligned.m16n8k16.row.col.f32.bf16.bf16.f32 "
        "{%0,%1,%2,%3}, {%4,%5,%6,%7}, {%8,%9}, {%0,%1,%2,%3};"
        : "+f"(c[0]), "+f"(c[1]), "+f"(c[2]), "+f"(c[3])
        : "r"(a0), "r"(a1), "r"(a2), "r"(a3), "r"(b0), "r"(b1));
}

__device__ __forceinline__ void ldsm4(uint32_t* r, uint32_t addr) {
    asm volatile("ldmatrix.sync.aligned.m8n8.x4.shared.b16 {%0,%1,%2,%3}, [%4];"
                 : "=r"(r[0]), "=r"(r[1]), "=r"(r[2]), "=r"(r[3]) : "r"(addr));
}

__device__ __forceinline__ void mm_compute(uint32_t aBase, uint32_t bBase,
                                           float (&acc)[4][4][4]) {
#pragma unroll
    for (int ks = 0; ks < 2; ks++) {
        uint32_t a[4][4], b[2][4];
#pragma unroll
        for (int mi = 0; mi < 4; mi++) ldsm4(a[mi], aBase + mi * (16 * SMA * 2) + ks * 32);
#pragma unroll
        for (int p = 0; p < 2; p++) ldsm4(b[p], bBase + p * (16 * SMA * 2) + ks * 32);
#pragma unroll
        for (int mi = 0; mi < 4; mi++)
#pragma unroll
            for (int ni = 0; ni < 4; ni++) {
                int p = ni >> 1, s = (ni & 1) * 2;
                mma_bf16(acc[mi][ni], a[mi][0], a[mi][1], a[mi][2], a[mi][3],
                         b[p][s], b[p][s + 1]);
            }
    }
}

#define CPA16(dst, src) \
    asm volatile("cp.async.cg.shared.global [%0], [%1], 16;" :: "r"(dst), "l"(src))
#define CPA_COMMIT() asm volatile("cp.async.commit_group;" ::: "memory")
#define CPA_WAIT0()  asm volatile("cp.async.wait_group 0;" ::: "memory")

// ---------------- 1) w_res = w - U @ V ----------------
__global__ void k_wres(const float* __restrict__ w, const float* __restrict__ U,
                       const float* __restrict__ V) {
    int o = blockIdx.x;
    __shared__ float u[TR];
    if (threadIdx.x < TR) u[threadIdx.x] = U[o * TR + threadIdx.x];
    __syncthreads();
    for (int c = threadIdx.x; c < TC; c += 256) {
        float acc = w[(size_t)o * TC + c];
#pragma unroll
        for (int r = 0; r < TR; r++) acc = __fmaf_rn(-u[r], V[r * TC + c], acc);
        g_wres[(size_t)o * TC + c] = acc;
    }
}

// ------- 2) weight rotate (Kahan fp32) + static quant -> bf16 codes -------
__global__ void __launch_bounds__(256) k_wrotq(const float* __restrict__ R0,
                                               const float* __restrict__ R1,
                                               const float* __restrict__ ws0,
                                               const float* __restrict__ ws1) {
    int half = blockIdx.y;
    const float* R = half ? R1 : R0;
    const float* ws = half ? ws1 : ws0;
    int o0 = blockIdx.x * 4;
    __shared__ float wr[4][TH];
    for (int i = threadIdx.x; i < 4 * TH; i += 256)
        wr[i >> 9][i & 511] = g_wres[(size_t)(o0 + (i >> 9)) * TC + half * TH + (i & 511)];
    __syncthreads();
    int n = threadIdx.x;
    float s[4][2] = {}, c[4][2] = {};
    for (int k = 0; k < TH; k++) {
        float b0 = R[k * TH + n], b1 = R[k * TH + n + 256];
#pragma unroll
        for (int i = 0; i < 4; i++) {
            float a = wr[i][k];
            float p0 = __fmul_rn(a, b0);
            float y0 = __fadd_rn(p0, -c[i][0]);
            float t0 = __fadd_rn(s[i][0], y0);
            c[i][0] = __fadd_rn(__fadd_rn(t0, -s[i][0]), -y0);
            s[i][0] = t0;
            float p1 = __fmul_rn(a, b1);
            float y1 = __fadd_rn(p1, -c[i][1]);
            float t1 = __fadd_rn(s[i][1], y1);
            c[i][1] = __fadd_rn(__fadd_rn(t1, -s[i][1]), -y1);
            s[i][1] = t1;
        }
    }
#pragma unroll
    for (int i = 0; i < 4; i++) {
        float sw = ws[o0 + i];
        g_qwb[(size_t)(o0 + i) * TC + half * TH + n]       = __float2bfloat16_rn(qcode(s[i][0], sw));
        g_qwb[(size_t)(o0 + i) * TC + half * TH + n + 256] = __float2bfloat16_rn(qcode(s[i][1], sw));
    }
}

// -------- 2b) pre-split R (transposed) --------
__global__ void k_rsplit(const float* __restrict__ R0, const float* __restrict__ R1) {
    int half = blockIdx.y, n = blockIdx.x;
    const float* R = half ? R1 : R0;
    size_t ob = (size_t)half * TH * TH + (size_t)n * TH;
    for (int k = threadIdx.x; k < TH; k += 256) {
        float v = R[(size_t)k * TH + n];
        __nv_bfloat16 h = __float2bfloat16_rn(v);
        g_rh[ob + k] = h;
        g_rm[ob + k] = __float2bfloat16_rn(v - __bfloat162float(h));
    }
}

// -------- 2c) pre-split x --------
__global__ void __launch_bounds__(256) k_xsplit(const float* __restrict__ x) {
    size_t base = ((size_t)blockIdx.x * 256 + threadIdx.x) * 16;
    __nv_bfloat16 h16[16], m16[16];
#pragma unroll
    for (int j = 0; j < 4; j++) {
        float4 v = *(const float4*)(x + base + j * 4);
        float vv[4] = {v.x, v.y, v.z, v.w};
#pragma unroll
        for (int q = 0; q < 4; q++) {
            __nv_bfloat16 h = __float2bfloat16_rn(vv[q]);
            h16[j * 4 + q] = h;
            m16[j * 4 + q] = __float2bfloat16_rn(vv[q] - __bfloat162float(h));
        }
    }
    *(uint4*)&g_xh[base]     = *(uint4*)&h16[0];
    *(uint4*)&g_xh[base + 8] = *(uint4*)&h16[8];
    *(uint4*)&g_xm[base]     = *(uint4*)&m16[0];
    *(uint4*)&g_xm[base + 8] = *(uint4*)&m16[8];
}

// ------- 3) x rotation: bf16 HMMA, 3 passes, double-buffered cp.async, 2 CTAs/SM -------
#define XBUFB (128 * SMA * 2)   // bytes per operand array (10240)

__global__ void __launch_bounds__(256, 2) k_xrot() {
    extern __shared__ __align__(16) char xsm[];
    const int half = blockIdx.z;
    const int n0 = blockIdx.x * 128, m0 = blockIdx.y * 128;
    const int tid = threadIdx.x, lane = tid & 31, wid = tid >> 5;
    const int wm = wid >> 2, wn = wid & 3;
    uint32_t sbase = (uint32_t)__cvta_generic_to_shared(xsm);

    float acc[4][4][4];
#pragma unroll
    for (int i = 0; i < 4; i++)
#pragma unroll
        for (int j = 0; j < 4; j++)
#pragma unroll
            for (int c = 0; c < 4; c++) acc[i][j][c] = 0.0f;

    const int g = lane >> 3, r = lane & 7;
    uint32_t aoff = (uint32_t)(((wm * 64 + (g & 1) * 8 + r) * SMA + (g >> 1) * 8) * 2);
    uint32_t boff = (uint32_t)(((wn * 32 + (g >> 1) * 8 + r) * SMA + (g & 1) * 8) * 2);

    const int srow = tid >> 1, skq = (tid & 1) * 16;
    const uint32_t stoff = (uint32_t)((srow * SMA + skq) * 2);
    const __nv_bfloat16* Axh = g_xh + (size_t)(m0 + srow) * TC + half * TH + skq;
    const __nv_bfloat16* Axm = g_xm + (size_t)(m0 + srow) * TC + half * TH + skq;
    const __nv_bfloat16* Brh = g_rh + (size_t)half * TH * TH + (size_t)(n0 + srow) * TH + skq;
    const __nv_bfloat16* Brm = g_rm + (size_t)half * TH * TH + (size_t)(n0 + srow) * TH + skq;

    auto issue = [&](int buf, int k0) {
        uint32_t b = sbase + (uint32_t)buf * (4 * XBUFB) + stoff;
        CPA16(b,                  Axh + k0);
        CPA16(b + 16,             Axh + k0 + 8);
        CPA16(b + XBUFB,          Axm + k0);
        CPA16(b + XBUFB + 16,     Axm + k0 + 8);
        CPA16(b + 2 * XBUFB,      Brh + k0);
        CPA16(b + 2 * XBUFB + 16, Brh + k0 + 8);
        CPA16(b + 3 * XBUFB,      Brm + k0);
        CPA16(b + 3 * XBUFB + 16, Brm + k0 + 8);
        CPA_COMMIT();
    };

    issue(0, 0);
    for (int it = 0; it < 16; it++) {
        CPA_WAIT0();
        __syncthreads();
        if (it < 15) issue((it + 1) & 1, (it + 1) * 32);
        uint32_t bb = sbase + (uint32_t)(it & 1) * (4 * XBUFB);
        mm_compute(bb + aoff, bb + 3 * XBUFB + boff, acc);              // h*m
        mm_compute(bb + XBUFB + aoff, bb + 2 * XBUFB + boff, acc);      // m*h
        mm_compute(bb + aoff, bb + 2 * XBUFB + boff, acc);              // h*h
    }

    const int qrow = lane >> 2, qcol = (lane & 3) * 2;
#pragma unroll
    for (int mi = 0; mi < 4; mi++) {
        size_t row = m0 + wm * 64 + mi * 16 + qrow;
#pragma unroll
        for (int ni = 0; ni < 4; ni++) {
            int col = half * TH + n0 + wn * 32 + ni * 8 + qcol;
            *(float2*)&g_x[row * TC + col] = make_float2(acc[mi][ni][0], acc[mi][ni][1]);
            *(float2*)&g_x[(row + 8) * TC + col] = make_float2(acc[mi][ni][2], acc[mi][ni][3]);
        }
    }
}

// ------- 4) p = x @ V^T via bf16 3-pass MMA, 2 CTAs/SM -------
__global__ void __launch_bounds__(256, 2) k_p(const float* __restrict__ V) {
    __shared__ __align__(16) __nv_bfloat16 Ah[128 * SMA], Am[128 * SMA];
    __shared__ __align__(16) __nv_bfloat16 Bh[32 * SMA], Bm[32 * SMA];
    const int m0 = blockIdx.x * 128;
    const int tid = threadIdx.x, lane = tid & 31, wid = tid >> 5;

    float acc[4][4];
#pragma unroll
    for (int i = 0; i < 4; i++)
#pragma unroll
        for (int c = 0; c < 4; c++) acc[i][c] = 0.0f;

    const int g = lane >> 3, r = lane & 7;
    uint32_t smAh = (uint32_t)__cvta_generic_to_shared(Ah);
    uint32_t smAm = (uint32_t)__cvta_generic_to_shared(Am);
    uint32_t smBh = (uint32_t)__cvta_generic_to_shared(Bh);
    uint32_t smBm = (uint32_t)__cvta_generic_to_shared(Bm);
    uint32_t aoff = (uint32_t)(((wid * 16 + (g & 1) * 8 + r) * SMA + (g >> 1) * 8) * 2);
    uint32_t boff = (uint32_t)((((g >> 1) * 8 + r) * SMA + (g & 1) * 8) * 2);

    const int srow = tid >> 1, skq = (tid & 1) * 16;
    const __nv_bfloat16* Axh = g_xh + (size_t)(m0 + srow) * TC + skq;
    const __nv_bfloat16* Axm = g_xm + (size_t)(m0 + srow) * TC + skq;
    const int vr = tid >> 3, vkq = (tid & 7) * 4;
    const float* Vg = V + (size_t)vr * TC + vkq;

    uint4 a0 = *(const uint4*)Axh, a1 = *(const uint4*)(Axh + 8);
    uint4 a2 = *(const uint4*)Axm, a3 = *(const uint4*)(Axm + 8);
    float4 bv = *(const float4*)Vg;

    for (int it = 0; it < 32; it++) {
        *(uint4*)&Ah[srow * SMA + skq]     = a0;
        *(uint4*)&Ah[srow * SMA + skq + 8] = a1;
        *(uint4*)&Am[srow * SMA + skq]     = a2;
        *(uint4*)&Am[srow * SMA + skq + 8] = a3;
        {
            float vv[4] = {bv.x, bv.y, bv.z, bv.w};
            __nv_bfloat16 h4[4], m4[4];
#pragma unroll
            for (int q = 0; q < 4; q++) {
                __nv_bfloat16 h = __float2bfloat16_rn(vv[q]);
                h4[q] = h;
                m4[q] = __float2bfloat16_rn(vv[q] - __bfloat162float(h));
            }
            *(uint2*)&Bh[vr * SMA + vkq] = *(uint2*)h4;
            *(uint2*)&Bm[vr * SMA + vkq] = *(uint2*)m4;
        }
        __syncthreads();
        if (it < 31) {
            int k0 = (it + 1) * 32;
            a0 = *(const uint4*)(Axh + k0);  a1 = *(const uint4*)(Axh + k0 + 8);
            a2 = *(const uint4*)(Axm + k0);  a3 = *(const uint4*)(Axm + k0 + 8);
            bv = *(const float4*)(Vg + k0);
        }
#pragma unroll 1
        for (int pass = 0; pass < 3; pass++) {
            uint32_t aB = (pass == 1) ? smAm + aoff : smAh + aoff;
            uint32_t bB = (pass == 0) ? smBm + boff : smBh + boff;
#pragma unroll
            for (int ks = 0; ks < 2; ks++) {
                uint32_t a[4], b[2][4];
                ldsm4(a, aB + ks * 32);
                ldsm4(b[0], bB + ks * 32);
                ldsm4(b[1], bB + 16 * SMA * 2 + ks * 32);
#pragma unroll
                for (int ni = 0; ni < 4; ni++) {
                    int p = ni >> 1, s = (ni & 1) * 2;
                    mma_bf16(acc[ni], a[0], a[1], a[2], a[3], b[p][s], b[p][s + 1]);
                }
            }
        }
        __syncthreads();
    }

    const int qrow = lane >> 2, qcol = (lane & 3) * 2;
#pragma unroll
    for (int ni = 0; ni < 4; ni++) {
        size_t row = m0 + wid * 16 + qrow;
        int col = ni * 8 + qcol;
        *(float2*)&g_p[row * TR + col]       = make_float2(acc[ni][0], acc[ni][1]);
        *(float2*)&g_p[(row + 8) * TR + col] = make_float2(acc[ni][2], acc[ni][3]);
    }
}

// -------- 5a) zero flag counter --------
__global__ void k_zero() { g_flagcnt = 0; }

// -------- 5b) dynamic quant: warp-per-half-token, shfl-only reduction --------
__global__ void __launch_bounds__(256) k_quant() {
    int wid = threadIdx.x >> 5, lane = threadIdx.x & 31;
    size_t t = (size_t)blockIdx.x * 4 + (wid >> 1);
    int half = wid & 1;
    const float* xr = g_x + t * TC + half * TH;

    float4 v[4];
    float m = 0.0f;
    int mi = 0;
#pragma unroll
    for (int j = 0; j < 4; j++) {
        int base = lane * 4 + j * 128;
        v[j] = *(const float4*)(xr + base);
        float a[4] = {fabsf(v[j].x), fabsf(v[j].y), fabsf(v[j].z), fabsf(v[j].w)};
#pragma unroll
        for (int q = 0; q < 4; q++)
            if (a[q] > m || (a[q] == m && base + q < mi)) { m = a[q]; mi = base + q; }
    }
#pragma unroll
    for (int o = 16; o; o >>= 1) {
        float om = __shfl_xor_sync(0xffffffffu, m, o);
        int   oi = __shfl_xor_sync(0xffffffffu, mi, o);
        if (om > m || (om == m && oi < mi)) { m = om; mi = oi; }
    }
    float s = fmaxf(__fdiv_rn(m, 7.0f), 1e-8f);
    if (lane == 0) {
        if (half) g_s1[t] = s; else g_s0[t] = s;
        g_aidx[t * 2 + half] = mi;
    }

    __nv_bfloat16* qr = g_qx + t * TC + half * TH;
#pragma unroll
    for (int j = 0; j < 4; j++) {
        int base = lane * 4 + j * 128;
        float vv[4] = {v[j].x, v[j].y, v[j].z, v[j].w};
        __nv_bfloat16 cd[4];
#pragma unroll
        for (int q = 0; q < 4; q++) {
            float u = __fdiv_rn(vv[q], s);
            float rr = rintf(u);
            cd[q] = __float2bfloat16_rn(fminf(fmaxf(rr, -8.0f), 7.0f));
            if (0.5f - fabsf(u - rr) < TAU) {
                int idx = atomicAdd(&g_flagcnt, 1);
                if (idx < FCAP) g_flags[idx] = ((int)t << 10) | (half * TH + base + q);
            }
        }
        *(uint2*)(qr + base) = *(uint2*)cd;
    }
}

// -------- 5c) fix-up: exact serial fp32 chain for flagged codes --------
__global__ void k_fix(const float* __restrict__ x, const float* __restrict__ R0,
                      const float* __restrict__ R1) {
    int cnt = g_flagcnt;
    if (cnt > FCAP) cnt = FCAP;
    for (int i = blockIdx.x * blockDim.x + threadIdx.x; i < cnt;
         i += gridDim.x * blockDim.x) {
        int e = g_flags[i];
        int t = e >> 10, c = e & 1023;
        int h = c >> 9, cc = c & 511;
        const float* xr = x + (size_t)t * TC + h * TH;
        const float* R = h ? R1 : R0;
        int ac = g_aidx[t * 2 + h];
        float v = 0.0f, va = 0.0f;
        for (int k = 0; k < TH; k++) {
            float xv = xr[k];
            v  = __fmaf_rn(xv, R[k * TH + cc], v);
            va = __fmaf_rn(xv, R[k * TH + ac], va);
        }
        float s = fmaxf(__fdiv_rn(fabsf(va), 7.0f), 1e-8f);
        g_qx[(size_t)t * TC + c] = __float2bfloat16_rn(qcode(v, s));
    }
}

// -------- 6) main GEMM: bf16 HMMA on integer codes + fused skip/affine, 2 CTAs/SM --------
__global__ void __launch_bounds__(256, 2) k_main(const float* __restrict__ U,
                                                 const float* __restrict__ bias,
                                                 const float* __restrict__ ws0,
                                                 const float* __restrict__ ws1,
                                                 const float* __restrict__ gamma,
                                                 const float* __restrict__ beta,
                                                 float* __restrict__ out) {
    __shared__ __align__(16) __nv_bfloat16 As[128 * SMA];
    __shared__ __align__(16) __nv_bfloat16 Bs[128 * SMA];
    const int tid = threadIdx.x;
    const int lane = tid & 31, wid = tid >> 5;
    const int wm = wid >> 2, wn = wid & 3;
    const int n0 = blockIdx.x * 128, m0 = blockIdx.y * 128;

    float acc[4][4][4];
#pragma unroll
    for (int i = 0; i < 4; i++)
#pragma unroll
        for (int j = 0; j < 4; j++)
#pragma unroll
            for (int c = 0; c < 4; c++) acc[i][j][c] = 0.0f;

    const int g = lane >> 3, r = lane & 7;
    uint32_t smA = (uint32_t)__cvta_generic_to_shared(As);
    uint32_t smB = (uint32_t)__cvta_generic_to_shared(Bs);
    uint32_t aBase = smA + (uint32_t)(((wm * 64 + (g & 1) * 8 + r) * SMA + (g >> 1) * 8) * 2);
    uint32_t bBase = smB + (uint32_t)(((wn * 32 + (g >> 1) * 8 + r) * SMA + (g & 1) * 8) * 2);

    const int lrow = tid >> 2, lq = (tid & 3) * 8;
    const __nv_bfloat16* Ag = g_qx + (size_t)m0 * TC;
    const __nv_bfloat16* Bg = g_qwb + (size_t)n0 * TC;

    uint4 av0, av1, bv0, bv1;
    av0 = *(const uint4*)(Ag + (size_t)lrow * TC + lq);
    av1 = *(const uint4*)(Ag + (size_t)(lrow + 64) * TC + lq);
    bv0 = *(const uint4*)(Bg + (size_t)lrow * TC + lq);
    bv1 = *(const uint4*)(Bg + (size_t)(lrow + 64) * TC + lq);
    *(uint4*)&As[lrow * SMA + lq] = av0;
    *(uint4*)&As[(lrow + 64) * SMA + lq] = av1;
    *(uint4*)&Bs[lrow * SMA + lq] = bv0;
    *(uint4*)&Bs[(lrow + 64) * SMA + lq] = bv1;
    __syncthreads();

    const int qrow = lane >> 2, qcol = (lane & 3) * 2;

    for (int it = 0; it < 32; it++) {
        if (it < 31) {
            int k0 = (it + 1) * 32;
            av0 = *(const uint4*)(Ag + (size_t)lrow * TC + k0 + lq);
            av1 = *(const uint4*)(Ag + (size_t)(lrow + 64) * TC + k0 + lq);
            bv0 = *(const uint4*)(Bg + (size_t)lrow * TC + k0 + lq);
            bv1 = *(const uint4*)(Bg + (size_t)(lrow + 64) * TC + k0 + lq);
        }
        mm_compute(aBase, bBase, acc);
        if (it == 15) {
            float rr[4][2], rc[4][2];
#pragma unroll
            for (int mi = 0; mi < 4; mi++) {
                int rw = m0 + wm * 64 + mi * 16 + qrow;
                rr[mi][0] = __fdiv_rn(g_s0[rw], g_s1[rw]);
                rr[mi][1] = __fdiv_rn(g_s0[rw + 8], g_s1[rw + 8]);
            }
#pragma unroll
            for (int ni = 0; ni < 4; ni++) {
                int cl = n0 + wn * 32 + ni * 8 + qcol;
                rc[ni][0] = __fdiv_rn(ws0[cl], ws1[cl]);
                rc[ni][1] = __fdiv_rn(ws0[cl + 1], ws1[cl + 1]);
            }
#pragma unroll
            for (int mi = 0; mi < 4; mi++)
#pragma unroll
                for (int ni = 0; ni < 4; ni++) {
                    acc[mi][ni][0] *= rr[mi][0] * rc[ni][0];
                    acc[mi][ni][1] *= rr[mi][0] * rc[ni][1];
                    acc[mi][ni][2] *= rr[mi][1] * rc[ni][0];
                    acc[mi][ni][3] *= rr[mi][1] * rc[ni][1];
                }
        }
        __syncthreads();
        if (it < 31) {
            *(uint4*)&As[lrow * SMA + lq] = av0;
            *(uint4*)&As[(lrow + 64) * SMA + lq] = av1;
            *(uint4*)&Bs[lrow * SMA + lq] = bv0;
            *(uint4*)&Bs[(lrow + 64) * SMA + lq] = bv1;
            __syncthreads();
        }
    }

    {
        float sr[4][2], sc[4][2];
#pragma unroll
        for (int mi = 0; mi < 4; mi++) {
            int rw = m0 + wm * 64 + mi * 16 + qrow;
            sr[mi][0] = g_s1[rw];
            sr[mi][1] = g_s1[rw + 8];
        }
#pragma unroll
        for (int ni = 0; ni < 4; ni++) {
            int cl = n0 + wn * 32 + ni * 8 + qcol;
            sc[ni][0] = ws1[cl];
            sc[ni][1] = ws1[cl + 1];
        }
#pragma unroll
        for (int mi = 0; mi < 4; mi++)
#pragma unroll
            for (int ni = 0; ni < 4; ni++) {
                acc[mi][ni][0] *= sr[mi][0] * sc[ni][0];
                acc[mi][ni][1] *= sr[mi][0] * sc[ni][1];
                acc[mi][ni][2] *= sr[mi][1] * sc[ni][0];
                acc[mi][ni][3] *= sr[mi][1] * sc[ni][1];
            }
    }

#pragma unroll 1
    for (int pass = 0; pass < 3; pass++) {
        __syncthreads();
#pragma unroll
        for (int l = 0; l < 16; l++) {
            int idx = tid + l * 256, row = idx >> 5, c = idx & 31;
            if (pass != 1) {
                float v = g_p[(size_t)(m0 + row) * TR + c];
                __nv_bfloat16 h = __float2bfloat16_rn(v);
                As[row * SMA + c] =
                    (pass == 2) ? __float2bfloat16_rn(v - __bfloat162float(h)) : h;
            }
            {
                float v = U[(size_t)(n0 + row) * TR + c];
                __nv_bfloat16 h = __float2bfloat16_rn(v);
                Bs[row * SMA + c] =
                    (pass == 1) ? __float2bfloat16_rn(v - __bfloat162float(h)) : h;
            }
        }
        __syncthreads();
        mm_compute(aBase, bBase, acc);
    }

    float bi[4][2], ga[4][2], be[4][2];
#pragma unroll
    for (int ni = 0; ni < 4; ni++) {
        int cl = n0 + wn * 32 + ni * 8 + qcol;
        bi[ni][0] = bias[cl];  bi[ni][1] = bias[cl + 1];
        ga[ni][0] = gamma[cl]; ga[ni][1] = gamma[cl + 1];
        be[ni][0] = beta[cl];  be[ni][1] = beta[cl + 1];
    }
#pragma unroll
    for (int mi = 0; mi < 4; mi++) {
        size_t r0 = m0 + wm * 64 + mi * 16 + qrow;
#pragma unroll
        for (int ni = 0; ni < 4; ni++) {
            int cl = n0 + wn * 32 + ni * 8 + qcol;
            float2 o0, o1;
            o0.x = __fmaf_rn(acc[mi][ni][0] + bi[ni][0], ga[ni][0], be[ni][0]);
            o0.y = __fmaf_rn(acc[mi][ni][1] + bi[ni][1], ga[ni][1], be[ni][1]);
            o1.x = __fmaf_rn(acc[mi][ni][2] + bi[ni][0], ga[ni][0], be[ni][0]);
            o1.y = __fmaf_rn(acc[mi][ni][3] + bi[ni][1], ga[ni][1], be[ni][1]);
            *(float2*)&out[r0 * TO + cl] = o0;
            *(float2*)&out[(r0 + 8) * TO + cl] = o1;
        }
    }
}

extern "C" void kernel_launch(void* const* d_in, const int* in_sizes, int n_in,
                              void* d_out, int out_size) {
    const float* x     = (const float*)d_in[0];
    const float* w     = (const float*)d_in[1];
    const float* bias  = (const float*)d_in[2];
    const float* U     = (const float*)d_in[3];
    const float* V     = (const float*)d_in[4];
    const float* R0    = (const float*)d_in[5];
    const float* R1    = (const float*)d_in[6];
    const float* ws0   = (const float*)d_in[7];
    const float* ws1   = (const float*)d_in[8];
    const float* gamma = (const float*)d_in[9];
    const float* beta  = (const float*)d_in[10];
    float* out = (float*)d_out;

    cudaFuncSetAttribute(k_xrot, cudaFuncAttributeMaxDynamicSharedMemorySize,
                         8 * XBUFB);

    k_wres<<<TO, 256>>>(w, U, V);
    k_wrotq<<<dim3(256, 2), 256>>>(R0, R1, ws0, ws1);
    k_rsplit<<<dim3(TH, 2), 256>>>(R0, R1);
    k_xsplit<<<(int)(((size_t)MT * TC) / (256 * 16)), 256>>>(x);
    k_xrot<<<dim3(4, 256, 2), 256, 8 * XBUFB>>>();
    k_p<<<256, 256>>>(V);
    k_zero<<<1, 1>>>();
    k_quant<<<MT / 4, 256>>>();
    k_fix<<<1024, 128>>>(x, R0, R1);
    k_main<<<dim3(8, 256), 256>>>(U, bias, ws0, ws1, gamma, beta, out);
}